// round 1
// baseline (speedup 1.0000x reference)
#include <cuda_runtime.h>
#include <math.h>

// Problem constants
#define BB   2
#define NQ   2048      // N (query length per batch)
#define DD   256       // feature dim
#define HH   8         // heads
#define DH   32        // head dim
#define MM   2
#define NNK  2048      // NN
#define LK   4096      // M*NN (kv length per batch)
#define KNN  8

#define NSETS 6        // 2 current (b=0,1) + 4 neighbor (m,b)

// ---------------- scratch (device globals; no runtime allocation) ----------------
__device__ float g_cur_edge[BB * NQ * DD];   // q-side edge features  [B, N, D]
__device__ float g_all_nbr [BB * LK * DD];   // kv-side edge features [B, M*NN, D]
__device__ float g_q   [BB * NQ * DD];
__device__ float g_k   [BB * LK * DD];
__device__ float g_v   [BB * LK * DD];
__device__ float g_attn[BB * NQ * DD];
__device__ int   g_idx [NSETS * NQ * KNN];

// =====================================================================
// Kernel 1: per-set KNN top-8 (smallest d2, lower index wins on ties)
// grid: (2048/128, 6), block: 128
// =====================================================================
__global__ void knn_topk_kernel(const float* __restrict__ cur_pts,
                                const float* __restrict__ nbr_pts)
{
    int set = blockIdx.y;
    const float* pts = (set < 2) ? (cur_pts + (size_t)set * NQ * 3)
                                 : (nbr_pts + (size_t)(set - 2) * NNK * 3); // (m*B+b) order
    __shared__ float px[2048], py[2048], pz[2048], sq[2048];
    for (int i = threadIdx.x; i < 2048; i += blockDim.x) {
        float x = pts[i * 3 + 0], y = pts[i * 3 + 1], z = pts[i * 3 + 2];
        px[i] = x; py[i] = y; pz[i] = z;
        sq[i] = x * x + y * y + z * z;
    }
    __syncthreads();

    int row = blockIdx.x * blockDim.x + threadIdx.x;
    float bx = px[row], by = py[row], bz = pz[row], bsq = sq[row];

    float bestd[KNN];
    int   besti[KNN];
#pragma unroll
    for (int t = 0; t < KNN; t++) { bestd[t] = INFINITY; besti[t] = -1; }

    for (int j = 0; j < 2048; j++) {
        float dot = bx * px[j] + by * py[j] + bz * pz[j];
        float d2  = bsq + sq[j] - 2.0f * dot;
        if (d2 < bestd[KNN - 1]) {
            int t = KNN - 1;
#pragma unroll
            for (int u = KNN - 1; u > 0; u--) {
                if (bestd[u - 1] > d2) { bestd[u] = bestd[u - 1]; besti[u] = besti[u - 1]; t = u - 1; }
                else break;
            }
            bestd[t] = d2; besti[t] = j;
        }
    }

    int* out = g_idx + ((size_t)set * NQ + row) * KNN;
#pragma unroll
    for (int t = 0; t < KNN; t++) out[t] = besti[t];
}

// =====================================================================
// Kernel 2: edge features  edge = f - mean(f[knn])
// grid: 6*2048 blocks, block: 256 (one thread per feature dim)
// neighbor-set output is written directly in the [B, M*NN, D] transposed layout
// =====================================================================
__global__ void edge_feats_kernel(const float* __restrict__ cur_f,
                                  const float* __restrict__ nbr_f)
{
    int gid = blockIdx.x;
    int set = gid >> 11;
    int row = gid & 2047;

    const float* f;
    float* outp;
    if (set < 2) {
        f    = cur_f + (size_t)set * NQ * DD;
        outp = g_cur_edge + ((size_t)set * NQ + row) * DD;
    } else {
        int mb = set - 2;          // m*B + b
        int m = mb >> 1, b = mb & 1;
        f    = nbr_f + (size_t)mb * NNK * DD;
        outp = g_all_nbr + ((size_t)b * LK + (size_t)m * NNK + row) * DD;
    }

    const int* idx = g_idx + ((size_t)set * NQ + row) * KNN;
    int d = threadIdx.x;

    float acc = 0.0f;
#pragma unroll
    for (int t = 0; t < KNN; t++)
        acc += f[(size_t)idx[t] * DD + d];

    outp[d] = f[(size_t)row * DD + d] - acc * (1.0f / 8.0f);
}

// =====================================================================
// Kernel 3: projection GEMM  C[R,256] = A[R,256] @ W[256,256]^T + bias
// tile 64x64, kc=16, block 256 threads (16x16), 4x4 micro-tile
// =====================================================================
__global__ void gemm_proj_kernel(const float* __restrict__ A,
                                 const float* __restrict__ W,
                                 const float* __restrict__ bias,
                                 float* __restrict__ C)
{
    __shared__ float As[16][64];
    __shared__ float Ws[16][64];

    int tid = threadIdx.x;
    int tx = tid & 15, ty = tid >> 4;
    int m0 = blockIdx.x * 64;
    int n0 = blockIdx.y * 64;

    int lrow = tid >> 2;      // 0..63
    int lkq  = tid & 3;       // 0..3 (float4 within 16 k-cols)

    float acc[4][4];
#pragma unroll
    for (int i = 0; i < 4; i++)
#pragma unroll
        for (int j = 0; j < 4; j++) acc[i][j] = 0.0f;

    for (int k0 = 0; k0 < 256; k0 += 16) {
        float4 av = *(const float4*)&A[((size_t)(m0 + lrow)) * 256 + k0 + lkq * 4];
        float4 wv = *(const float4*)&W[((size_t)(n0 + lrow)) * 256 + k0 + lkq * 4];
        As[lkq * 4 + 0][lrow] = av.x; As[lkq * 4 + 1][lrow] = av.y;
        As[lkq * 4 + 2][lrow] = av.z; As[lkq * 4 + 3][lrow] = av.w;
        Ws[lkq * 4 + 0][lrow] = wv.x; Ws[lkq * 4 + 1][lrow] = wv.y;
        Ws[lkq * 4 + 2][lrow] = wv.z; Ws[lkq * 4 + 3][lrow] = wv.w;
        __syncthreads();

#pragma unroll
        for (int kk = 0; kk < 16; kk++) {
            float4 a = *(const float4*)&As[kk][ty * 4];
            float4 b = *(const float4*)&Ws[kk][tx * 4];
            float aa[4] = {a.x, a.y, a.z, a.w};
            float bb[4] = {b.x, b.y, b.z, b.w};
#pragma unroll
            for (int i = 0; i < 4; i++)
#pragma unroll
                for (int j = 0; j < 4; j++) acc[i][j] += aa[i] * bb[j];
        }
        __syncthreads();
    }

#pragma unroll
    for (int i = 0; i < 4; i++) {
        int gr = m0 + ty * 4 + i;
#pragma unroll
        for (int j = 0; j < 4; j++) {
            int gc = n0 + tx * 4 + j;
            C[(size_t)gr * 256 + gc] = acc[i][j] + bias[gc];
        }
    }
}

// =====================================================================
// Kernel 4: flash attention (fp32, online softmax)
// grid: (NQ/64, B*H), block 256 (16x16 threads)
// S tile 64x64 (4x4/thread), O tile 64x32 (4x2/thread)
// =====================================================================
__global__ void flash_attn_kernel(const float* __restrict__ Q,
                                  const float* __restrict__ Kp,
                                  const float* __restrict__ Vp,
                                  float* __restrict__ O)
{
    __shared__ float Qs[64][DH + 1];
    __shared__ float Ks[64][DH + 1];
    __shared__ float Vs[64][DH + 1];
    __shared__ float Ss[64][65];
    __shared__ float m_s[64], l_s[64], alpha_s[64];

    const float SCALE = 0.17677669529663687f;  // 1/sqrt(32)

    int tid = threadIdx.x;
    int tx = tid & 15, ty = tid >> 4;
    int qt = blockIdx.x;
    int bh = blockIdx.y;
    int b = bh >> 3, h = bh & 7;
    int q0 = qt * 64;

    const float* qptr = Q  + (size_t)b * NQ * DD + h * DH;
    const float* kptr = Kp + (size_t)b * LK * DD + h * DH;
    const float* vptr = Vp + (size_t)b * LK * DD + h * DH;

    // load Q tile (64 x 32)
#pragma unroll
    for (int u = 0; u < 2; u++) {
        int fid = (tid << 1) + u;           // 0..511 float4 slots
        int r = fid >> 3, c4 = fid & 7;
        float4 qv = *(const float4*)&qptr[(size_t)(q0 + r) * DD + c4 * 4];
        Qs[r][c4 * 4 + 0] = qv.x; Qs[r][c4 * 4 + 1] = qv.y;
        Qs[r][c4 * 4 + 2] = qv.z; Qs[r][c4 * 4 + 3] = qv.w;
    }
    if (tid < 64) { m_s[tid] = -INFINITY; l_s[tid] = 0.0f; }

    float o[4][2];
#pragma unroll
    for (int i = 0; i < 4; i++) { o[i][0] = 0.0f; o[i][1] = 0.0f; }

    for (int c = 0; c < LK / 64; c++) {
        int kb = c * 64;
        __syncthreads();   // previous iteration's PV done before overwriting Ks/Vs

        // load K, V chunks (each 64x32)
#pragma unroll
        for (int u = 0; u < 2; u++) {
            int fid = (tid << 1) + u;
            int r = fid >> 3, c4 = fid & 7;
            float4 kv = *(const float4*)&kptr[(size_t)(kb + r) * DD + c4 * 4];
            float4 vv = *(const float4*)&vptr[(size_t)(kb + r) * DD + c4 * 4];
            Ks[r][c4 * 4 + 0] = kv.x; Ks[r][c4 * 4 + 1] = kv.y;
            Ks[r][c4 * 4 + 2] = kv.z; Ks[r][c4 * 4 + 3] = kv.w;
            Vs[r][c4 * 4 + 0] = vv.x; Vs[r][c4 * 4 + 1] = vv.y;
            Vs[r][c4 * 4 + 2] = vv.z; Vs[r][c4 * 4 + 3] = vv.w;
        }
        __syncthreads();

        // S = Q K^T * scale
        float s[4][4];
#pragma unroll
        for (int i = 0; i < 4; i++)
#pragma unroll
            for (int j = 0; j < 4; j++) s[i][j] = 0.0f;

#pragma unroll 8
        for (int kk = 0; kk < DH; kk++) {
            float aa[4], bb[4];
#pragma unroll
            for (int i = 0; i < 4; i++) aa[i] = Qs[ty * 4 + i][kk];
#pragma unroll
            for (int j = 0; j < 4; j++) bb[j] = Ks[tx * 4 + j][kk];
#pragma unroll
            for (int i = 0; i < 4; i++)
#pragma unroll
                for (int j = 0; j < 4; j++) s[i][j] += aa[i] * bb[j];
        }
#pragma unroll
        for (int i = 0; i < 4; i++)
#pragma unroll
            for (int j = 0; j < 4; j++)
                Ss[ty * 4 + i][tx * 4 + j] = s[i][j] * SCALE;
        __syncthreads();

        // online softmax per row (64 rows on threads 0..63)
        if (tid < 64) {
            int r = tid;
            float mold = m_s[r];
            float mnew = mold;
#pragma unroll 8
            for (int j = 0; j < 64; j++) mnew = fmaxf(mnew, Ss[r][j]);
            float alpha = expf(mold - mnew);
            float l = l_s[r] * alpha;
#pragma unroll 8
            for (int j = 0; j < 64; j++) {
                float p = expf(Ss[r][j] - mnew);
                Ss[r][j] = p;
                l += p;
            }
            m_s[r] = mnew; l_s[r] = l; alpha_s[r] = alpha;
        }
        __syncthreads();

        // O = O*alpha + P V
        float al[4];
#pragma unroll
        for (int i = 0; i < 4; i++) al[i] = alpha_s[ty * 4 + i];
#pragma unroll
        for (int i = 0; i < 4; i++) { o[i][0] *= al[i]; o[i][1] *= al[i]; }

#pragma unroll 8
        for (int kk = 0; kk < 64; kk++) {
            float aa[4], vv[2];
#pragma unroll
            for (int i = 0; i < 4; i++) aa[i] = Ss[ty * 4 + i][kk];
            vv[0] = Vs[kk][tx * 2 + 0];
            vv[1] = Vs[kk][tx * 2 + 1];
#pragma unroll
            for (int i = 0; i < 4; i++) {
                o[i][0] += aa[i] * vv[0];
                o[i][1] += aa[i] * vv[1];
            }
        }
    }
    __syncthreads();

    // final normalize + write  O[b, q0+r, h*32 + col]
#pragma unroll
    for (int i = 0; i < 4; i++) {
        int r = ty * 4 + i;
        float linv = 1.0f / l_s[r];
        size_t base = ((size_t)b * NQ + q0 + r) * DD + h * DH + tx * 2;
        O[base + 0] = o[i][0] * linv;
        O[base + 1] = o[i][1] * linv;
    }
}

// =====================================================================
// Kernel 5: output projection + spatial embedding fused
// out[r,c] = attn[r,:] @ out_w[c,:] + out_b[c] + pts[r,:3] @ sw[c,:3] + sb[c]
// =====================================================================
__global__ void gemm_out_kernel(const float* __restrict__ A,
                                const float* __restrict__ W,
                                const float* __restrict__ bias,
                                const float* __restrict__ pts,      // [4096,3]
                                const float* __restrict__ sw,       // [256,3]
                                const float* __restrict__ sb,       // [256]
                                float* __restrict__ C)
{
    __shared__ float As[16][64];
    __shared__ float Ws[16][64];

    int tid = threadIdx.x;
    int tx = tid & 15, ty = tid >> 4;
    int m0 = blockIdx.x * 64;
    int n0 = blockIdx.y * 64;
    int lrow = tid >> 2, lkq = tid & 3;

    float acc[4][4];
#pragma unroll
    for (int i = 0; i < 4; i++)
#pragma unroll
        for (int j = 0; j < 4; j++) acc[i][j] = 0.0f;

    for (int k0 = 0; k0 < 256; k0 += 16) {
        float4 av = *(const float4*)&A[((size_t)(m0 + lrow)) * 256 + k0 + lkq * 4];
        float4 wv = *(const float4*)&W[((size_t)(n0 + lrow)) * 256 + k0 + lkq * 4];
        As[lkq * 4 + 0][lrow] = av.x; As[lkq * 4 + 1][lrow] = av.y;
        As[lkq * 4 + 2][lrow] = av.z; As[lkq * 4 + 3][lrow] = av.w;
        Ws[lkq * 4 + 0][lrow] = wv.x; Ws[lkq * 4 + 1][lrow] = wv.y;
        Ws[lkq * 4 + 2][lrow] = wv.z; Ws[lkq * 4 + 3][lrow] = wv.w;
        __syncthreads();

#pragma unroll
        for (int kk = 0; kk < 16; kk++) {
            float4 a = *(const float4*)&As[kk][ty * 4];
            float4 b = *(const float4*)&Ws[kk][tx * 4];
            float aa[4] = {a.x, a.y, a.z, a.w};
            float bb[4] = {b.x, b.y, b.z, b.w};
#pragma unroll
            for (int i = 0; i < 4; i++)
#pragma unroll
                for (int j = 0; j < 4; j++) acc[i][j] += aa[i] * bb[j];
        }
        __syncthreads();
    }

#pragma unroll
    for (int i = 0; i < 4; i++) {
        int gr = m0 + ty * 4 + i;
        float p0 = pts[gr * 3 + 0], p1 = pts[gr * 3 + 1], p2 = pts[gr * 3 + 2];
#pragma unroll
        for (int j = 0; j < 4; j++) {
            int gc = n0 + tx * 4 + j;
            float sp = p0 * sw[gc * 3 + 0] + p1 * sw[gc * 3 + 1] + p2 * sw[gc * 3 + 2] + sb[gc];
            C[(size_t)gr * 256 + gc] = (acc[i][j] + bias[gc]) + sp;
        }
    }
}

// =====================================================================
// Launch
// =====================================================================
extern "C" void kernel_launch(void* const* d_in, const int* in_sizes, int n_in,
                              void* d_out, int out_size)
{
    const float* cur_pts = (const float*)d_in[0];   // [B,N,3]
    const float* cur_f   = (const float*)d_in[1];   // [B,N,D]
    const float* nbr_pts = (const float*)d_in[2];   // [M,B,NN,3]
    const float* nbr_f   = (const float*)d_in[3];   // [M,B,NN,D]
    const float* in_w    = (const float*)d_in[4];   // [3D,D]
    const float* in_b    = (const float*)d_in[5];   // [3D]
    const float* out_w   = (const float*)d_in[6];   // [D,D]
    const float* out_b   = (const float*)d_in[7];   // [D]
    const float* sw      = (const float*)d_in[8];   // [D,3]
    const float* sb      = (const float*)d_in[9];   // [D]
    float* out = (float*)d_out;

    float *dq, *dk, *dv, *dce, *dan, *dat;
    cudaGetSymbolAddress((void**)&dq,  g_q);
    cudaGetSymbolAddress((void**)&dk,  g_k);
    cudaGetSymbolAddress((void**)&dv,  g_v);
    cudaGetSymbolAddress((void**)&dce, g_cur_edge);
    cudaGetSymbolAddress((void**)&dan, g_all_nbr);
    cudaGetSymbolAddress((void**)&dat, g_attn);

    // 1. KNN top-8 (all 6 sets)
    knn_topk_kernel<<<dim3(NQ / 128, NSETS), 128>>>(cur_pts, nbr_pts);

    // 2. edge features
    edge_feats_kernel<<<NSETS * NQ, DD>>>(cur_f, nbr_f);

    // 3. q/k/v projections
    gemm_proj_kernel<<<dim3((BB * NQ) / 64, 4), 256>>>(dce, in_w,            in_b,            dq);
    gemm_proj_kernel<<<dim3((BB * LK) / 64, 4), 256>>>(dan, in_w + 256*256,  in_b + 256,      dk);
    gemm_proj_kernel<<<dim3((BB * LK) / 64, 4), 256>>>(dan, in_w + 512*256,  in_b + 512,      dv);

    // 4. flash attention
    flash_attn_kernel<<<dim3(NQ / 64, BB * HH), 256>>>(dq, dk, dv, dat);

    // 5. out projection + spatial, writes final output
    gemm_out_kernel<<<dim3((BB * NQ) / 64, 4), 256>>>(dat, out_w, out_b, cur_pts, sw, sb, out);
}

// round 2
// speedup vs baseline: 1.1876x; 1.1876x over previous
#include <cuda_runtime.h>
#include <math.h>

// Problem constants
#define BB   2
#define NQ   2048
#define DD   256
#define HH   8
#define DH   32
#define MM   2
#define NNK  2048
#define LK   4096      // M*NN
#define KNN  8
#define NSETS 6

// ---------------- packed f32x2 helpers ----------------
#define FMA2(acc, a, b) asm("fma.rn.f32x2 %0, %1, %2, %0;" : "+l"(acc) : "l"(a), "l"(b))
#define MUL2(d, a, b)   asm("mul.rn.f32x2 %0, %1, %2;" : "=l"(d) : "l"(a), "l"(b))

static __device__ __forceinline__ float2 upk(unsigned long long u) {
    float2 r;
    asm("mov.b64 {%0, %1}, %2;" : "=f"(r.x), "=f"(r.y) : "l"(u));
    return r;
}
static __device__ __forceinline__ unsigned long long pk2(float v) {
    unsigned long long r;
    asm("mov.b64 %0, {%1, %1};" : "=l"(r) : "f"(v));
    return r;
}

// ---------------- scratch ----------------
__device__ float g_cur_edge[BB * NQ * DD];
__device__ float g_all_nbr [BB * LK * DD];
__device__ float g_q   [BB * NQ * DD];
__device__ float g_k   [BB * LK * DD];
__device__ float g_v   [BB * LK * DD];
__device__ float g_attn[BB * NQ * DD];
__device__ int   g_idx [NSETS * NQ * KNN];

// =====================================================================
// Kernel 1: KNN top-8
// =====================================================================
__global__ void knn_topk_kernel(const float* __restrict__ cur_pts,
                                const float* __restrict__ nbr_pts)
{
    int set = blockIdx.y;
    const float* pts = (set < 2) ? (cur_pts + (size_t)set * NQ * 3)
                                 : (nbr_pts + (size_t)(set - 2) * NNK * 3);
    __shared__ float px[2048], py[2048], pz[2048], sq[2048];
    for (int i = threadIdx.x; i < 2048; i += blockDim.x) {
        float x = pts[i * 3 + 0], y = pts[i * 3 + 1], z = pts[i * 3 + 2];
        px[i] = x; py[i] = y; pz[i] = z;
        sq[i] = x * x + y * y + z * z;
    }
    __syncthreads();

    int row = blockIdx.x * blockDim.x + threadIdx.x;
    float bx = px[row], by = py[row], bz = pz[row], bsq = sq[row];

    float bestd[KNN];
    int   besti[KNN];
#pragma unroll
    for (int t = 0; t < KNN; t++) { bestd[t] = INFINITY; besti[t] = -1; }

    for (int j = 0; j < 2048; j++) {
        float dot = bx * px[j] + by * py[j] + bz * pz[j];
        float d2  = bsq + sq[j] - 2.0f * dot;
        if (d2 < bestd[KNN - 1]) {
            int t = KNN - 1;
#pragma unroll
            for (int u = KNN - 1; u > 0; u--) {
                if (bestd[u - 1] > d2) { bestd[u] = bestd[u - 1]; besti[u] = besti[u - 1]; t = u - 1; }
                else break;
            }
            bestd[t] = d2; besti[t] = j;
        }
    }

    int* out = g_idx + ((size_t)set * NQ + row) * KNN;
#pragma unroll
    for (int t = 0; t < KNN; t++) out[t] = besti[t];
}

// =====================================================================
// Kernel 2: edge features
// =====================================================================
__global__ void edge_feats_kernel(const float* __restrict__ cur_f,
                                  const float* __restrict__ nbr_f)
{
    int gid = blockIdx.x;
    int set = gid >> 11;
    int row = gid & 2047;

    const float* f;
    float* outp;
    if (set < 2) {
        f    = cur_f + (size_t)set * NQ * DD;
        outp = g_cur_edge + ((size_t)set * NQ + row) * DD;
    } else {
        int mb = set - 2;
        int m = mb >> 1, b = mb & 1;
        f    = nbr_f + (size_t)mb * NNK * DD;
        outp = g_all_nbr + ((size_t)b * LK + (size_t)m * NNK + row) * DD;
    }

    const int* idx = g_idx + ((size_t)set * NQ + row) * KNN;
    int d = threadIdx.x;

    float acc = 0.0f;
#pragma unroll
    for (int t = 0; t < KNN; t++)
        acc += f[(size_t)idx[t] * DD + d];

    outp[d] = f[(size_t)row * DD + d] - acc * 0.125f;
}

// =====================================================================
// Kernel 3: projection GEMM with FFMA2 (even/odd-k lane partials)
// C[R,256] = A[R,256] @ W[256,256]^T + bias ; 64x64 tile, 256 thr
// interleaved thread tiles: row = ty+16i, col = tx+16j
// =====================================================================
#define GSTR 20
__global__ void __launch_bounds__(256, 2)
gemm_proj_kernel(const float* __restrict__ A,
                 const float* __restrict__ W,
                 const float* __restrict__ bias,
                 float* __restrict__ C)
{
    __shared__ float As[64 * GSTR];
    __shared__ float Ws[64 * GSTR];

    int tid = threadIdx.x;
    int tx = tid & 15, ty = tid >> 4;
    int m0 = blockIdx.x * 64;
    int n0 = blockIdx.y * 64;
    int lrow = tid >> 2, lkq = tid & 3;

    unsigned long long acc2[4][4];
#pragma unroll
    for (int i = 0; i < 4; i++)
#pragma unroll
        for (int j = 0; j < 4; j++) acc2[i][j] = 0ULL;

    for (int k0 = 0; k0 < 256; k0 += 16) {
        float4 av = *(const float4*)&A[((size_t)(m0 + lrow)) * 256 + k0 + lkq * 4];
        float4 wv = *(const float4*)&W[((size_t)(n0 + lrow)) * 256 + k0 + lkq * 4];
        __syncthreads();
        *(float4*)&As[lrow * GSTR + lkq * 4] = av;
        *(float4*)&Ws[lrow * GSTR + lkq * 4] = wv;
        __syncthreads();

#pragma unroll
        for (int kk = 0; kk < 16; kk += 4) {
            ulonglong2 a[4], w[4];
#pragma unroll
            for (int i = 0; i < 4; i++) a[i] = *(const ulonglong2*)&As[(ty + 16 * i) * GSTR + kk];
#pragma unroll
            for (int j = 0; j < 4; j++) w[j] = *(const ulonglong2*)&Ws[(tx + 16 * j) * GSTR + kk];
#pragma unroll
            for (int i = 0; i < 4; i++)
#pragma unroll
                for (int j = 0; j < 4; j++) {
                    FMA2(acc2[i][j], a[i].x, w[j].x);
                    FMA2(acc2[i][j], a[i].y, w[j].y);
                }
        }
    }

#pragma unroll
    for (int i = 0; i < 4; i++) {
        int gr = m0 + ty + 16 * i;
#pragma unroll
        for (int j = 0; j < 4; j++) {
            int gc = n0 + tx + 16 * j;
            float2 f = upk(acc2[i][j]);
            C[(size_t)gr * 256 + gc] = (f.x + f.y) + bias[gc];
        }
    }
}

// =====================================================================
// Kernel 4: flash attention, FFMA2, interleaved tiles, pipelined loads
// q-tile 64, k-chunk 64, 256 threads; grid (32, B*H)
// =====================================================================
#define QSTR 36
#define KSTR 36
#define PSTR 68
#define VSTR 68

__global__ void __launch_bounds__(256, 2)
flash_attn_kernel(const float* __restrict__ Q,
                  const float* __restrict__ Kp,
                  const float* __restrict__ Vp,
                  float* __restrict__ O)
{
    __shared__ float Qs[64 * QSTR];
    __shared__ float Ks[64 * KSTR];
    __shared__ float Ps[64 * PSTR];
    __shared__ float Vt[32 * VSTR];

    const float SCALE = 0.17677669529663687f;  // 1/sqrt(32)

    int tid = threadIdx.x;
    int tx = tid & 15, ty = tid >> 4;
    int q0 = blockIdx.x * 64;
    int bh = blockIdx.y;
    int b = bh >> 3, h = bh & 7;

    const float* qptr = Q  + (size_t)b * NQ * DD + h * DH;
    const float* kptr = Kp + (size_t)b * LK * DD + h * DH;
    const float* vptr = Vp + (size_t)b * LK * DD + h * DH;

    // load Q tile (64 x 32) row-major, stride QSTR
    {
        int fid0 = tid * 2;
#pragma unroll
        for (int u = 0; u < 2; u++) {
            int fid = fid0 + u;
            int r = fid >> 3, c4 = fid & 7;
            float4 qv = *(const float4*)&qptr[(size_t)(q0 + r) * DD + c4 * 4];
            *(float4*)&Qs[r * QSTR + c4 * 4] = qv;
        }
    }

    unsigned long long o2[4][2];
#pragma unroll
    for (int i = 0; i < 4; i++) { o2[i][0] = 0ULL; o2[i][1] = 0ULL; }
    float rm[4], rl[4];
#pragma unroll
    for (int i = 0; i < 4; i++) { rm[i] = -INFINITY; rl[i] = 0.0f; }

    // prefetch chunk 0
    int fid0 = tid * 2;
    int pr[2], pc[2];
#pragma unroll
    for (int u = 0; u < 2; u++) { pr[u] = (fid0 + u) >> 3; pc[u] = ((fid0 + u) & 7) * 4; }

    float4 kreg[2], vreg[2];
#pragma unroll
    for (int u = 0; u < 2; u++) {
        kreg[u] = *(const float4*)&kptr[(size_t)pr[u] * DD + pc[u]];
        vreg[u] = *(const float4*)&vptr[(size_t)pr[u] * DD + pc[u]];
    }

    for (int c = 0; c < LK / 64; c++) {
        __syncthreads();   // prev QK/PV done: Ks/Vt reusable
#pragma unroll
        for (int u = 0; u < 2; u++) {
            *(float4*)&Ks[pr[u] * KSTR + pc[u]] = kreg[u];
            Vt[(pc[u] + 0) * VSTR + pr[u]] = vreg[u].x;
            Vt[(pc[u] + 1) * VSTR + pr[u]] = vreg[u].y;
            Vt[(pc[u] + 2) * VSTR + pr[u]] = vreg[u].z;
            Vt[(pc[u] + 3) * VSTR + pr[u]] = vreg[u].w;
        }
        __syncthreads();

        // prefetch next chunk
        if (c + 1 < LK / 64) {
            int kb = (c + 1) * 64;
#pragma unroll
            for (int u = 0; u < 2; u++) {
                kreg[u] = *(const float4*)&kptr[(size_t)(kb + pr[u]) * DD + pc[u]];
                vreg[u] = *(const float4*)&vptr[(size_t)(kb + pr[u]) * DD + pc[u]];
            }
        }

        // ---- S = Q K^T (even/odd k partials in f32x2 lanes) ----
        unsigned long long s2[4][4];
#pragma unroll
        for (int i = 0; i < 4; i++)
#pragma unroll
            for (int j = 0; j < 4; j++) s2[i][j] = 0ULL;

#pragma unroll
        for (int kk = 0; kk < DH; kk += 4) {
            ulonglong2 a[4], bq[4];
#pragma unroll
            for (int i = 0; i < 4; i++) a[i]  = *(const ulonglong2*)&Qs[(ty + 16 * i) * QSTR + kk];
#pragma unroll
            for (int j = 0; j < 4; j++) bq[j] = *(const ulonglong2*)&Ks[(tx + 16 * j) * KSTR + kk];
#pragma unroll
            for (int i = 0; i < 4; i++)
#pragma unroll
                for (int j = 0; j < 4; j++) {
                    FMA2(s2[i][j], a[i].x, bq[j].x);
                    FMA2(s2[i][j], a[i].y, bq[j].y);
                }
        }

        // ---- distributed online softmax (rows reduced across 16 tx lanes) ----
#pragma unroll
        for (int i = 0; i < 4; i++) {
            float p[4];
            float mx = -INFINITY;
#pragma unroll
            for (int j = 0; j < 4; j++) {
                float2 f = upk(s2[i][j]);
                p[j] = (f.x + f.y) * SCALE;
                mx = fmaxf(mx, p[j]);
            }
#pragma unroll
            for (int off = 8; off >= 1; off >>= 1)
                mx = fmaxf(mx, __shfl_xor_sync(0xffffffffu, mx, off, 16));

            float mnew = fmaxf(rm[i], mx);
            float alpha = __expf(rm[i] - mnew);
            float sum = 0.0f;
#pragma unroll
            for (int j = 0; j < 4; j++) {
                p[j] = __expf(p[j] - mnew);
                sum += p[j];
            }
#pragma unroll
            for (int off = 8; off >= 1; off >>= 1)
                sum += __shfl_xor_sync(0xffffffffu, sum, off, 16);

            rl[i] = rl[i] * alpha + sum;
            rm[i] = mnew;

            unsigned long long a2 = pk2(alpha);
            MUL2(o2[i][0], o2[i][0], a2);
            MUL2(o2[i][1], o2[i][1], a2);

#pragma unroll
            for (int j = 0; j < 4; j++)
                Ps[(ty + 16 * i) * PSTR + tx + 16 * j] = p[j];
        }
        __syncthreads();

        // ---- O += P V (even/odd k partials) ----
#pragma unroll 4
        for (int kk = 0; kk < 64; kk += 4) {
            ulonglong2 pp[4], vv[2];
#pragma unroll
            for (int i = 0; i < 4; i++) pp[i] = *(const ulonglong2*)&Ps[(ty + 16 * i) * PSTR + kk];
#pragma unroll
            for (int j = 0; j < 2; j++) vv[j] = *(const ulonglong2*)&Vt[(tx + 16 * j) * VSTR + kk];
#pragma unroll
            for (int i = 0; i < 4; i++)
#pragma unroll
                for (int j = 0; j < 2; j++) {
                    FMA2(o2[i][j], pp[i].x, vv[j].x);
                    FMA2(o2[i][j], pp[i].y, vv[j].y);
                }
        }
    }

    // ---- epilogue ----
#pragma unroll
    for (int i = 0; i < 4; i++) {
        float linv = 1.0f / rl[i];
        int row = q0 + ty + 16 * i;
#pragma unroll
        for (int j = 0; j < 2; j++) {
            float2 f = upk(o2[i][j]);
            O[((size_t)b * NQ + row) * DD + h * DH + tx + 16 * j] = (f.x + f.y) * linv;
        }
    }
}

// =====================================================================
// Kernel 5: output projection + spatial, FFMA2
// =====================================================================
__global__ void __launch_bounds__(256, 2)
gemm_out_kernel(const float* __restrict__ A,
                const float* __restrict__ W,
                const float* __restrict__ bias,
                const float* __restrict__ pts,
                const float* __restrict__ sw,
                const float* __restrict__ sb,
                float* __restrict__ C)
{
    __shared__ float As[64 * GSTR];
    __shared__ float Ws[64 * GSTR];

    int tid = threadIdx.x;
    int tx = tid & 15, ty = tid >> 4;
    int m0 = blockIdx.x * 64;
    int n0 = blockIdx.y * 64;
    int lrow = tid >> 2, lkq = tid & 3;

    unsigned long long acc2[4][4];
#pragma unroll
    for (int i = 0; i < 4; i++)
#pragma unroll
        for (int j = 0; j < 4; j++) acc2[i][j] = 0ULL;

    for (int k0 = 0; k0 < 256; k0 += 16) {
        float4 av = *(const float4*)&A[((size_t)(m0 + lrow)) * 256 + k0 + lkq * 4];
        float4 wv = *(const float4*)&W[((size_t)(n0 + lrow)) * 256 + k0 + lkq * 4];
        __syncthreads();
        *(float4*)&As[lrow * GSTR + lkq * 4] = av;
        *(float4*)&Ws[lrow * GSTR + lkq * 4] = wv;
        __syncthreads();

#pragma unroll
        for (int kk = 0; kk < 16; kk += 4) {
            ulonglong2 a[4], w[4];
#pragma unroll
            for (int i = 0; i < 4; i++) a[i] = *(const ulonglong2*)&As[(ty + 16 * i) * GSTR + kk];
#pragma unroll
            for (int j = 0; j < 4; j++) w[j] = *(const ulonglong2*)&Ws[(tx + 16 * j) * GSTR + kk];
#pragma unroll
            for (int i = 0; i < 4; i++)
#pragma unroll
                for (int j = 0; j < 4; j++) {
                    FMA2(acc2[i][j], a[i].x, w[j].x);
                    FMA2(acc2[i][j], a[i].y, w[j].y);
                }
        }
    }

#pragma unroll
    for (int i = 0; i < 4; i++) {
        int gr = m0 + ty + 16 * i;
        float p0 = pts[gr * 3 + 0], p1 = pts[gr * 3 + 1], p2 = pts[gr * 3 + 2];
#pragma unroll
        for (int j = 0; j < 4; j++) {
            int gc = n0 + tx + 16 * j;
            float2 f = upk(acc2[i][j]);
            float sp = p0 * sw[gc * 3 + 0] + p1 * sw[gc * 3 + 1] + p2 * sw[gc * 3 + 2] + sb[gc];
            C[(size_t)gr * 256 + gc] = (f.x + f.y) + bias[gc] + sp;
        }
    }
}

// =====================================================================
// Launch
// =====================================================================
extern "C" void kernel_launch(void* const* d_in, const int* in_sizes, int n_in,
                              void* d_out, int out_size)
{
    const float* cur_pts = (const float*)d_in[0];
    const float* cur_f   = (const float*)d_in[1];
    const float* nbr_pts = (const float*)d_in[2];
    const float* nbr_f   = (const float*)d_in[3];
    const float* in_w    = (const float*)d_in[4];
    const float* in_b    = (const float*)d_in[5];
    const float* out_w   = (const float*)d_in[6];
    const float* out_b   = (const float*)d_in[7];
    const float* sw      = (const float*)d_in[8];
    const float* sb      = (const float*)d_in[9];
    float* out = (float*)d_out;

    float *dq, *dk, *dv, *dce, *dan, *dat;
    cudaGetSymbolAddress((void**)&dq,  g_q);
    cudaGetSymbolAddress((void**)&dk,  g_k);
    cudaGetSymbolAddress((void**)&dv,  g_v);
    cudaGetSymbolAddress((void**)&dce, g_cur_edge);
    cudaGetSymbolAddress((void**)&dan, g_all_nbr);
    cudaGetSymbolAddress((void**)&dat, g_attn);

    knn_topk_kernel<<<dim3(NQ / 128, NSETS), 128>>>(cur_pts, nbr_pts);
    edge_feats_kernel<<<NSETS * NQ, DD>>>(cur_f, nbr_f);

    gemm_proj_kernel<<<dim3((BB * NQ) / 64, 4), 256>>>(dce, in_w,           in_b,       dq);
    gemm_proj_kernel<<<dim3((BB * LK) / 64, 4), 256>>>(dan, in_w + 256*256, in_b + 256, dk);
    gemm_proj_kernel<<<dim3((BB * LK) / 64, 4), 256>>>(dan, in_w + 512*256, in_b + 512, dv);

    flash_attn_kernel<<<dim3(NQ / 64, BB * HH), 256>>>(dq, dk, dv, dat);

    gemm_out_kernel<<<dim3((BB * NQ) / 64, 4), 256>>>(dat, out_w, out_b, cur_pts, sw, sb, out);
}

// round 3
// speedup vs baseline: 1.1915x; 1.0033x over previous
#include <cuda_runtime.h>
#include <math.h>

// Problem constants
#define BB   2
#define NQ   2048
#define DD   256
#define HH   8
#define DH   32
#define MM   2
#define NNK  2048
#define LK   4096      // M*NN
#define KNN  8
#define NSETS 6

// ---------------- packed f32x2 helpers ----------------
#define FMA2(acc, a, b) asm("fma.rn.f32x2 %0, %1, %2, %0;" : "+l"(acc) : "l"(a), "l"(b))
#define MUL2(d, a, b)   asm("mul.rn.f32x2 %0, %1, %2;" : "=l"(d) : "l"(a), "l"(b))

static __device__ __forceinline__ float2 upk(unsigned long long u) {
    float2 r;
    asm("mov.b64 {%0, %1}, %2;" : "=f"(r.x), "=f"(r.y) : "l"(u));
    return r;
}
static __device__ __forceinline__ unsigned long long pk2(float v) {
    unsigned long long r;
    asm("mov.b64 %0, {%1, %1};" : "=l"(r) : "f"(v));
    return r;
}

// ---------------- scratch ----------------
__device__ float g_cur_edge[BB * NQ * DD];
__device__ float g_all_nbr [BB * LK * DD];
__device__ float g_q   [BB * NQ * DD];
__device__ float g_k   [BB * LK * DD];
__device__ float g_v   [BB * LK * DD];
__device__ float g_attn[BB * NQ * DD];
__device__ int   g_idx [NSETS * NQ * KNN];

// =====================================================================
// Kernel 1: KNN top-8
// =====================================================================
__global__ void knn_topk_kernel(const float* __restrict__ cur_pts,
                                const float* __restrict__ nbr_pts)
{
    int set = blockIdx.y;
    const float* pts = (set < 2) ? (cur_pts + (size_t)set * NQ * 3)
                                 : (nbr_pts + (size_t)(set - 2) * NNK * 3);
    __shared__ float px[2048], py[2048], pz[2048], sq[2048];
    for (int i = threadIdx.x; i < 2048; i += blockDim.x) {
        float x = pts[i * 3 + 0], y = pts[i * 3 + 1], z = pts[i * 3 + 2];
        px[i] = x; py[i] = y; pz[i] = z;
        sq[i] = x * x + y * y + z * z;
    }
    __syncthreads();

    int row = blockIdx.x * blockDim.x + threadIdx.x;
    float bx = px[row], by = py[row], bz = pz[row], bsq = sq[row];

    float bestd[KNN];
    int   besti[KNN];
#pragma unroll
    for (int t = 0; t < KNN; t++) { bestd[t] = INFINITY; besti[t] = -1; }

    for (int j = 0; j < 2048; j++) {
        float dot = bx * px[j] + by * py[j] + bz * pz[j];
        float d2  = bsq + sq[j] - 2.0f * dot;
        if (d2 < bestd[KNN - 1]) {
            int t = KNN - 1;
#pragma unroll
            for (int u = KNN - 1; u > 0; u--) {
                if (bestd[u - 1] > d2) { bestd[u] = bestd[u - 1]; besti[u] = besti[u - 1]; t = u - 1; }
                else break;
            }
            bestd[t] = d2; besti[t] = j;
        }
    }

    int* out = g_idx + ((size_t)set * NQ + row) * KNN;
#pragma unroll
    for (int t = 0; t < KNN; t++) out[t] = besti[t];
}

// =====================================================================
// Kernel 2: edge features
// =====================================================================
__global__ void edge_feats_kernel(const float* __restrict__ cur_f,
                                  const float* __restrict__ nbr_f)
{
    int gid = blockIdx.x;
    int set = gid >> 11;
    int row = gid & 2047;

    const float* f;
    float* outp;
    if (set < 2) {
        f    = cur_f + (size_t)set * NQ * DD;
        outp = g_cur_edge + ((size_t)set * NQ + row) * DD;
    } else {
        int mb = set - 2;
        int m = mb >> 1, b = mb & 1;
        f    = nbr_f + (size_t)mb * NNK * DD;
        outp = g_all_nbr + ((size_t)b * LK + (size_t)m * NNK + row) * DD;
    }

    const int* idx = g_idx + ((size_t)set * NQ + row) * KNN;
    int d = threadIdx.x;

    float acc = 0.0f;
#pragma unroll
    for (int t = 0; t < KNN; t++)
        acc += f[(size_t)idx[t] * DD + d];

    outp[d] = f[(size_t)row * DD + d] - acc * 0.125f;
}

// =====================================================================
// Kernel 3: projection GEMM, FFMA2, double-buffered k-step 32
// C[R,256] = A[R,256] @ W[256,256]^T + bias ; 64x64 tile, 256 thr
// =====================================================================
#define GSTR 36
__global__ void __launch_bounds__(256, 2)
gemm_proj_kernel(const float* __restrict__ A,
                 const float* __restrict__ W,
                 const float* __restrict__ bias,
                 float* __restrict__ C)
{
    __shared__ float As[2][64 * GSTR];
    __shared__ float Ws[2][64 * GSTR];

    int tid = threadIdx.x;
    int tx = tid & 15, ty = tid >> 4;
    int m0 = blockIdx.x * 64;
    int n0 = blockIdx.y * 64;
    int lrow = tid >> 2, lkq = (tid & 3) * 4;   // row 0..63, k-offset 0/4/8/12

    const float* Arow = A + (size_t)(m0 + lrow) * 256 + lkq;
    const float* Wrow = W + (size_t)(n0 + lrow) * 256 + lkq;

    unsigned long long acc2[4][4];
#pragma unroll
    for (int i = 0; i < 4; i++)
#pragma unroll
        for (int j = 0; j < 4; j++) acc2[i][j] = 0ULL;

    float4 av[2], wv[2];
    // prefetch k-stage 0
#pragma unroll
    for (int u = 0; u < 2; u++) {
        av[u] = *(const float4*)&Arow[u * 16];
        wv[u] = *(const float4*)&Wrow[u * 16];
    }
#pragma unroll
    for (int u = 0; u < 2; u++) {
        *(float4*)&As[0][lrow * GSTR + lkq + u * 16] = av[u];
        *(float4*)&Ws[0][lrow * GSTR + lkq + u * 16] = wv[u];
    }

    for (int it = 0; it < 8; it++) {
        int s = it & 1;
        if (it < 7) {
            int ko = (it + 1) * 32;
#pragma unroll
            for (int u = 0; u < 2; u++) {
                av[u] = *(const float4*)&Arow[ko + u * 16];
                wv[u] = *(const float4*)&Wrow[ko + u * 16];
            }
        }
        __syncthreads();   // stage s visible; all warps done with stage 1-s
        if (it < 7) {
#pragma unroll
            for (int u = 0; u < 2; u++) {
                *(float4*)&As[1 - s][lrow * GSTR + lkq + u * 16] = av[u];
                *(float4*)&Ws[1 - s][lrow * GSTR + lkq + u * 16] = wv[u];
            }
        }

        const float* as = As[s];
        const float* ws = Ws[s];
#pragma unroll
        for (int kk = 0; kk < 32; kk += 4) {
            ulonglong2 a[4], w[4];
#pragma unroll
            for (int i = 0; i < 4; i++) a[i] = *(const ulonglong2*)&as[(ty + 16 * i) * GSTR + kk];
#pragma unroll
            for (int j = 0; j < 4; j++) w[j] = *(const ulonglong2*)&ws[(tx + 16 * j) * GSTR + kk];
#pragma unroll
            for (int i = 0; i < 4; i++)
#pragma unroll
                for (int j = 0; j < 4; j++) {
                    FMA2(acc2[i][j], a[i].x, w[j].x);
                    FMA2(acc2[i][j], a[i].y, w[j].y);
                }
        }
    }

#pragma unroll
    for (int i = 0; i < 4; i++) {
        int gr = m0 + ty + 16 * i;
#pragma unroll
        for (int j = 0; j < 4; j++) {
            int gc = n0 + tx + 16 * j;
            float2 f = upk(acc2[i][j]);
            C[(size_t)gr * 256 + gc] = (f.x + f.y) + bias[gc];
        }
    }
}

// =====================================================================
// Kernel 4: flash attention, FFMA2, double-buffered K/V, 2 syncs/chunk
// q-tile 64, kv-chunk 64, 256 threads; grid (32, B*H); dynamic smem
// =====================================================================
#define QSTR 36
#define KSTR 36
#define PSTR 68
#define VSTR 68
#define SM_QS   0
#define SM_KS   (64 * QSTR)                       // 2 buffers of 64*KSTR
#define SM_VT   (SM_KS + 2 * 64 * KSTR)           // 2 buffers of 32*VSTR
#define SM_PS   (SM_VT + 2 * 32 * VSTR)
#define SM_TOT  (SM_PS + 64 * PSTR)               // floats

__global__ void __launch_bounds__(256, 2)
flash_attn_kernel(const float* __restrict__ Q,
                  const float* __restrict__ Kp,
                  const float* __restrict__ Vp,
                  float* __restrict__ O)
{
    extern __shared__ float sm[];
    float* Qs = sm + SM_QS;
    float* Ps = sm + SM_PS;

    const float SCALE = 0.17677669529663687f;  // 1/sqrt(32)

    int tid = threadIdx.x;
    int tx = tid & 15, ty = tid >> 4;
    int q0 = blockIdx.x * 64;
    int bh = blockIdx.y;
    int b = bh >> 3, h = bh & 7;

    const float* qptr = Q  + (size_t)b * NQ * DD + h * DH;
    const float* kptr = Kp + (size_t)b * LK * DD + h * DH;
    const float* vptr = Vp + (size_t)b * LK * DD + h * DH;

    int fid0 = tid * 2;
    int pr[2], pc[2];
#pragma unroll
    for (int u = 0; u < 2; u++) { pr[u] = (fid0 + u) >> 3; pc[u] = ((fid0 + u) & 7) * 4; }

    // load Q tile (64 x 32)
#pragma unroll
    for (int u = 0; u < 2; u++) {
        float4 qv = *(const float4*)&qptr[(size_t)(q0 + pr[u]) * DD + pc[u]];
        *(float4*)&Qs[pr[u] * QSTR + pc[u]] = qv;
    }

    // prefetch chunk 0 and stage into buffer 0
    float4 kreg[2], vreg[2];
#pragma unroll
    for (int u = 0; u < 2; u++) {
        kreg[u] = *(const float4*)&kptr[(size_t)pr[u] * DD + pc[u]];
        vreg[u] = *(const float4*)&vptr[(size_t)pr[u] * DD + pc[u]];
    }
    {
        float* Ks0 = sm + SM_KS;
        float* Vt0 = sm + SM_VT;
#pragma unroll
        for (int u = 0; u < 2; u++) {
            *(float4*)&Ks0[pr[u] * KSTR + pc[u]] = kreg[u];
            Vt0[(pc[u] + 0) * VSTR + pr[u]] = vreg[u].x;
            Vt0[(pc[u] + 1) * VSTR + pr[u]] = vreg[u].y;
            Vt0[(pc[u] + 2) * VSTR + pr[u]] = vreg[u].z;
            Vt0[(pc[u] + 3) * VSTR + pr[u]] = vreg[u].w;
        }
    }
    __syncthreads();

    unsigned long long o2[4][2];
#pragma unroll
    for (int i = 0; i < 4; i++) { o2[i][0] = 0ULL; o2[i][1] = 0ULL; }
    float rm[4], rl[4];
#pragma unroll
    for (int i = 0; i < 4; i++) { rm[i] = -INFINITY; rl[i] = 0.0f; }

    for (int c = 0; c < LK / 64; c++) {
        int cur = c & 1;
        float* Ksc = sm + SM_KS + cur * (64 * KSTR);
        float* Vtc = sm + SM_VT + cur * (32 * VSTR);
        float* Ksn = sm + SM_KS + (1 - cur) * (64 * KSTR);
        float* Vtn = sm + SM_VT + (1 - cur) * (32 * VSTR);

        // prefetch chunk c+1 into registers (consumed after next barrier)
        bool more = (c + 1 < LK / 64);
        if (more) {
            int kb = (c + 1) * 64;
#pragma unroll
            for (int u = 0; u < 2; u++) {
                kreg[u] = *(const float4*)&kptr[(size_t)(kb + pr[u]) * DD + pc[u]];
                vreg[u] = *(const float4*)&vptr[(size_t)(kb + pr[u]) * DD + pc[u]];
            }
        }

        // ---- S = Q K^T (even/odd k partials in f32x2 lanes) ----
        unsigned long long s2[4][4];
#pragma unroll
        for (int i = 0; i < 4; i++)
#pragma unroll
            for (int j = 0; j < 4; j++) s2[i][j] = 0ULL;

#pragma unroll
        for (int kk = 0; kk < DH; kk += 4) {
            ulonglong2 a[4], bq[4];
#pragma unroll
            for (int i = 0; i < 4; i++) a[i]  = *(const ulonglong2*)&Qs[(ty + 16 * i) * QSTR + kk];
#pragma unroll
            for (int j = 0; j < 4; j++) bq[j] = *(const ulonglong2*)&Ksc[(tx + 16 * j) * KSTR + kk];
#pragma unroll
            for (int i = 0; i < 4; i++)
#pragma unroll
                for (int j = 0; j < 4; j++) {
                    FMA2(s2[i][j], a[i].x, bq[j].x);
                    FMA2(s2[i][j], a[i].y, bq[j].y);
                }
        }

        // ---- distributed online softmax (rows reduced across 16 tx lanes) ----
#pragma unroll
        for (int i = 0; i < 4; i++) {
            float p[4];
            float mx = -INFINITY;
#pragma unroll
            for (int j = 0; j < 4; j++) {
                float2 f = upk(s2[i][j]);
                p[j] = (f.x + f.y) * SCALE;
                mx = fmaxf(mx, p[j]);
            }
#pragma unroll
            for (int off = 8; off >= 1; off >>= 1)
                mx = fmaxf(mx, __shfl_xor_sync(0xffffffffu, mx, off, 16));

            float mnew = fmaxf(rm[i], mx);
            float alpha = __expf(rm[i] - mnew);
            float sum = 0.0f;
#pragma unroll
            for (int j = 0; j < 4; j++) {
                p[j] = __expf(p[j] - mnew);
                sum += p[j];
            }
#pragma unroll
            for (int off = 8; off >= 1; off >>= 1)
                sum += __shfl_xor_sync(0xffffffffu, sum, off, 16);

            rl[i] = rl[i] * alpha + sum;
            rm[i] = mnew;

            unsigned long long a2 = pk2(alpha);
            MUL2(o2[i][0], o2[i][0], a2);
            MUL2(o2[i][1], o2[i][1], a2);

#pragma unroll
            for (int j = 0; j < 4; j++)
                Ps[(ty + 16 * i) * PSTR + tx + 16 * j] = p[j];
        }
        __syncthreads();   // Ps visible; all warps past QK(cur) and PV(c-1)

        // stage next chunk into the other buffer (overlaps PV below)
        if (more) {
#pragma unroll
            for (int u = 0; u < 2; u++) {
                *(float4*)&Ksn[pr[u] * KSTR + pc[u]] = kreg[u];
                Vtn[(pc[u] + 0) * VSTR + pr[u]] = vreg[u].x;
                Vtn[(pc[u] + 1) * VSTR + pr[u]] = vreg[u].y;
                Vtn[(pc[u] + 2) * VSTR + pr[u]] = vreg[u].z;
                Vtn[(pc[u] + 3) * VSTR + pr[u]] = vreg[u].w;
            }
        }

        // ---- O += P V (even/odd k partials) ----
#pragma unroll 4
        for (int kk = 0; kk < 64; kk += 4) {
            ulonglong2 pp[4], vv[2];
#pragma unroll
            for (int i = 0; i < 4; i++) pp[i] = *(const ulonglong2*)&Ps[(ty + 16 * i) * PSTR + kk];
#pragma unroll
            for (int j = 0; j < 2; j++) vv[j] = *(const ulonglong2*)&Vtc[(tx + 16 * j) * VSTR + kk];
#pragma unroll
            for (int i = 0; i < 4; i++)
#pragma unroll
                for (int j = 0; j < 2; j++) {
                    FMA2(o2[i][j], pp[i].x, vv[j].x);
                    FMA2(o2[i][j], pp[i].y, vv[j].y);
                }
        }
        __syncthreads();   // next-buffer STS visible before QK(c+1); Ps reusable
    }

    // ---- epilogue ----
#pragma unroll
    for (int i = 0; i < 4; i++) {
        float linv = 1.0f / rl[i];
        int row = q0 + ty + 16 * i;
#pragma unroll
        for (int j = 0; j < 2; j++) {
            float2 f = upk(o2[i][j]);
            O[((size_t)b * NQ + row) * DD + h * DH + tx + 16 * j] = (f.x + f.y) * linv;
        }
    }
}

// =====================================================================
// Kernel 5: output projection + spatial, FFMA2, double-buffered
// =====================================================================
__global__ void __launch_bounds__(256, 2)
gemm_out_kernel(const float* __restrict__ A,
                const float* __restrict__ W,
                const float* __restrict__ bias,
                const float* __restrict__ pts,
                const float* __restrict__ sw,
                const float* __restrict__ sb,
                float* __restrict__ C)
{
    __shared__ float As[2][64 * GSTR];
    __shared__ float Ws[2][64 * GSTR];

    int tid = threadIdx.x;
    int tx = tid & 15, ty = tid >> 4;
    int m0 = blockIdx.x * 64;
    int n0 = blockIdx.y * 64;
    int lrow = tid >> 2, lkq = (tid & 3) * 4;

    const float* Arow = A + (size_t)(m0 + lrow) * 256 + lkq;
    const float* Wrow = W + (size_t)(n0 + lrow) * 256 + lkq;

    unsigned long long acc2[4][4];
#pragma unroll
    for (int i = 0; i < 4; i++)
#pragma unroll
        for (int j = 0; j < 4; j++) acc2[i][j] = 0ULL;

    float4 av[2], wv[2];
#pragma unroll
    for (int u = 0; u < 2; u++) {
        av[u] = *(const float4*)&Arow[u * 16];
        wv[u] = *(const float4*)&Wrow[u * 16];
    }
#pragma unroll
    for (int u = 0; u < 2; u++) {
        *(float4*)&As[0][lrow * GSTR + lkq + u * 16] = av[u];
        *(float4*)&Ws[0][lrow * GSTR + lkq + u * 16] = wv[u];
    }

    for (int it = 0; it < 8; it++) {
        int s = it & 1;
        if (it < 7) {
            int ko = (it + 1) * 32;
#pragma unroll
            for (int u = 0; u < 2; u++) {
                av[u] = *(const float4*)&Arow[ko + u * 16];
                wv[u] = *(const float4*)&Wrow[ko + u * 16];
            }
        }
        __syncthreads();
        if (it < 7) {
#pragma unroll
            for (int u = 0; u < 2; u++) {
                *(float4*)&As[1 - s][lrow * GSTR + lkq + u * 16] = av[u];
                *(float4*)&Ws[1 - s][lrow * GSTR + lkq + u * 16] = wv[u];
            }
        }

        const float* as = As[s];
        const float* ws = Ws[s];
#pragma unroll
        for (int kk = 0; kk < 32; kk += 4) {
            ulonglong2 a[4], w[4];
#pragma unroll
            for (int i = 0; i < 4; i++) a[i] = *(const ulonglong2*)&as[(ty + 16 * i) * GSTR + kk];
#pragma unroll
            for (int j = 0; j < 4; j++) w[j] = *(const ulonglong2*)&ws[(tx + 16 * j) * GSTR + kk];
#pragma unroll
            for (int i = 0; i < 4; i++)
#pragma unroll
                for (int j = 0; j < 4; j++) {
                    FMA2(acc2[i][j], a[i].x, w[j].x);
                    FMA2(acc2[i][j], a[i].y, w[j].y);
                }
        }
    }

#pragma unroll
    for (int i = 0; i < 4; i++) {
        int gr = m0 + ty + 16 * i;
        float p0 = pts[gr * 3 + 0], p1 = pts[gr * 3 + 1], p2 = pts[gr * 3 + 2];
#pragma unroll
        for (int j = 0; j < 4; j++) {
            int gc = n0 + tx + 16 * j;
            float2 f = upk(acc2[i][j]);
            float sp = p0 * sw[gc * 3 + 0] + p1 * sw[gc * 3 + 1] + p2 * sw[gc * 3 + 2] + sb[gc];
            C[(size_t)gr * 256 + gc] = (f.x + f.y) + bias[gc] + sp;
        }
    }
}

// =====================================================================
// Launch
// =====================================================================
extern "C" void kernel_launch(void* const* d_in, const int* in_sizes, int n_in,
                              void* d_out, int out_size)
{
    const float* cur_pts = (const float*)d_in[0];
    const float* cur_f   = (const float*)d_in[1];
    const float* nbr_pts = (const float*)d_in[2];
    const float* nbr_f   = (const float*)d_in[3];
    const float* in_w    = (const float*)d_in[4];
    const float* in_b    = (const float*)d_in[5];
    const float* out_w   = (const float*)d_in[6];
    const float* out_b   = (const float*)d_in[7];
    const float* sw      = (const float*)d_in[8];
    const float* sb      = (const float*)d_in[9];
    float* out = (float*)d_out;

    float *dq, *dk, *dv, *dce, *dan, *dat;
    cudaGetSymbolAddress((void**)&dq,  g_q);
    cudaGetSymbolAddress((void**)&dk,  g_k);
    cudaGetSymbolAddress((void**)&dv,  g_v);
    cudaGetSymbolAddress((void**)&dce, g_cur_edge);
    cudaGetSymbolAddress((void**)&dan, g_all_nbr);
    cudaGetSymbolAddress((void**)&dat, g_attn);

    static int attr_set = 0;
    if (!attr_set) {
        cudaFuncSetAttribute(flash_attn_kernel,
                             cudaFuncAttributeMaxDynamicSharedMemorySize,
                             SM_TOT * (int)sizeof(float));
        attr_set = 1;
    }

    knn_topk_kernel<<<dim3(NQ / 128, NSETS), 128>>>(cur_pts, nbr_pts);
    edge_feats_kernel<<<NSETS * NQ, DD>>>(cur_f, nbr_f);

    gemm_proj_kernel<<<dim3((BB * NQ) / 64, 4), 256>>>(dce, in_w,           in_b,       dq);
    gemm_proj_kernel<<<dim3((BB * LK) / 64, 4), 256>>>(dan, in_w + 256*256, in_b + 256, dk);
    gemm_proj_kernel<<<dim3((BB * LK) / 64, 4), 256>>>(dan, in_w + 512*256, in_b + 512, dv);

    flash_attn_kernel<<<dim3(NQ / 64, BB * HH), 256, SM_TOT * (int)sizeof(float)>>>(dq, dk, dv, dat);

    gemm_out_kernel<<<dim3((BB * NQ) / 64, 4), 256>>>(dat, out_w, out_b, cur_pts, sw, sb, out);
}

// round 5
// speedup vs baseline: 2.3655x; 1.9853x over previous
#include <cuda_runtime.h>
#include <math.h>
#include <stdint.h>

// Problem constants
#define BB   2
#define NQ   2048
#define DD   256
#define HH   8
#define DH   32
#define LK   4096      // M*NN
#define NNK  2048
#define KNN  8
#define NSETS 6

// ---------------- packed f32x2 helpers ----------------
#define FMA2(acc, a, b) asm("fma.rn.f32x2 %0, %1, %2, %0;" : "+l"(acc) : "l"(a), "l"(b))

static __device__ __forceinline__ float2 upk(unsigned long long u) {
    float2 r;
    asm("mov.b64 {%0, %1}, %2;" : "=f"(r.x), "=f"(r.y) : "l"(u));
    return r;
}
static __device__ __forceinline__ uint32_t f2tf32(float x) {
    uint32_t u;
    asm("cvt.rna.tf32.f32 %0, %1;" : "=r"(u) : "f"(x));
    return u;
}

// m16n8k8 tf32 mma: D += A*B  (A row-major 16x8, B col-major 8x8, fp32 accum)
static __device__ __forceinline__ void mma_tf32(float& d0, float& d1, float& d2, float& d3,
                                                uint32_t a0, uint32_t a1, uint32_t a2, uint32_t a3,
                                                uint32_t b0, uint32_t b1)
{
    asm volatile(
        "mma.sync.aligned.m16n8k8.row.col.f32.tf32.tf32.f32 "
        "{%0,%1,%2,%3}, {%4,%5,%6,%7}, {%8,%9}, {%0,%1,%2,%3};"
        : "+f"(d0), "+f"(d1), "+f"(d2), "+f"(d3)
        : "r"(a0), "r"(a1), "r"(a2), "r"(a3), "r"(b0), "r"(b1));
}

// ---------------- scratch ----------------
__device__ float g_cur_edge[BB * NQ * DD];
__device__ float g_all_nbr [BB * LK * DD];
__device__ float g_q   [BB * NQ * DD];
__device__ float g_k   [BB * LK * DD];
__device__ float g_v   [BB * LK * DD];
__device__ float g_attn[BB * NQ * DD];
__device__ int   g_idx [NSETS * NQ * KNN];

// =====================================================================
// Kernel 1: KNN top-8
// =====================================================================
__global__ void knn_topk_kernel(const float* __restrict__ cur_pts,
                                const float* __restrict__ nbr_pts)
{
    int set = blockIdx.y;
    const float* pts = (set < 2) ? (cur_pts + (size_t)set * NQ * 3)
                                 : (nbr_pts + (size_t)(set - 2) * NNK * 3);
    __shared__ float px[2048], py[2048], pz[2048], sq[2048];
    for (int i = threadIdx.x; i < 2048; i += blockDim.x) {
        float x = pts[i * 3 + 0], y = pts[i * 3 + 1], z = pts[i * 3 + 2];
        px[i] = x; py[i] = y; pz[i] = z;
        sq[i] = x * x + y * y + z * z;
    }
    __syncthreads();

    int row = blockIdx.x * blockDim.x + threadIdx.x;
    float bx = px[row], by = py[row], bz = pz[row], bsq = sq[row];

    float bestd[KNN];
    int   besti[KNN];
#pragma unroll
    for (int t = 0; t < KNN; t++) { bestd[t] = INFINITY; besti[t] = -1; }

    for (int j = 0; j < 2048; j++) {
        float dot = bx * px[j] + by * py[j] + bz * pz[j];
        float d2  = bsq + sq[j] - 2.0f * dot;
        if (d2 < bestd[KNN - 1]) {
            int t = KNN - 1;
#pragma unroll
            for (int u = KNN - 1; u > 0; u--) {
                if (bestd[u - 1] > d2) { bestd[u] = bestd[u - 1]; besti[u] = besti[u - 1]; t = u - 1; }
                else break;
            }
            bestd[t] = d2; besti[t] = j;
        }
    }

    int* out = g_idx + ((size_t)set * NQ + row) * KNN;
#pragma unroll
    for (int t = 0; t < KNN; t++) out[t] = besti[t];
}

// =====================================================================
// Kernel 2: edge features
// =====================================================================
__global__ void edge_feats_kernel(const float* __restrict__ cur_f,
                                  const float* __restrict__ nbr_f)
{
    int gid = blockIdx.x;
    int set = gid >> 11;
    int row = gid & 2047;

    const float* f;
    float* outp;
    if (set < 2) {
        f    = cur_f + (size_t)set * NQ * DD;
        outp = g_cur_edge + ((size_t)set * NQ + row) * DD;
    } else {
        int mb = set - 2;
        int m = mb >> 1, b = mb & 1;
        f    = nbr_f + (size_t)mb * NNK * DD;
        outp = g_all_nbr + ((size_t)b * LK + (size_t)m * NNK + row) * DD;
    }

    const int* idx = g_idx + ((size_t)set * NQ + row) * KNN;
    int d = threadIdx.x;

    float acc = 0.0f;
#pragma unroll
    for (int t = 0; t < KNN; t++)
        acc += f[(size_t)idx[t] * DD + d];

    outp[d] = f[(size_t)row * DD + d] - acc * 0.125f;
}

// =====================================================================
// Kernel 3: projection GEMM, FFMA2, double-buffered
// optional tf32 rounding of output (for MMA operands)
// =====================================================================
#define GSTR 36
__global__ void __launch_bounds__(256, 2)
gemm_proj_kernel(const float* __restrict__ A,
                 const float* __restrict__ W,
                 const float* __restrict__ bias,
                 float* __restrict__ C,
                 int round_tf32)
{
    __shared__ float As[2][64 * GSTR];
    __shared__ float Ws[2][64 * GSTR];

    int tid = threadIdx.x;
    int tx = tid & 15, ty = tid >> 4;
    int m0 = blockIdx.x * 64;
    int n0 = blockIdx.y * 64;
    int lrow = tid >> 2, lkq = (tid & 3) * 4;

    const float* Arow = A + (size_t)(m0 + lrow) * 256 + lkq;
    const float* Wrow = W + (size_t)(n0 + lrow) * 256 + lkq;

    unsigned long long acc2[4][4];
#pragma unroll
    for (int i = 0; i < 4; i++)
#pragma unroll
        for (int j = 0; j < 4; j++) acc2[i][j] = 0ULL;

    float4 av[2], wv[2];
#pragma unroll
    for (int u = 0; u < 2; u++) {
        av[u] = *(const float4*)&Arow[u * 16];
        wv[u] = *(const float4*)&Wrow[u * 16];
    }
#pragma unroll
    for (int u = 0; u < 2; u++) {
        *(float4*)&As[0][lrow * GSTR + lkq + u * 16] = av[u];
        *(float4*)&Ws[0][lrow * GSTR + lkq + u * 16] = wv[u];
    }

    for (int it = 0; it < 8; it++) {
        int s = it & 1;
        if (it < 7) {
            int ko = (it + 1) * 32;
#pragma unroll
            for (int u = 0; u < 2; u++) {
                av[u] = *(const float4*)&Arow[ko + u * 16];
                wv[u] = *(const float4*)&Wrow[ko + u * 16];
            }
        }
        __syncthreads();
        if (it < 7) {
#pragma unroll
            for (int u = 0; u < 2; u++) {
                *(float4*)&As[1 - s][lrow * GSTR + lkq + u * 16] = av[u];
                *(float4*)&Ws[1 - s][lrow * GSTR + lkq + u * 16] = wv[u];
            }
        }

        const float* as = As[s];
        const float* ws = Ws[s];
#pragma unroll
        for (int kk = 0; kk < 32; kk += 4) {
            ulonglong2 a[4], w[4];
#pragma unroll
            for (int i = 0; i < 4; i++) a[i] = *(const ulonglong2*)&as[(ty + 16 * i) * GSTR + kk];
#pragma unroll
            for (int j = 0; j < 4; j++) w[j] = *(const ulonglong2*)&ws[(tx + 16 * j) * GSTR + kk];
#pragma unroll
            for (int i = 0; i < 4; i++)
#pragma unroll
                for (int j = 0; j < 4; j++) {
                    FMA2(acc2[i][j], a[i].x, w[j].x);
                    FMA2(acc2[i][j], a[i].y, w[j].y);
                }
        }
    }

#pragma unroll
    for (int i = 0; i < 4; i++) {
        int gr = m0 + ty + 16 * i;
#pragma unroll
        for (int j = 0; j < 4; j++) {
            int gc = n0 + tx + 16 * j;
            float2 f = upk(acc2[i][j]);
            float val = (f.x + f.y) + bias[gc];
            if (round_tf32) val = __uint_as_float(f2tf32(val));
            C[(size_t)gr * 256 + gc] = val;
        }
    }
}

// =====================================================================
// Kernel 4: flash attention on tensor pipe (mma.sync m16n8k8 tf32)
// 128 q-rows per CTA, 8 warps (16 rows each); kv chunk = 128
// K/V chunks double-buffered in dynamic smem (strides 36/40: conflict-free
// fragment loads); P kept in registers via quad shuffles; no-max softmax.
// =====================================================================
#define KS_STR 36
#define VS_STR 40
#define SMEM_K_OFF(buf) ((buf) * (128 * KS_STR))
#define SMEM_V_OFF(buf) (2 * 128 * KS_STR + (buf) * (128 * VS_STR))
#define FLASH_SMEM_FLOATS (2 * 128 * KS_STR + 2 * 128 * VS_STR)

__global__ void __launch_bounds__(256, 2)
flash_mma_kernel(const float* __restrict__ Q, const float* __restrict__ K,
                 const float* __restrict__ V, float* __restrict__ O)
{
    extern __shared__ float sm[];

    const float SCALE = 0.17677669529663687f;   // 1/sqrt(32)
    int tid = threadIdx.x;
    int wid = tid >> 5, lane = tid & 31;
    int g = lane >> 2, j = lane & 3;
    int q0 = blockIdx.x * 128;
    int bh = blockIdx.y, b = bh >> 3, h = bh & 7;

    const float* qp = Q + ((size_t)b * NQ + q0 + wid * 16) * DD + h * DH;
    const float* kp = K + (size_t)b * LK * DD + h * DH;
    const float* vp = V + (size_t)b * LK * DD + h * DH;

    // ---- Q fragments in registers (rows: g, g+8 of this warp's 16) ----
    uint32_t aq[4][4];
#pragma unroll
    for (int kt = 0; kt < 4; kt++) {
        aq[kt][0] = __float_as_uint(qp[(size_t)g * DD + kt * 8 + j]);
        aq[kt][1] = __float_as_uint(qp[(size_t)(g + 8) * DD + kt * 8 + j]);
        aq[kt][2] = __float_as_uint(qp[(size_t)g * DD + kt * 8 + j + 4]);
        aq[kt][3] = __float_as_uint(qp[(size_t)(g + 8) * DD + kt * 8 + j + 4]);
    }

    // ---- O accumulators + row sums ----
    float o[4][4];
#pragma unroll
    for (int n = 0; n < 4; n++)
#pragma unroll
        for (int r = 0; r < 4; r++) o[n][r] = 0.0f;
    float l0 = 0.0f, l1 = 0.0f;

    // ---- stage chunk 0 ----
    int sr = tid >> 1;                 // 0..127 (row), 2 float4 per thread per array
    int sc = (tid & 1) * 16;           // byte-col group: 2 float4 halves? -> cols 0..15 / 16..31
    // each thread: rows sr, loads cols [sc, sc+16) as 4 floats x? use float4 pairs:
    // simpler mapping: 1024 float4 per array, 4 per thread
    float4 kpre[4], vpre[4];
    int rr[4], cc[4];
#pragma unroll
    for (int u = 0; u < 4; u++) {
        int fid = tid + 256 * u;       // 0..1023
        rr[u] = fid >> 3;
        cc[u] = (fid & 7) * 4;
        kpre[u] = *(const float4*)&kp[(size_t)rr[u] * DD + cc[u]];
        vpre[u] = *(const float4*)&vp[(size_t)rr[u] * DD + cc[u]];
    }
#pragma unroll
    for (int u = 0; u < 4; u++) {
        *(float4*)&sm[SMEM_K_OFF(0) + rr[u] * KS_STR + cc[u]] = kpre[u];
        *(float4*)&sm[SMEM_V_OFF(0) + rr[u] * VS_STR + cc[u]] = vpre[u];
    }
    (void)sr; (void)sc;

    for (int c = 0; c < 32; c++) {
        int buf = c & 1;
        // prefetch next chunk into registers (LDG overlaps barrier + compute)
        if (c < 31) {
            int kb = (c + 1) * 128;
#pragma unroll
            for (int u = 0; u < 4; u++) {
                kpre[u] = *(const float4*)&kp[(size_t)(kb + rr[u]) * DD + cc[u]];
                vpre[u] = *(const float4*)&vp[(size_t)(kb + rr[u]) * DD + cc[u]];
            }
        }
        __syncthreads();   // buf stored (prev iter) visible; all prior reads done

        const float* Ks = &sm[SMEM_K_OFF(buf)];
        const float* Vs = &sm[SMEM_V_OFF(buf)];

        // two halves of 64 kv columns each (limits live S registers)
#pragma unroll
        for (int nh = 0; nh < 2; nh++) {
            // ---- S = Q K^T for 8 n-tiles ----
            float s[8][4];
#pragma unroll
            for (int nt = 0; nt < 8; nt++)
#pragma unroll
                for (int r = 0; r < 4; r++) s[nt][r] = 0.0f;

#pragma unroll
            for (int kt = 0; kt < 4; kt++) {
#pragma unroll
                for (int nt = 0; nt < 8; nt++) {
                    int kvrow = nh * 64 + nt * 8 + g;
                    uint32_t b0 = __float_as_uint(Ks[kvrow * KS_STR + kt * 8 + j]);
                    uint32_t b1 = __float_as_uint(Ks[kvrow * KS_STR + kt * 8 + j + 4]);
                    mma_tf32(s[nt][0], s[nt][1], s[nt][2], s[nt][3],
                             aq[kt][0], aq[kt][1], aq[kt][2], aq[kt][3], b0, b1);
                }
            }

            // ---- softmax (no max-shift) + P->A-frag conversion + PV ----
#pragma unroll
            for (int nt = 0; nt < 8; nt++) {
                float p0 = __expf(s[nt][0] * SCALE);
                float p1 = __expf(s[nt][1] * SCALE);
                float p2 = __expf(s[nt][2] * SCALE);
                float p3 = __expf(s[nt][3] * SCALE);
                l0 += p0 + p1;
                l1 += p2 + p3;

                // convert C-layout (rows g,g+8; cols 2j,2j+1) to A-layout
                // (cols j and j+4) via quad shuffles
                int src_lo = (lane & ~3) | (j >> 1);
                int src_hi = src_lo + 2;
                float x0l = __shfl_sync(0xffffffffu, p0, src_lo);
                float x1l = __shfl_sync(0xffffffffu, p1, src_lo);
                float x2l = __shfl_sync(0xffffffffu, p2, src_lo);
                float x3l = __shfl_sync(0xffffffffu, p3, src_lo);
                float x0h = __shfl_sync(0xffffffffu, p0, src_hi);
                float x1h = __shfl_sync(0xffffffffu, p1, src_hi);
                float x2h = __shfl_sync(0xffffffffu, p2, src_hi);
                float x3h = __shfl_sync(0xffffffffu, p3, src_hi);
                uint32_t pa0 = f2tf32((j & 1) ? x1l : x0l);   // row g,   col j
                uint32_t pa1 = f2tf32((j & 1) ? x3l : x2l);   // row g+8, col j
                uint32_t pa2 = f2tf32((j & 1) ? x1h : x0h);   // row g,   col j+4
                uint32_t pa3 = f2tf32((j & 1) ? x3h : x2h);   // row g+8, col j+4

                int t = nh * 8 + nt;     // kv k-tile for PV
#pragma unroll
                for (int no = 0; no < 4; no++) {
                    uint32_t b0 = __float_as_uint(Vs[(t * 8 + j) * VS_STR + no * 8 + g]);
                    uint32_t b1 = __float_as_uint(Vs[(t * 8 + j + 4) * VS_STR + no * 8 + g]);
                    mma_tf32(o[no][0], o[no][1], o[no][2], o[no][3],
                             pa0, pa1, pa2, pa3, b0, b1);
                }
            }
        }

        // stage prefetched chunk into the other buffer
        if (c < 31) {
            int nb = 1 - buf;
#pragma unroll
            for (int u = 0; u < 4; u++) {
                *(float4*)&sm[SMEM_K_OFF(nb) + rr[u] * KS_STR + cc[u]] = kpre[u];
                *(float4*)&sm[SMEM_V_OFF(nb) + rr[u] * VS_STR + cc[u]] = vpre[u];
            }
        }
    }

    // ---- epilogue: quad-reduce l, normalize, store ----
    l0 += __shfl_xor_sync(0xffffffffu, l0, 1, 4);
    l0 += __shfl_xor_sync(0xffffffffu, l0, 2, 4);
    l1 += __shfl_xor_sync(0xffffffffu, l1, 1, 4);
    l1 += __shfl_xor_sync(0xffffffffu, l1, 2, 4);
    float inv0 = 1.0f / l0, inv1 = 1.0f / l1;

    float* op = O + ((size_t)b * NQ + q0 + wid * 16) * DD + h * DH;
#pragma unroll
    for (int no = 0; no < 4; no++) {
        int col = no * 8 + 2 * j;
        float2 lo = make_float2(o[no][0] * inv0, o[no][1] * inv0);
        float2 hi = make_float2(o[no][2] * inv1, o[no][3] * inv1);
        *(float2*)&op[(size_t)g * DD + col]       = lo;
        *(float2*)&op[(size_t)(g + 8) * DD + col] = hi;
    }
}

// =====================================================================
// Kernel 5: output projection + spatial, FFMA2, double-buffered
// =====================================================================
__global__ void __launch_bounds__(256, 2)
gemm_out_kernel(const float* __restrict__ A,
                const float* __restrict__ W,
                const float* __restrict__ bias,
                const float* __restrict__ pts,
                const float* __restrict__ sw,
                const float* __restrict__ sb,
                float* __restrict__ C)
{
    __shared__ float As[2][64 * GSTR];
    __shared__ float Ws[2][64 * GSTR];

    int tid = threadIdx.x;
    int tx = tid & 15, ty = tid >> 4;
    int m0 = blockIdx.x * 64;
    int n0 = blockIdx.y * 64;
    int lrow = tid >> 2, lkq = (tid & 3) * 4;

    const float* Arow = A + (size_t)(m0 + lrow) * 256 + lkq;
    const float* Wrow = W + (size_t)(n0 + lrow) * 256 + lkq;

    unsigned long long acc2[4][4];
#pragma unroll
    for (int i = 0; i < 4; i++)
#pragma unroll
        for (int j = 0; j < 4; j++) acc2[i][j] = 0ULL;

    float4 av[2], wv[2];
#pragma unroll
    for (int u = 0; u < 2; u++) {
        av[u] = *(const float4*)&Arow[u * 16];
        wv[u] = *(const float4*)&Wrow[u * 16];
    }
#pragma unroll
    for (int u = 0; u < 2; u++) {
        *(float4*)&As[0][lrow * GSTR + lkq + u * 16] = av[u];
        *(float4*)&Ws[0][lrow * GSTR + lkq + u * 16] = wv[u];
    }

    for (int it = 0; it < 8; it++) {
        int s = it & 1;
        if (it < 7) {
            int ko = (it + 1) * 32;
#pragma unroll
            for (int u = 0; u < 2; u++) {
                av[u] = *(const float4*)&Arow[ko + u * 16];
                wv[u] = *(const float4*)&Wrow[ko + u * 16];
            }
        }
        __syncthreads();
        if (it < 7) {
#pragma unroll
            for (int u = 0; u < 2; u++) {
                *(float4*)&As[1 - s][lrow * GSTR + lkq + u * 16] = av[u];
                *(float4*)&Ws[1 - s][lrow * GSTR + lkq + u * 16] = wv[u];
            }
        }

        const float* as = As[s];
        const float* ws = Ws[s];
#pragma unroll
        for (int kk = 0; kk < 32; kk += 4) {
            ulonglong2 a[4], w[4];
#pragma unroll
            for (int i = 0; i < 4; i++) a[i] = *(const ulonglong2*)&as[(ty + 16 * i) * GSTR + kk];
#pragma unroll
            for (int j = 0; j < 4; j++) w[j] = *(const ulonglong2*)&ws[(tx + 16 * j) * GSTR + kk];
#pragma unroll
            for (int i = 0; i < 4; i++)
#pragma unroll
                for (int j = 0; j < 4; j++) {
                    FMA2(acc2[i][j], a[i].x, w[j].x);
                    FMA2(acc2[i][j], a[i].y, w[j].y);
                }
        }
    }

#pragma unroll
    for (int i = 0; i < 4; i++) {
        int gr = m0 + ty + 16 * i;
        float p0 = pts[gr * 3 + 0], p1 = pts[gr * 3 + 1], p2 = pts[gr * 3 + 2];
#pragma unroll
        for (int j = 0; j < 4; j++) {
            int gc = n0 + tx + 16 * j;
            float2 f = upk(acc2[i][j]);
            float sp = p0 * sw[gc * 3 + 0] + p1 * sw[gc * 3 + 1] + p2 * sw[gc * 3 + 2] + sb[gc];
            C[(size_t)gr * 256 + gc] = (f.x + f.y) + bias[gc] + sp;
        }
    }
}

// =====================================================================
// Launch
// =====================================================================
extern "C" void kernel_launch(void* const* d_in, const int* in_sizes, int n_in,
                              void* d_out, int out_size)
{
    const float* cur_pts = (const float*)d_in[0];
    const float* cur_f   = (const float*)d_in[1];
    const float* nbr_pts = (const float*)d_in[2];
    const float* nbr_f   = (const float*)d_in[3];
    const float* in_w    = (const float*)d_in[4];
    const float* in_b    = (const float*)d_in[5];
    const float* out_w   = (const float*)d_in[6];
    const float* out_b   = (const float*)d_in[7];
    const float* sw      = (const float*)d_in[8];
    const float* sb      = (const float*)d_in[9];
    float* out = (float*)d_out;

    float *dq, *dk, *dv, *dce, *dan, *dat;
    cudaGetSymbolAddress((void**)&dq,  g_q);
    cudaGetSymbolAddress((void**)&dk,  g_k);
    cudaGetSymbolAddress((void**)&dv,  g_v);
    cudaGetSymbolAddress((void**)&dce, g_cur_edge);
    cudaGetSymbolAddress((void**)&dan, g_all_nbr);
    cudaGetSymbolAddress((void**)&dat, g_attn);

    int flash_smem = FLASH_SMEM_FLOATS * (int)sizeof(float);
    static int attr_set = 0;
    if (!attr_set) {
        cudaFuncSetAttribute(flash_mma_kernel,
                             cudaFuncAttributeMaxDynamicSharedMemorySize, flash_smem);
        attr_set = 1;
    }

    knn_topk_kernel<<<dim3(NQ / 128, NSETS), 128>>>(cur_pts, nbr_pts);
    edge_feats_kernel<<<NSETS * NQ, DD>>>(cur_f, nbr_f);

    gemm_proj_kernel<<<dim3((BB * NQ) / 64, 4), 256>>>(dce, in_w,           in_b,       dq, 1);
    gemm_proj_kernel<<<dim3((BB * LK) / 64, 4), 256>>>(dan, in_w + 256*256, in_b + 256, dk, 1);
    gemm_proj_kernel<<<dim3((BB * LK) / 64, 4), 256>>>(dan, in_w + 512*256, in_b + 512, dv, 1);

    flash_mma_kernel<<<dim3(NQ / 128, BB * HH), 256, flash_smem>>>(dq, dk, dv, dat);

    gemm_out_kernel<<<dim3((BB * NQ) / 64, 4), 256>>>(dat, out_w, out_b, cur_pts, sw, sb, out);
}

// round 6
// speedup vs baseline: 2.7290x; 1.1537x over previous
#include <cuda_runtime.h>
#include <math.h>
#include <stdint.h>

// Problem constants
#define BB   2
#define NQ   2048
#define DD   256
#define HH   8
#define DH   32
#define LK   4096      // M*NN
#define NNK  2048
#define KNN  8
#define NSETS 6

// ---------------- packed f32x2 helpers ----------------
#define FMA2(acc, a, b) asm("fma.rn.f32x2 %0, %1, %2, %0;" : "+l"(acc) : "l"(a), "l"(b))

static __device__ __forceinline__ float2 upk(unsigned long long u) {
    float2 r;
    asm("mov.b64 {%0, %1}, %2;" : "=f"(r.x), "=f"(r.y) : "l"(u));
    return r;
}
static __device__ __forceinline__ uint32_t f2tf32(float x) {
    uint32_t u;
    asm("cvt.rna.tf32.f32 %0, %1;" : "=r"(u) : "f"(x));
    return u;
}

// m16n8k8 tf32 mma: D += A*B  (A row-major 16x8, B col-major 8x8, fp32 accum)
static __device__ __forceinline__ void mma_tf32(float& d0, float& d1, float& d2, float& d3,
                                                uint32_t a0, uint32_t a1, uint32_t a2, uint32_t a3,
                                                uint32_t b0, uint32_t b1)
{
    asm volatile(
        "mma.sync.aligned.m16n8k8.row.col.f32.tf32.tf32.f32 "
        "{%0,%1,%2,%3}, {%4,%5,%6,%7}, {%8,%9}, {%0,%1,%2,%3};"
        : "+f"(d0), "+f"(d1), "+f"(d2), "+f"(d3)
        : "r"(a0), "r"(a1), "r"(a2), "r"(a3), "r"(b0), "r"(b1));
}

// ---------------- scratch ----------------
__device__ float g_cur_edge[BB * NQ * DD];
__device__ float g_all_nbr [BB * LK * DD];
__device__ float g_q   [BB * NQ * DD];
__device__ float g_k   [BB * LK * DD];
__device__ float g_v   [BB * LK * DD];
__device__ float g_attn[BB * NQ * DD];
__device__ int   g_idx [NSETS * NQ * KNN];

// =====================================================================
// Kernel 1: KNN top-8
// =====================================================================
__global__ void knn_topk_kernel(const float* __restrict__ cur_pts,
                                const float* __restrict__ nbr_pts)
{
    int set = blockIdx.y;
    const float* pts = (set < 2) ? (cur_pts + (size_t)set * NQ * 3)
                                 : (nbr_pts + (size_t)(set - 2) * NNK * 3);
    __shared__ float px[2048], py[2048], pz[2048], sq[2048];
    for (int i = threadIdx.x; i < 2048; i += blockDim.x) {
        float x = pts[i * 3 + 0], y = pts[i * 3 + 1], z = pts[i * 3 + 2];
        px[i] = x; py[i] = y; pz[i] = z;
        sq[i] = x * x + y * y + z * z;
    }
    __syncthreads();

    int row = blockIdx.x * blockDim.x + threadIdx.x;
    float bx = px[row], by = py[row], bz = pz[row], bsq = sq[row];

    float bestd[KNN];
    int   besti[KNN];
#pragma unroll
    for (int t = 0; t < KNN; t++) { bestd[t] = INFINITY; besti[t] = -1; }

    for (int j = 0; j < 2048; j++) {
        float dot = bx * px[j] + by * py[j] + bz * pz[j];
        float d2  = bsq + sq[j] - 2.0f * dot;
        if (d2 < bestd[KNN - 1]) {
            int t = KNN - 1;
#pragma unroll
            for (int u = KNN - 1; u > 0; u--) {
                if (bestd[u - 1] > d2) { bestd[u] = bestd[u - 1]; besti[u] = besti[u - 1]; t = u - 1; }
                else break;
            }
            bestd[t] = d2; besti[t] = j;
        }
    }

    int* out = g_idx + ((size_t)set * NQ + row) * KNN;
#pragma unroll
    for (int t = 0; t < KNN; t++) out[t] = besti[t];
}

// =====================================================================
// Kernel 2: edge features
// =====================================================================
__global__ void edge_feats_kernel(const float* __restrict__ cur_f,
                                  const float* __restrict__ nbr_f)
{
    int gid = blockIdx.x;
    int set = gid >> 11;
    int row = gid & 2047;

    const float* f;
    float* outp;
    if (set < 2) {
        f    = cur_f + (size_t)set * NQ * DD;
        outp = g_cur_edge + ((size_t)set * NQ + row) * DD;
    } else {
        int mb = set - 2;
        int m = mb >> 1, b = mb & 1;
        f    = nbr_f + (size_t)mb * NNK * DD;
        outp = g_all_nbr + ((size_t)b * LK + (size_t)m * NNK + row) * DD;
    }

    const int* idx = g_idx + ((size_t)set * NQ + row) * KNN;
    int d = threadIdx.x;

    float acc = 0.0f;
#pragma unroll
    for (int t = 0; t < KNN; t++)
        acc += f[(size_t)idx[t] * DD + d];

    outp[d] = f[(size_t)row * DD + d] - acc * 0.125f;
}

// =====================================================================
// Kernel 3: projection GEMM on tensor pipe (m16n8k8 tf32)
// C[R,256] = round_tf32( A[R,256] @ W[256,256]^T + bias )
// CTA tile 128x64, 8 warps (4m x 2n), warp tile 32x32
// k-chunk 32, double-buffered smem (stride 36 => conflict-free frag loads)
// operands rounded to tf32 at staging
// =====================================================================
#define PSTR 36
#define PROJ_SMEM_FLOATS (2 * 128 * PSTR + 2 * 64 * PSTR)
#define PSM_A(buf) ((buf) * (128 * PSTR))
#define PSM_W(buf) (2 * 128 * PSTR + (buf) * (64 * PSTR))

__global__ void __launch_bounds__(256, 2)
gemm_proj_mma(const float* __restrict__ A,
              const float* __restrict__ W,
              const float* __restrict__ bias,
              float* __restrict__ C)
{
    extern __shared__ float psm[];

    int tid = threadIdx.x;
    int wid = tid >> 5, lane = tid & 31;
    int g = lane >> 2, j = lane & 3;
    int wm = wid >> 1, wn = wid & 1;          // warp tile: rows wm*32, cols wn*32
    int m0 = blockIdx.x * 128;
    int n0 = blockIdx.y * 64;

    // staging maps
    int ar[4], ac[4];                          // A chunk: 128 rows x 32 cols
#pragma unroll
    for (int u = 0; u < 4; u++) {
        int fid = tid + 256 * u;
        ar[u] = fid >> 3;  ac[u] = (fid & 7) * 4;
    }
    int wr[2], wc[2];                          // W chunk: 64 rows x 32 cols
#pragma unroll
    for (int u = 0; u < 2; u++) {
        int fid = tid + 256 * u;
        wr[u] = fid >> 3;  wc[u] = (fid & 7) * 4;
    }

    const float* Ab = A + (size_t)m0 * 256;
    const float* Wb = W + (size_t)n0 * 256;

    float acc[2][4][4];
#pragma unroll
    for (int i = 0; i < 2; i++)
#pragma unroll
        for (int n = 0; n < 4; n++)
#pragma unroll
            for (int r = 0; r < 4; r++) acc[i][n][r] = 0.0f;

    // prefetch + stage k-chunk 0
    float4 apre[4], wpre[2];
#pragma unroll
    for (int u = 0; u < 4; u++) apre[u] = *(const float4*)&Ab[(size_t)ar[u] * 256 + ac[u]];
#pragma unroll
    for (int u = 0; u < 2; u++) wpre[u] = *(const float4*)&Wb[(size_t)wr[u] * 256 + wc[u]];
#pragma unroll
    for (int u = 0; u < 4; u++) {
        uint4 t;
        t.x = f2tf32(apre[u].x); t.y = f2tf32(apre[u].y);
        t.z = f2tf32(apre[u].z); t.w = f2tf32(apre[u].w);
        *(uint4*)&psm[PSM_A(0) + ar[u] * PSTR + ac[u]] = t;
    }
#pragma unroll
    for (int u = 0; u < 2; u++) {
        uint4 t;
        t.x = f2tf32(wpre[u].x); t.y = f2tf32(wpre[u].y);
        t.z = f2tf32(wpre[u].z); t.w = f2tf32(wpre[u].w);
        *(uint4*)&psm[PSM_W(0) + wr[u] * PSTR + wc[u]] = t;
    }

    for (int it = 0; it < 8; it++) {
        int s = it & 1;
        if (it < 7) {
            int ko = (it + 1) * 32;
#pragma unroll
            for (int u = 0; u < 4; u++) apre[u] = *(const float4*)&Ab[(size_t)ar[u] * 256 + ko + ac[u]];
#pragma unroll
            for (int u = 0; u < 2; u++) wpre[u] = *(const float4*)&Wb[(size_t)wr[u] * 256 + ko + wc[u]];
        }
        __syncthreads();   // stage s ready; all warps done reading 1-s
        if (it < 7) {
#pragma unroll
            for (int u = 0; u < 4; u++) {
                uint4 t;
                t.x = f2tf32(apre[u].x); t.y = f2tf32(apre[u].y);
                t.z = f2tf32(apre[u].z); t.w = f2tf32(apre[u].w);
                *(uint4*)&psm[PSM_A(1 - s) + ar[u] * PSTR + ac[u]] = t;
            }
#pragma unroll
            for (int u = 0; u < 2; u++) {
                uint4 t;
                t.x = f2tf32(wpre[u].x); t.y = f2tf32(wpre[u].y);
                t.z = f2tf32(wpre[u].z); t.w = f2tf32(wpre[u].w);
                *(uint4*)&psm[PSM_W(1 - s) + wr[u] * PSTR + wc[u]] = t;
            }
        }

        const uint32_t* As = (const uint32_t*)&psm[PSM_A(s)];
        const uint32_t* Ws = (const uint32_t*)&psm[PSM_W(s)];

#pragma unroll
        for (int kt = 0; kt < 4; kt++) {
            uint32_t af[2][4];
#pragma unroll
            for (int i = 0; i < 2; i++) {
                int rb = wm * 32 + i * 16;
                af[i][0] = As[(rb + g)     * PSTR + kt * 8 + j];
                af[i][1] = As[(rb + g + 8) * PSTR + kt * 8 + j];
                af[i][2] = As[(rb + g)     * PSTR + kt * 8 + j + 4];
                af[i][3] = As[(rb + g + 8) * PSTR + kt * 8 + j + 4];
            }
#pragma unroll
            for (int n = 0; n < 4; n++) {
                int nb = wn * 32 + n * 8;
                uint32_t b0 = Ws[(nb + g) * PSTR + kt * 8 + j];
                uint32_t b1 = Ws[(nb + g) * PSTR + kt * 8 + j + 4];
#pragma unroll
                for (int i = 0; i < 2; i++)
                    mma_tf32(acc[i][n][0], acc[i][n][1], acc[i][n][2], acc[i][n][3],
                             af[i][0], af[i][1], af[i][2], af[i][3], b0, b1);
            }
        }
    }

    // epilogue: add bias, round to tf32 (MMA consumers downstream), store
#pragma unroll
    for (int i = 0; i < 2; i++) {
        int r_lo = m0 + wm * 32 + i * 16 + g;
#pragma unroll
        for (int n = 0; n < 4; n++) {
            int col = n0 + wn * 32 + n * 8 + 2 * j;
            float b0 = bias[col], b1 = bias[col + 1];
            float2 lo, hi;
            lo.x = __uint_as_float(f2tf32(acc[i][n][0] + b0));
            lo.y = __uint_as_float(f2tf32(acc[i][n][1] + b1));
            hi.x = __uint_as_float(f2tf32(acc[i][n][2] + b0));
            hi.y = __uint_as_float(f2tf32(acc[i][n][3] + b1));
            *(float2*)&C[(size_t)r_lo * 256 + col]       = lo;
            *(float2*)&C[(size_t)(r_lo + 8) * 256 + col] = hi;
        }
    }
}

// =====================================================================
// Kernel 4: flash attention on tensor pipe (mma.sync m16n8k8 tf32)
// (unchanged from round 5 — validated)
// =====================================================================
#define KS_STR 36
#define VS_STR 40
#define SMEM_K_OFF(buf) ((buf) * (128 * KS_STR))
#define SMEM_V_OFF(buf) (2 * 128 * KS_STR + (buf) * (128 * VS_STR))
#define FLASH_SMEM_FLOATS (2 * 128 * KS_STR + 2 * 128 * VS_STR)

__global__ void __launch_bounds__(256, 2)
flash_mma_kernel(const float* __restrict__ Q, const float* __restrict__ K,
                 const float* __restrict__ V, float* __restrict__ O)
{
    extern __shared__ float sm[];

    const float SCALE = 0.17677669529663687f;   // 1/sqrt(32)
    int tid = threadIdx.x;
    int wid = tid >> 5, lane = tid & 31;
    int g = lane >> 2, j = lane & 3;
    int q0 = blockIdx.x * 128;
    int bh = blockIdx.y, b = bh >> 3, h = bh & 7;

    const float* qp = Q + ((size_t)b * NQ + q0 + wid * 16) * DD + h * DH;
    const float* kp = K + (size_t)b * LK * DD + h * DH;
    const float* vp = V + (size_t)b * LK * DD + h * DH;

    uint32_t aq[4][4];
#pragma unroll
    for (int kt = 0; kt < 4; kt++) {
        aq[kt][0] = __float_as_uint(qp[(size_t)g * DD + kt * 8 + j]);
        aq[kt][1] = __float_as_uint(qp[(size_t)(g + 8) * DD + kt * 8 + j]);
        aq[kt][2] = __float_as_uint(qp[(size_t)g * DD + kt * 8 + j + 4]);
        aq[kt][3] = __float_as_uint(qp[(size_t)(g + 8) * DD + kt * 8 + j + 4]);
    }

    float o[4][4];
#pragma unroll
    for (int n = 0; n < 4; n++)
#pragma unroll
        for (int r = 0; r < 4; r++) o[n][r] = 0.0f;
    float l0 = 0.0f, l1 = 0.0f;

    float4 kpre[4], vpre[4];
    int rr[4], cc[4];
#pragma unroll
    for (int u = 0; u < 4; u++) {
        int fid = tid + 256 * u;
        rr[u] = fid >> 3;
        cc[u] = (fid & 7) * 4;
        kpre[u] = *(const float4*)&kp[(size_t)rr[u] * DD + cc[u]];
        vpre[u] = *(const float4*)&vp[(size_t)rr[u] * DD + cc[u]];
    }
#pragma unroll
    for (int u = 0; u < 4; u++) {
        *(float4*)&sm[SMEM_K_OFF(0) + rr[u] * KS_STR + cc[u]] = kpre[u];
        *(float4*)&sm[SMEM_V_OFF(0) + rr[u] * VS_STR + cc[u]] = vpre[u];
    }

    for (int c = 0; c < 32; c++) {
        int buf = c & 1;
        if (c < 31) {
            int kb = (c + 1) * 128;
#pragma unroll
            for (int u = 0; u < 4; u++) {
                kpre[u] = *(const float4*)&kp[(size_t)(kb + rr[u]) * DD + cc[u]];
                vpre[u] = *(const float4*)&vp[(size_t)(kb + rr[u]) * DD + cc[u]];
            }
        }
        __syncthreads();

        const float* Ks = &sm[SMEM_K_OFF(buf)];
        const float* Vs = &sm[SMEM_V_OFF(buf)];

#pragma unroll
        for (int nh = 0; nh < 2; nh++) {
            float s[8][4];
#pragma unroll
            for (int nt = 0; nt < 8; nt++)
#pragma unroll
                for (int r = 0; r < 4; r++) s[nt][r] = 0.0f;

#pragma unroll
            for (int kt = 0; kt < 4; kt++) {
#pragma unroll
                for (int nt = 0; nt < 8; nt++) {
                    int kvrow = nh * 64 + nt * 8 + g;
                    uint32_t b0 = __float_as_uint(Ks[kvrow * KS_STR + kt * 8 + j]);
                    uint32_t b1 = __float_as_uint(Ks[kvrow * KS_STR + kt * 8 + j + 4]);
                    mma_tf32(s[nt][0], s[nt][1], s[nt][2], s[nt][3],
                             aq[kt][0], aq[kt][1], aq[kt][2], aq[kt][3], b0, b1);
                }
            }

#pragma unroll
            for (int nt = 0; nt < 8; nt++) {
                float p0 = __expf(s[nt][0] * SCALE);
                float p1 = __expf(s[nt][1] * SCALE);
                float p2 = __expf(s[nt][2] * SCALE);
                float p3 = __expf(s[nt][3] * SCALE);
                l0 += p0 + p1;
                l1 += p2 + p3;

                int src_lo = (lane & ~3) | (j >> 1);
                int src_hi = src_lo + 2;
                float x0l = __shfl_sync(0xffffffffu, p0, src_lo);
                float x1l = __shfl_sync(0xffffffffu, p1, src_lo);
                float x2l = __shfl_sync(0xffffffffu, p2, src_lo);
                float x3l = __shfl_sync(0xffffffffu, p3, src_lo);
                float x0h = __shfl_sync(0xffffffffu, p0, src_hi);
                float x1h = __shfl_sync(0xffffffffu, p1, src_hi);
                float x2h = __shfl_sync(0xffffffffu, p2, src_hi);
                float x3h = __shfl_sync(0xffffffffu, p3, src_hi);
                uint32_t pa0 = f2tf32((j & 1) ? x1l : x0l);
                uint32_t pa1 = f2tf32((j & 1) ? x3l : x2l);
                uint32_t pa2 = f2tf32((j & 1) ? x1h : x0h);
                uint32_t pa3 = f2tf32((j & 1) ? x3h : x2h);

                int t = nh * 8 + nt;
#pragma unroll
                for (int no = 0; no < 4; no++) {
                    uint32_t b0 = __float_as_uint(Vs[(t * 8 + j) * VS_STR + no * 8 + g]);
                    uint32_t b1 = __float_as_uint(Vs[(t * 8 + j + 4) * VS_STR + no * 8 + g]);
                    mma_tf32(o[no][0], o[no][1], o[no][2], o[no][3],
                             pa0, pa1, pa2, pa3, b0, b1);
                }
            }
        }

        if (c < 31) {
            int nb = 1 - buf;
#pragma unroll
            for (int u = 0; u < 4; u++) {
                *(float4*)&sm[SMEM_K_OFF(nb) + rr[u] * KS_STR + cc[u]] = kpre[u];
                *(float4*)&sm[SMEM_V_OFF(nb) + rr[u] * VS_STR + cc[u]] = vpre[u];
            }
        }
    }

    l0 += __shfl_xor_sync(0xffffffffu, l0, 1, 4);
    l0 += __shfl_xor_sync(0xffffffffu, l0, 2, 4);
    l1 += __shfl_xor_sync(0xffffffffu, l1, 1, 4);
    l1 += __shfl_xor_sync(0xffffffffu, l1, 2, 4);
    float inv0 = 1.0f / l0, inv1 = 1.0f / l1;

    float* op = O + ((size_t)b * NQ + q0 + wid * 16) * DD + h * DH;
#pragma unroll
    for (int no = 0; no < 4; no++) {
        int col = no * 8 + 2 * j;
        float2 lo = make_float2(o[no][0] * inv0, o[no][1] * inv0);
        float2 hi = make_float2(o[no][2] * inv1, o[no][3] * inv1);
        *(float2*)&op[(size_t)g * DD + col]       = lo;
        *(float2*)&op[(size_t)(g + 8) * DD + col] = hi;
    }
}

// =====================================================================
// Kernel 5: output projection + spatial, FFMA2, double-buffered
// (kept fp32 for final-output accuracy)
// =====================================================================
#define GSTR 36
__global__ void __launch_bounds__(256, 2)
gemm_out_kernel(const float* __restrict__ A,
                const float* __restrict__ W,
                const float* __restrict__ bias,
                const float* __restrict__ pts,
                const float* __restrict__ sw,
                const float* __restrict__ sb,
                float* __restrict__ C)
{
    __shared__ float As[2][64 * GSTR];
    __shared__ float Ws[2][64 * GSTR];

    int tid = threadIdx.x;
    int tx = tid & 15, ty = tid >> 4;
    int m0 = blockIdx.x * 64;
    int n0 = blockIdx.y * 64;
    int lrow = tid >> 2, lkq = (tid & 3) * 4;

    const float* Arow = A + (size_t)(m0 + lrow) * 256 + lkq;
    const float* Wrow = W + (size_t)(n0 + lrow) * 256 + lkq;

    unsigned long long acc2[4][4];
#pragma unroll
    for (int i = 0; i < 4; i++)
#pragma unroll
        for (int j = 0; j < 4; j++) acc2[i][j] = 0ULL;

    float4 av[2], wv[2];
#pragma unroll
    for (int u = 0; u < 2; u++) {
        av[u] = *(const float4*)&Arow[u * 16];
        wv[u] = *(const float4*)&Wrow[u * 16];
    }
#pragma unroll
    for (int u = 0; u < 2; u++) {
        *(float4*)&As[0][lrow * GSTR + lkq + u * 16] = av[u];
        *(float4*)&Ws[0][lrow * GSTR + lkq + u * 16] = wv[u];
    }

    for (int it = 0; it < 8; it++) {
        int s = it & 1;
        if (it < 7) {
            int ko = (it + 1) * 32;
#pragma unroll
            for (int u = 0; u < 2; u++) {
                av[u] = *(const float4*)&Arow[ko + u * 16];
                wv[u] = *(const float4*)&Wrow[ko + u * 16];
            }
        }
        __syncthreads();
        if (it < 7) {
#pragma unroll
            for (int u = 0; u < 2; u++) {
                *(float4*)&As[1 - s][lrow * GSTR + lkq + u * 16] = av[u];
                *(float4*)&Ws[1 - s][lrow * GSTR + lkq + u * 16] = wv[u];
            }
        }

        const float* as = As[s];
        const float* ws = Ws[s];
#pragma unroll
        for (int kk = 0; kk < 32; kk += 4) {
            ulonglong2 a[4], w[4];
#pragma unroll
            for (int i = 0; i < 4; i++) a[i] = *(const ulonglong2*)&as[(ty + 16 * i) * GSTR + kk];
#pragma unroll
            for (int j = 0; j < 4; j++) w[j] = *(const ulonglong2*)&ws[(tx + 16 * j) * GSTR + kk];
#pragma unroll
            for (int i = 0; i < 4; i++)
#pragma unroll
                for (int j = 0; j < 4; j++) {
                    FMA2(acc2[i][j], a[i].x, w[j].x);
                    FMA2(acc2[i][j], a[i].y, w[j].y);
                }
        }
    }

#pragma unroll
    for (int i = 0; i < 4; i++) {
        int gr = m0 + ty + 16 * i;
        float p0 = pts[gr * 3 + 0], p1 = pts[gr * 3 + 1], p2 = pts[gr * 3 + 2];
#pragma unroll
        for (int j = 0; j < 4; j++) {
            int gc = n0 + tx + 16 * j;
            float2 f = upk(acc2[i][j]);
            float sp = p0 * sw[gc * 3 + 0] + p1 * sw[gc * 3 + 1] + p2 * sw[gc * 3 + 2] + sb[gc];
            C[(size_t)gr * 256 + gc] = (f.x + f.y) + bias[gc] + sp;
        }
    }
}

// =====================================================================
// Launch
// =====================================================================
extern "C" void kernel_launch(void* const* d_in, const int* in_sizes, int n_in,
                              void* d_out, int out_size)
{
    const float* cur_pts = (const float*)d_in[0];
    const float* cur_f   = (const float*)d_in[1];
    const float* nbr_pts = (const float*)d_in[2];
    const float* nbr_f   = (const float*)d_in[3];
    const float* in_w    = (const float*)d_in[4];
    const float* in_b    = (const float*)d_in[5];
    const float* out_w   = (const float*)d_in[6];
    const float* out_b   = (const float*)d_in[7];
    const float* sw      = (const float*)d_in[8];
    const float* sb      = (const float*)d_in[9];
    float* out = (float*)d_out;

    float *dq, *dk, *dv, *dce, *dan, *dat;
    cudaGetSymbolAddress((void**)&dq,  g_q);
    cudaGetSymbolAddress((void**)&dk,  g_k);
    cudaGetSymbolAddress((void**)&dv,  g_v);
    cudaGetSymbolAddress((void**)&dce, g_cur_edge);
    cudaGetSymbolAddress((void**)&dan, g_all_nbr);
    cudaGetSymbolAddress((void**)&dat, g_attn);

    int flash_smem = FLASH_SMEM_FLOATS * (int)sizeof(float);
    int proj_smem  = PROJ_SMEM_FLOATS * (int)sizeof(float);
    static int attr_set = 0;
    if (!attr_set) {
        cudaFuncSetAttribute(flash_mma_kernel,
                             cudaFuncAttributeMaxDynamicSharedMemorySize, flash_smem);
        cudaFuncSetAttribute(gemm_proj_mma,
                             cudaFuncAttributeMaxDynamicSharedMemorySize, proj_smem);
        attr_set = 1;
    }

    knn_topk_kernel<<<dim3(NQ / 128, NSETS), 128>>>(cur_pts, nbr_pts);
    edge_feats_kernel<<<NSETS * NQ, DD>>>(cur_f, nbr_f);

    gemm_proj_mma<<<dim3((BB * NQ) / 128, 4), 256, proj_smem>>>(dce, in_w,           in_b,       dq);
    gemm_proj_mma<<<dim3((BB * LK) / 128, 4), 256, proj_smem>>>(dan, in_w + 256*256, in_b + 256, dk);
    gemm_proj_mma<<<dim3((BB * LK) / 128, 4), 256, proj_smem>>>(dan, in_w + 512*256, in_b + 512, dv);

    flash_mma_kernel<<<dim3(NQ / 128, BB * HH), 256, flash_smem>>>(dq, dk, dv, dat);

    gemm_out_kernel<<<dim3((BB * NQ) / 64, 4), 256>>>(dat, out_w, out_b, cur_pts, sw, sb, out);
}

// round 7
// speedup vs baseline: 3.2208x; 1.1802x over previous
#include <cuda_runtime.h>
#include <math.h>
#include <stdint.h>

// Problem constants
#define BB   2
#define NQ   2048
#define DD   256
#define HH   8
#define DH   32
#define LK   4096      // M*NN
#define NNK  2048
#define KNN  8
#define NSETS 6

static __device__ __forceinline__ uint32_t f2tf32(float x) {
    uint32_t u;
    asm("cvt.rna.tf32.f32 %0, %1;" : "=r"(u) : "f"(x));
    return u;
}
// pack {lo, hi} floats into bf16x2 (lo -> bits[0:16])
static __device__ __forceinline__ uint32_t pk_bf16x2(float lo, float hi) {
    uint32_t d;
    asm("cvt.rn.bf16x2.f32 %0, %1, %2;" : "=r"(d) : "f"(hi), "f"(lo));
    return d;
}

// m16n8k8 tf32 mma
static __device__ __forceinline__ void mma_tf32(float& d0, float& d1, float& d2, float& d3,
                                                uint32_t a0, uint32_t a1, uint32_t a2, uint32_t a3,
                                                uint32_t b0, uint32_t b1)
{
    asm volatile(
        "mma.sync.aligned.m16n8k8.row.col.f32.tf32.tf32.f32 "
        "{%0,%1,%2,%3}, {%4,%5,%6,%7}, {%8,%9}, {%0,%1,%2,%3};"
        : "+f"(d0), "+f"(d1), "+f"(d2), "+f"(d3)
        : "r"(a0), "r"(a1), "r"(a2), "r"(a3), "r"(b0), "r"(b1));
}

// m16n8k16 bf16 mma
static __device__ __forceinline__ void mma_bf16(float& d0, float& d1, float& d2, float& d3,
                                                uint32_t a0, uint32_t a1, uint32_t a2, uint32_t a3,
                                                uint32_t b0, uint32_t b1)
{
    asm volatile(
        "mma.sync.aligned.m16n8k16.row.col.f32.bf16.bf16.f32 "
        "{%0,%1,%2,%3}, {%4,%5,%6,%7}, {%8,%9}, {%0,%1,%2,%3};"
        : "+f"(d0), "+f"(d1), "+f"(d2), "+f"(d3)
        : "r"(a0), "r"(a1), "r"(a2), "r"(a3), "r"(b0), "r"(b1));
}

// ---------------- scratch ----------------
__device__ float g_cur_edge[BB * NQ * DD];
__device__ float g_all_nbr [BB * LK * DD];
__device__ float g_q   [BB * NQ * DD];
__device__ float g_k   [BB * LK * DD];
__device__ float g_v   [BB * LK * DD];
__device__ float g_attn[BB * NQ * DD];
__device__ int   g_idx [NSETS * NQ * KNN];

// =====================================================================
// Kernel 1: KNN top-8
// =====================================================================
__global__ void knn_topk_kernel(const float* __restrict__ cur_pts,
                                const float* __restrict__ nbr_pts)
{
    int set = blockIdx.y;
    const float* pts = (set < 2) ? (cur_pts + (size_t)set * NQ * 3)
                                 : (nbr_pts + (size_t)(set - 2) * NNK * 3);
    __shared__ float px[2048], py[2048], pz[2048], sq[2048];
    for (int i = threadIdx.x; i < 2048; i += blockDim.x) {
        float x = pts[i * 3 + 0], y = pts[i * 3 + 1], z = pts[i * 3 + 2];
        px[i] = x; py[i] = y; pz[i] = z;
        sq[i] = x * x + y * y + z * z;
    }
    __syncthreads();

    int row = blockIdx.x * blockDim.x + threadIdx.x;
    float bx = px[row], by = py[row], bz = pz[row], bsq = sq[row];

    float bestd[KNN];
    int   besti[KNN];
#pragma unroll
    for (int t = 0; t < KNN; t++) { bestd[t] = INFINITY; besti[t] = -1; }

    for (int j = 0; j < 2048; j++) {
        float dot = bx * px[j] + by * py[j] + bz * pz[j];
        float d2  = bsq + sq[j] - 2.0f * dot;
        if (d2 < bestd[KNN - 1]) {
            int t = KNN - 1;
#pragma unroll
            for (int u = KNN - 1; u > 0; u--) {
                if (bestd[u - 1] > d2) { bestd[u] = bestd[u - 1]; besti[u] = besti[u - 1]; t = u - 1; }
                else break;
            }
            bestd[t] = d2; besti[t] = j;
        }
    }

    int* out = g_idx + ((size_t)set * NQ + row) * KNN;
#pragma unroll
    for (int t = 0; t < KNN; t++) out[t] = besti[t];
}

// =====================================================================
// Kernel 2: edge features
// =====================================================================
__global__ void edge_feats_kernel(const float* __restrict__ cur_f,
                                  const float* __restrict__ nbr_f)
{
    int gid = blockIdx.x;
    int set = gid >> 11;
    int row = gid & 2047;

    const float* f;
    float* outp;
    if (set < 2) {
        f    = cur_f + (size_t)set * NQ * DD;
        outp = g_cur_edge + ((size_t)set * NQ + row) * DD;
    } else {
        int mb = set - 2;
        int m = mb >> 1, b = mb & 1;
        f    = nbr_f + (size_t)mb * NNK * DD;
        outp = g_all_nbr + ((size_t)b * LK + (size_t)m * NNK + row) * DD;
    }

    const int* idx = g_idx + ((size_t)set * NQ + row) * KNN;
    int d = threadIdx.x;

    float acc = 0.0f;
#pragma unroll
    for (int t = 0; t < KNN; t++)
        acc += f[(size_t)idx[t] * DD + d];

    outp[d] = f[(size_t)row * DD + d] - acc * 0.125f;
}

// =====================================================================
// Kernel 3: projection GEMM on tensor pipe (m16n8k8 tf32)
// CTA tile 128x64, 8 warps (4m x 2n), k-chunk 32, double-buffered
// spatial != 0 => fused spatial-embedding epilogue (final output kernel)
// round_out != 0 => tf32-round outputs (operands of downstream MMAs)
// =====================================================================
#define PSTR 36
#define PROJ_SMEM_FLOATS (2 * 128 * PSTR + 2 * 64 * PSTR)
#define PSM_A(buf) ((buf) * (128 * PSTR))
#define PSM_W(buf) (2 * 128 * PSTR + (buf) * (64 * PSTR))

__global__ void __launch_bounds__(256, 2)
gemm_proj_mma(const float* __restrict__ A,
              const float* __restrict__ W,
              const float* __restrict__ bias,
              float* __restrict__ C,
              int round_out,
              const float* __restrict__ pts,   // may be null
              const float* __restrict__ sw,
              const float* __restrict__ sb)
{
    extern __shared__ float psm[];

    int tid = threadIdx.x;
    int wid = tid >> 5, lane = tid & 31;
    int g = lane >> 2, j = lane & 3;
    int wm = wid >> 1, wn = wid & 1;
    int m0 = blockIdx.x * 128;
    int n0 = blockIdx.y * 64;

    int ar[4], ac[4];
#pragma unroll
    for (int u = 0; u < 4; u++) {
        int fid = tid + 256 * u;
        ar[u] = fid >> 3;  ac[u] = (fid & 7) * 4;
    }
    int wr[2], wc[2];
#pragma unroll
    for (int u = 0; u < 2; u++) {
        int fid = tid + 256 * u;
        wr[u] = fid >> 3;  wc[u] = (fid & 7) * 4;
    }

    const float* Ab = A + (size_t)m0 * 256;
    const float* Wb = W + (size_t)n0 * 256;

    float acc[2][4][4];
#pragma unroll
    for (int i = 0; i < 2; i++)
#pragma unroll
        for (int n = 0; n < 4; n++)
#pragma unroll
            for (int r = 0; r < 4; r++) acc[i][n][r] = 0.0f;

    float4 apre[4], wpre[2];
#pragma unroll
    for (int u = 0; u < 4; u++) apre[u] = *(const float4*)&Ab[(size_t)ar[u] * 256 + ac[u]];
#pragma unroll
    for (int u = 0; u < 2; u++) wpre[u] = *(const float4*)&Wb[(size_t)wr[u] * 256 + wc[u]];
#pragma unroll
    for (int u = 0; u < 4; u++) {
        uint4 t;
        t.x = f2tf32(apre[u].x); t.y = f2tf32(apre[u].y);
        t.z = f2tf32(apre[u].z); t.w = f2tf32(apre[u].w);
        *(uint4*)&psm[PSM_A(0) + ar[u] * PSTR + ac[u]] = t;
    }
#pragma unroll
    for (int u = 0; u < 2; u++) {
        uint4 t;
        t.x = f2tf32(wpre[u].x); t.y = f2tf32(wpre[u].y);
        t.z = f2tf32(wpre[u].z); t.w = f2tf32(wpre[u].w);
        *(uint4*)&psm[PSM_W(0) + wr[u] * PSTR + wc[u]] = t;
    }

    for (int it = 0; it < 8; it++) {
        int s = it & 1;
        if (it < 7) {
            int ko = (it + 1) * 32;
#pragma unroll
            for (int u = 0; u < 4; u++) apre[u] = *(const float4*)&Ab[(size_t)ar[u] * 256 + ko + ac[u]];
#pragma unroll
            for (int u = 0; u < 2; u++) wpre[u] = *(const float4*)&Wb[(size_t)wr[u] * 256 + ko + wc[u]];
        }
        __syncthreads();
        if (it < 7) {
#pragma unroll
            for (int u = 0; u < 4; u++) {
                uint4 t;
                t.x = f2tf32(apre[u].x); t.y = f2tf32(apre[u].y);
                t.z = f2tf32(apre[u].z); t.w = f2tf32(apre[u].w);
                *(uint4*)&psm[PSM_A(1 - s) + ar[u] * PSTR + ac[u]] = t;
            }
#pragma unroll
            for (int u = 0; u < 2; u++) {
                uint4 t;
                t.x = f2tf32(wpre[u].x); t.y = f2tf32(wpre[u].y);
                t.z = f2tf32(wpre[u].z); t.w = f2tf32(wpre[u].w);
                *(uint4*)&psm[PSM_W(1 - s) + wr[u] * PSTR + wc[u]] = t;
            }
        }

        const uint32_t* As = (const uint32_t*)&psm[PSM_A(s)];
        const uint32_t* Ws = (const uint32_t*)&psm[PSM_W(s)];

#pragma unroll
        for (int kt = 0; kt < 4; kt++) {
            uint32_t af[2][4];
#pragma unroll
            for (int i = 0; i < 2; i++) {
                int rb = wm * 32 + i * 16;
                af[i][0] = As[(rb + g)     * PSTR + kt * 8 + j];
                af[i][1] = As[(rb + g + 8) * PSTR + kt * 8 + j];
                af[i][2] = As[(rb + g)     * PSTR + kt * 8 + j + 4];
                af[i][3] = As[(rb + g + 8) * PSTR + kt * 8 + j + 4];
            }
#pragma unroll
            for (int n = 0; n < 4; n++) {
                int nb = wn * 32 + n * 8;
                uint32_t b0 = Ws[(nb + g) * PSTR + kt * 8 + j];
                uint32_t b1 = Ws[(nb + g) * PSTR + kt * 8 + j + 4];
#pragma unroll
                for (int i = 0; i < 2; i++)
                    mma_tf32(acc[i][n][0], acc[i][n][1], acc[i][n][2], acc[i][n][3],
                             af[i][0], af[i][1], af[i][2], af[i][3], b0, b1);
            }
        }
    }

#pragma unroll
    for (int i = 0; i < 2; i++) {
        int r_lo = m0 + wm * 32 + i * 16 + g;
        float p0a = 0.f, p1a = 0.f, p2a = 0.f, p0b = 0.f, p1b = 0.f, p2b = 0.f;
        if (pts) {
            p0a = pts[r_lo * 3 + 0]; p1a = pts[r_lo * 3 + 1]; p2a = pts[r_lo * 3 + 2];
            p0b = pts[(r_lo + 8) * 3 + 0]; p1b = pts[(r_lo + 8) * 3 + 1]; p2b = pts[(r_lo + 8) * 3 + 2];
        }
#pragma unroll
        for (int n = 0; n < 4; n++) {
            int col = n0 + wn * 32 + n * 8 + 2 * j;
            float b0 = bias[col], b1 = bias[col + 1];
            float v00 = acc[i][n][0] + b0, v01 = acc[i][n][1] + b1;
            float v10 = acc[i][n][2] + b0, v11 = acc[i][n][3] + b1;
            if (pts) {
                float s0 = sw[col * 3], s1 = sw[col * 3 + 1], s2 = sw[col * 3 + 2];
                float t0 = sw[(col+1) * 3], t1 = sw[(col+1) * 3 + 1], t2 = sw[(col+1) * 3 + 2];
                v00 += p0a * s0 + p1a * s1 + p2a * s2 + sb[col];
                v01 += p0a * t0 + p1a * t1 + p2a * t2 + sb[col + 1];
                v10 += p0b * s0 + p1b * s1 + p2b * s2 + sb[col];
                v11 += p0b * t0 + p1b * t1 + p2b * t2 + sb[col + 1];
            }
            if (round_out) {
                v00 = __uint_as_float(f2tf32(v00)); v01 = __uint_as_float(f2tf32(v01));
                v10 = __uint_as_float(f2tf32(v10)); v11 = __uint_as_float(f2tf32(v11));
            }
            *(float2*)&C[(size_t)r_lo * 256 + col]       = make_float2(v00, v01);
            *(float2*)&C[(size_t)(r_lo + 8) * 256 + col] = make_float2(v10, v11);
        }
    }
}

// =====================================================================
// Kernel 4: flash attention, tf32 QK^T + bf16 P*V (FA2 fragment trick)
// 128 q/CTA, 8 warps x 16 q-rows; kv chunk 128, double-buffered.
// V staged as bf16 kv-pair-packed u32 [kvpair][dh], stride 40.
// =====================================================================
#define KS_STR 36
#define VS32   40
#define SMEM_K_OFF(buf) ((buf) * (128 * KS_STR))
#define SMEM_V_OFF(buf) (2 * 128 * KS_STR + (buf) * (64 * VS32))
#define FLASH_SMEM_FLOATS (2 * 128 * KS_STR + 2 * 64 * VS32)

__global__ void __launch_bounds__(256, 2)
flash_mma_kernel(const float* __restrict__ Q, const float* __restrict__ K,
                 const float* __restrict__ V, float* __restrict__ O)
{
    extern __shared__ float sm[];

    const float SCALE = 0.17677669529663687f;   // 1/sqrt(32)
    int tid = threadIdx.x;
    int wid = tid >> 5, lane = tid & 31;
    int g = lane >> 2, j = lane & 3;
    int q0 = blockIdx.x * 128;
    int bh = blockIdx.y, b = bh >> 3, h = bh & 7;

    const float* qp = Q + ((size_t)b * NQ + q0 + wid * 16) * DD + h * DH;
    const float* kp = K + (size_t)b * LK * DD + h * DH;
    const float* vp = V + (size_t)b * LK * DD + h * DH;

    // Q fragments (tf32 already rounded upstream)
    uint32_t aq[4][4];
#pragma unroll
    for (int kt = 0; kt < 4; kt++) {
        aq[kt][0] = __float_as_uint(qp[(size_t)g * DD + kt * 8 + j]);
        aq[kt][1] = __float_as_uint(qp[(size_t)(g + 8) * DD + kt * 8 + j]);
        aq[kt][2] = __float_as_uint(qp[(size_t)g * DD + kt * 8 + j + 4]);
        aq[kt][3] = __float_as_uint(qp[(size_t)(g + 8) * DD + kt * 8 + j + 4]);
    }

    float o[4][4];
#pragma unroll
    for (int n = 0; n < 4; n++)
#pragma unroll
        for (int r = 0; r < 4; r++) o[n][r] = 0.0f;
    float l0 = 0.0f, l1 = 0.0f;

    // staging maps: K 4 x float4 per thread; V 2 x (even,odd) float4 pairs
    int kr[4], kc[4];
#pragma unroll
    for (int u = 0; u < 4; u++) {
        int fid = tid + 256 * u;
        kr[u] = fid >> 3;  kc[u] = (fid & 7) * 4;
    }
    int vpair[2], vcg[2];
#pragma unroll
    for (int u = 0; u < 2; u++) {
        int fid = tid + 256 * u;
        vpair[u] = fid >> 3;       // 0..63
        vcg[u]   = (fid & 7) * 4;  // dh base 0..28
    }

    float4 kpre[4], vea[2], voa[2];
#pragma unroll
    for (int u = 0; u < 4; u++)
        kpre[u] = *(const float4*)&kp[(size_t)kr[u] * DD + kc[u]];
#pragma unroll
    for (int u = 0; u < 2; u++) {
        vea[u] = *(const float4*)&vp[(size_t)(2 * vpair[u])     * DD + vcg[u]];
        voa[u] = *(const float4*)&vp[(size_t)(2 * vpair[u] + 1) * DD + vcg[u]];
    }
    // stage chunk 0
#pragma unroll
    for (int u = 0; u < 4; u++)
        *(float4*)&sm[SMEM_K_OFF(0) + kr[u] * KS_STR + kc[u]] = kpre[u];
#pragma unroll
    for (int u = 0; u < 2; u++) {
        uint4 w;
        w.x = pk_bf16x2(vea[u].x, voa[u].x);
        w.y = pk_bf16x2(vea[u].y, voa[u].y);
        w.z = pk_bf16x2(vea[u].z, voa[u].z);
        w.w = pk_bf16x2(vea[u].w, voa[u].w);
        *(uint4*)&((uint32_t*)sm)[SMEM_V_OFF(0) + vpair[u] * VS32 + vcg[u]] = w;
    }

    for (int c = 0; c < 32; c++) {
        int buf = c & 1;
        if (c < 31) {
            int kb = (c + 1) * 128;
#pragma unroll
            for (int u = 0; u < 4; u++)
                kpre[u] = *(const float4*)&kp[(size_t)(kb + kr[u]) * DD + kc[u]];
#pragma unroll
            for (int u = 0; u < 2; u++) {
                vea[u] = *(const float4*)&vp[(size_t)(kb + 2 * vpair[u])     * DD + vcg[u]];
                voa[u] = *(const float4*)&vp[(size_t)(kb + 2 * vpair[u] + 1) * DD + vcg[u]];
            }
        }
        __syncthreads();

        const float* Ks = &sm[SMEM_K_OFF(buf)];
        const uint32_t* Vs = &((const uint32_t*)sm)[SMEM_V_OFF(buf)];

#pragma unroll
        for (int nh = 0; nh < 2; nh++) {
            // ---- S = Q K^T (tf32) for 8 n-tiles (64 kv) ----
            float s[8][4];
#pragma unroll
            for (int nt = 0; nt < 8; nt++)
#pragma unroll
                for (int r = 0; r < 4; r++) s[nt][r] = 0.0f;

#pragma unroll
            for (int kt = 0; kt < 4; kt++) {
#pragma unroll
                for (int nt = 0; nt < 8; nt++) {
                    int kvrow = nh * 64 + nt * 8 + g;
                    uint32_t b0 = __float_as_uint(Ks[kvrow * KS_STR + kt * 8 + j]);
                    uint32_t b1 = __float_as_uint(Ks[kvrow * KS_STR + kt * 8 + j + 4]);
                    mma_tf32(s[nt][0], s[nt][1], s[nt][2], s[nt][3],
                             aq[kt][0], aq[kt][1], aq[kt][2], aq[kt][3], b0, b1);
                }
            }

            // ---- exp + pack to bf16 A-frags + P*V (k16) ----
#pragma unroll
            for (int t = 0; t < 4; t++) {          // k16 tile within half
                float pe0 = __expf(s[2*t][0] * SCALE);
                float pe1 = __expf(s[2*t][1] * SCALE);
                float pe2 = __expf(s[2*t][2] * SCALE);
                float pe3 = __expf(s[2*t][3] * SCALE);
                float po0 = __expf(s[2*t+1][0] * SCALE);
                float po1 = __expf(s[2*t+1][1] * SCALE);
                float po2 = __expf(s[2*t+1][2] * SCALE);
                float po3 = __expf(s[2*t+1][3] * SCALE);
                l0 += (pe0 + pe1) + (po0 + po1);
                l1 += (pe2 + pe3) + (po2 + po3);

                uint32_t a0 = pk_bf16x2(pe0, pe1);  // row g,   A cols 2j,2j+1
                uint32_t a1 = pk_bf16x2(pe2, pe3);  // row g+8
                uint32_t a2 = pk_bf16x2(po0, po1);  // row g,   A cols 2j+8,2j+9
                uint32_t a3 = pk_bf16x2(po2, po3);  // row g+8

                int pairbase = (nh * 4 + t) * 8;    // kv pairs of this k16 tile
#pragma unroll
                for (int no = 0; no < 4; no++) {
                    uint32_t b0 = Vs[(pairbase + j)     * VS32 + no * 8 + g];
                    uint32_t b1 = Vs[(pairbase + j + 4) * VS32 + no * 8 + g];
                    mma_bf16(o[no][0], o[no][1], o[no][2], o[no][3],
                             a0, a1, a2, a3, b0, b1);
                }
            }
        }

        if (c < 31) {
            int nb = 1 - buf;
#pragma unroll
            for (int u = 0; u < 4; u++)
                *(float4*)&sm[SMEM_K_OFF(nb) + kr[u] * KS_STR + kc[u]] = kpre[u];
#pragma unroll
            for (int u = 0; u < 2; u++) {
                uint4 w;
                w.x = pk_bf16x2(vea[u].x, voa[u].x);
                w.y = pk_bf16x2(vea[u].y, voa[u].y);
                w.z = pk_bf16x2(vea[u].z, voa[u].z);
                w.w = pk_bf16x2(vea[u].w, voa[u].w);
                *(uint4*)&((uint32_t*)sm)[SMEM_V_OFF(nb) + vpair[u] * VS32 + vcg[u]] = w;
            }
        }
    }

    l0 += __shfl_xor_sync(0xffffffffu, l0, 1, 4);
    l0 += __shfl_xor_sync(0xffffffffu, l0, 2, 4);
    l1 += __shfl_xor_sync(0xffffffffu, l1, 1, 4);
    l1 += __shfl_xor_sync(0xffffffffu, l1, 2, 4);
    float inv0 = 1.0f / l0, inv1 = 1.0f / l1;

    float* op = O + ((size_t)b * NQ + q0 + wid * 16) * DD + h * DH;
#pragma unroll
    for (int no = 0; no < 4; no++) {
        int col = no * 8 + 2 * j;
        float2 lo = make_float2(o[no][0] * inv0, o[no][1] * inv0);
        float2 hi = make_float2(o[no][2] * inv1, o[no][3] * inv1);
        *(float2*)&op[(size_t)g * DD + col]       = lo;
        *(float2*)&op[(size_t)(g + 8) * DD + col] = hi;
    }
}

// =====================================================================
// Launch
// =====================================================================
extern "C" void kernel_launch(void* const* d_in, const int* in_sizes, int n_in,
                              void* d_out, int out_size)
{
    const float* cur_pts = (const float*)d_in[0];
    const float* cur_f   = (const float*)d_in[1];
    const float* nbr_pts = (const float*)d_in[2];
    const float* nbr_f   = (const float*)d_in[3];
    const float* in_w    = (const float*)d_in[4];
    const float* in_b    = (const float*)d_in[5];
    const float* out_w   = (const float*)d_in[6];
    const float* out_b   = (const float*)d_in[7];
    const float* sw      = (const float*)d_in[8];
    const float* sb      = (const float*)d_in[9];
    float* out = (float*)d_out;

    float *dq, *dk, *dv, *dce, *dan, *dat;
    cudaGetSymbolAddress((void**)&dq,  g_q);
    cudaGetSymbolAddress((void**)&dk,  g_k);
    cudaGetSymbolAddress((void**)&dv,  g_v);
    cudaGetSymbolAddress((void**)&dce, g_cur_edge);
    cudaGetSymbolAddress((void**)&dan, g_all_nbr);
    cudaGetSymbolAddress((void**)&dat, g_attn);

    int flash_smem = FLASH_SMEM_FLOATS * (int)sizeof(float);
    int proj_smem  = PROJ_SMEM_FLOATS * (int)sizeof(float);
    static int attr_set = 0;
    if (!attr_set) {
        cudaFuncSetAttribute(flash_mma_kernel,
                             cudaFuncAttributeMaxDynamicSharedMemorySize, flash_smem);
        cudaFuncSetAttribute(gemm_proj_mma,
                             cudaFuncAttributeMaxDynamicSharedMemorySize, proj_smem);
        attr_set = 1;
    }

    knn_topk_kernel<<<dim3(NQ / 128, NSETS), 128>>>(cur_pts, nbr_pts);
    edge_feats_kernel<<<NSETS * NQ, DD>>>(cur_f, nbr_f);

    gemm_proj_mma<<<dim3((BB * NQ) / 128, 4), 256, proj_smem>>>(
        dce, in_w,           in_b,       dq, 1, nullptr, nullptr, nullptr);
    gemm_proj_mma<<<dim3((BB * LK) / 128, 4), 256, proj_smem>>>(
        dan, in_w + 256*256, in_b + 256, dk, 1, nullptr, nullptr, nullptr);
    gemm_proj_mma<<<dim3((BB * LK) / 128, 4), 256, proj_smem>>>(
        dan, in_w + 512*256, in_b + 512, dv, 0, nullptr, nullptr, nullptr);

    flash_mma_kernel<<<dim3(NQ / 128, BB * HH), 256, flash_smem>>>(dq, dk, dv, dat);

    // output projection + fused spatial epilogue (fp32 epilogue, tf32 GEMM)
    gemm_proj_mma<<<dim3((BB * NQ) / 128, 4), 256, proj_smem>>>(
        dat, out_w, out_b, out, 0, cur_pts, sw, sb);
}

// round 8
// speedup vs baseline: 3.5682x; 1.1079x over previous
#include <cuda_runtime.h>
#include <math.h>
#include <stdint.h>

// Problem constants
#define BB   2
#define NQ   2048
#define DD   256
#define HH   8
#define DH   32
#define LK   4096      // M*NN
#define NNK  2048
#define KNN  8
#define NSETS 6

static __device__ __forceinline__ uint32_t f2tf32(float x) {
    uint32_t u;
    asm("cvt.rna.tf32.f32 %0, %1;" : "=r"(u) : "f"(x));
    return u;
}
// pack {lo, hi} floats into bf16x2 (lo -> bits[0:16])
static __device__ __forceinline__ uint32_t pk_bf16x2(float lo, float hi) {
    uint32_t d;
    asm("cvt.rn.bf16x2.f32 %0, %1, %2;" : "=r"(d) : "f"(hi), "f"(lo));
    return d;
}
static __device__ __forceinline__ uint32_t prmt(uint32_t a, uint32_t b, uint32_t s) {
    uint32_t d;
    asm("prmt.b32 %0, %1, %2, %3;" : "=r"(d) : "r"(a), "r"(b), "r"(s));
    return d;
}

// m16n8k8 tf32 mma (projection kernels)
static __device__ __forceinline__ void mma_tf32(float& d0, float& d1, float& d2, float& d3,
                                                uint32_t a0, uint32_t a1, uint32_t a2, uint32_t a3,
                                                uint32_t b0, uint32_t b1)
{
    asm volatile(
        "mma.sync.aligned.m16n8k8.row.col.f32.tf32.tf32.f32 "
        "{%0,%1,%2,%3}, {%4,%5,%6,%7}, {%8,%9}, {%0,%1,%2,%3};"
        : "+f"(d0), "+f"(d1), "+f"(d2), "+f"(d3)
        : "r"(a0), "r"(a1), "r"(a2), "r"(a3), "r"(b0), "r"(b1));
}

// m16n8k16 bf16 mma
static __device__ __forceinline__ void mma_bf16(float& d0, float& d1, float& d2, float& d3,
                                                uint32_t a0, uint32_t a1, uint32_t a2, uint32_t a3,
                                                uint32_t b0, uint32_t b1)
{
    asm volatile(
        "mma.sync.aligned.m16n8k16.row.col.f32.bf16.bf16.f32 "
        "{%0,%1,%2,%3}, {%4,%5,%6,%7}, {%8,%9}, {%0,%1,%2,%3};"
        : "+f"(d0), "+f"(d1), "+f"(d2), "+f"(d3)
        : "r"(a0), "r"(a1), "r"(a2), "r"(a3), "r"(b0), "r"(b1));
}

// ---------------- scratch ----------------
__device__ float    g_cur_edge[BB * NQ * DD];
__device__ float    g_all_nbr [BB * LK * DD];
__device__ uint32_t g_q   [BB * NQ * DD / 2];    // bf16x2 packed
__device__ uint32_t g_k   [BB * LK * DD / 2];
__device__ uint32_t g_v   [BB * LK * DD / 2];
__device__ float    g_attn[BB * NQ * DD];
__device__ int      g_idx [NSETS * NQ * KNN];

// =====================================================================
// Kernel 1: KNN top-8
// =====================================================================
__global__ void knn_topk_kernel(const float* __restrict__ cur_pts,
                                const float* __restrict__ nbr_pts)
{
    int set = blockIdx.y;
    const float* pts = (set < 2) ? (cur_pts + (size_t)set * NQ * 3)
                                 : (nbr_pts + (size_t)(set - 2) * NNK * 3);
    __shared__ float px[2048], py[2048], pz[2048], sq[2048];
    for (int i = threadIdx.x; i < 2048; i += blockDim.x) {
        float x = pts[i * 3 + 0], y = pts[i * 3 + 1], z = pts[i * 3 + 2];
        px[i] = x; py[i] = y; pz[i] = z;
        sq[i] = x * x + y * y + z * z;
    }
    __syncthreads();

    int row = blockIdx.x * blockDim.x + threadIdx.x;
    float bx = px[row], by = py[row], bz = pz[row], bsq = sq[row];

    float bestd[KNN];
    int   besti[KNN];
#pragma unroll
    for (int t = 0; t < KNN; t++) { bestd[t] = INFINITY; besti[t] = -1; }

    for (int j = 0; j < 2048; j++) {
        float dot = bx * px[j] + by * py[j] + bz * pz[j];
        float d2  = bsq + sq[j] - 2.0f * dot;
        if (d2 < bestd[KNN - 1]) {
            int t = KNN - 1;
#pragma unroll
            for (int u = KNN - 1; u > 0; u--) {
                if (bestd[u - 1] > d2) { bestd[u] = bestd[u - 1]; besti[u] = besti[u - 1]; t = u - 1; }
                else break;
            }
            bestd[t] = d2; besti[t] = j;
        }
    }

    int* out = g_idx + ((size_t)set * NQ + row) * KNN;
#pragma unroll
    for (int t = 0; t < KNN; t++) out[t] = besti[t];
}

// =====================================================================
// Kernel 2: edge features
// =====================================================================
__global__ void edge_feats_kernel(const float* __restrict__ cur_f,
                                  const float* __restrict__ nbr_f)
{
    int gid = blockIdx.x;
    int set = gid >> 11;
    int row = gid & 2047;

    const float* f;
    float* outp;
    if (set < 2) {
        f    = cur_f + (size_t)set * NQ * DD;
        outp = g_cur_edge + ((size_t)set * NQ + row) * DD;
    } else {
        int mb = set - 2;
        int m = mb >> 1, b = mb & 1;
        f    = nbr_f + (size_t)mb * NNK * DD;
        outp = g_all_nbr + ((size_t)b * LK + (size_t)m * NNK + row) * DD;
    }

    const int* idx = g_idx + ((size_t)set * NQ + row) * KNN;
    int d = threadIdx.x;

    float acc = 0.0f;
#pragma unroll
    for (int t = 0; t < KNN; t++)
        acc += f[(size_t)idx[t] * DD + d];

    outp[d] = f[(size_t)row * DD + d] - acc * 0.125f;
}

// =====================================================================
// Kernel 3: projection GEMM on tensor pipe (m16n8k8 tf32)
// CTA tile 128x64, 8 warps, k-chunk 32, double-buffered.
// out_bf16: pack output as bf16x2 u32 (Q/K/V for flash)
// pts != null: fused spatial-embedding epilogue (final output kernel)
// =====================================================================
#define PSTR 36
#define PROJ_SMEM_FLOATS (2 * 128 * PSTR + 2 * 64 * PSTR)
#define PSM_A(buf) ((buf) * (128 * PSTR))
#define PSM_W(buf) (2 * 128 * PSTR + (buf) * (64 * PSTR))

__global__ void __launch_bounds__(256, 2)
gemm_proj_mma(const float* __restrict__ A,
              const float* __restrict__ W,
              const float* __restrict__ bias,
              float* __restrict__ C,
              int out_bf16,
              const float* __restrict__ pts,   // may be null
              const float* __restrict__ sw,
              const float* __restrict__ sb)
{
    extern __shared__ float psm[];

    int tid = threadIdx.x;
    int wid = tid >> 5, lane = tid & 31;
    int g = lane >> 2, j = lane & 3;
    int wm = wid >> 1, wn = wid & 1;
    int m0 = blockIdx.x * 128;
    int n0 = blockIdx.y * 64;

    int ar[4], ac[4];
#pragma unroll
    for (int u = 0; u < 4; u++) {
        int fid = tid + 256 * u;
        ar[u] = fid >> 3;  ac[u] = (fid & 7) * 4;
    }
    int wr[2], wc[2];
#pragma unroll
    for (int u = 0; u < 2; u++) {
        int fid = tid + 256 * u;
        wr[u] = fid >> 3;  wc[u] = (fid & 7) * 4;
    }

    const float* Ab = A + (size_t)m0 * 256;
    const float* Wb = W + (size_t)n0 * 256;

    float acc[2][4][4];
#pragma unroll
    for (int i = 0; i < 2; i++)
#pragma unroll
        for (int n = 0; n < 4; n++)
#pragma unroll
            for (int r = 0; r < 4; r++) acc[i][n][r] = 0.0f;

    float4 apre[4], wpre[2];
#pragma unroll
    for (int u = 0; u < 4; u++) apre[u] = *(const float4*)&Ab[(size_t)ar[u] * 256 + ac[u]];
#pragma unroll
    for (int u = 0; u < 2; u++) wpre[u] = *(const float4*)&Wb[(size_t)wr[u] * 256 + wc[u]];
#pragma unroll
    for (int u = 0; u < 4; u++) {
        uint4 t;
        t.x = f2tf32(apre[u].x); t.y = f2tf32(apre[u].y);
        t.z = f2tf32(apre[u].z); t.w = f2tf32(apre[u].w);
        *(uint4*)&psm[PSM_A(0) + ar[u] * PSTR + ac[u]] = t;
    }
#pragma unroll
    for (int u = 0; u < 2; u++) {
        uint4 t;
        t.x = f2tf32(wpre[u].x); t.y = f2tf32(wpre[u].y);
        t.z = f2tf32(wpre[u].z); t.w = f2tf32(wpre[u].w);
        *(uint4*)&psm[PSM_W(0) + wr[u] * PSTR + wc[u]] = t;
    }

    for (int it = 0; it < 8; it++) {
        int s = it & 1;
        if (it < 7) {
            int ko = (it + 1) * 32;
#pragma unroll
            for (int u = 0; u < 4; u++) apre[u] = *(const float4*)&Ab[(size_t)ar[u] * 256 + ko + ac[u]];
#pragma unroll
            for (int u = 0; u < 2; u++) wpre[u] = *(const float4*)&Wb[(size_t)wr[u] * 256 + ko + wc[u]];
        }
        __syncthreads();
        if (it < 7) {
#pragma unroll
            for (int u = 0; u < 4; u++) {
                uint4 t;
                t.x = f2tf32(apre[u].x); t.y = f2tf32(apre[u].y);
                t.z = f2tf32(apre[u].z); t.w = f2tf32(apre[u].w);
                *(uint4*)&psm[PSM_A(1 - s) + ar[u] * PSTR + ac[u]] = t;
            }
#pragma unroll
            for (int u = 0; u < 2; u++) {
                uint4 t;
                t.x = f2tf32(wpre[u].x); t.y = f2tf32(wpre[u].y);
                t.z = f2tf32(wpre[u].z); t.w = f2tf32(wpre[u].w);
                *(uint4*)&psm[PSM_W(1 - s) + wr[u] * PSTR + wc[u]] = t;
            }
        }

        const uint32_t* As = (const uint32_t*)&psm[PSM_A(s)];
        const uint32_t* Ws = (const uint32_t*)&psm[PSM_W(s)];

#pragma unroll
        for (int kt = 0; kt < 4; kt++) {
            uint32_t af[2][4];
#pragma unroll
            for (int i = 0; i < 2; i++) {
                int rb = wm * 32 + i * 16;
                af[i][0] = As[(rb + g)     * PSTR + kt * 8 + j];
                af[i][1] = As[(rb + g + 8) * PSTR + kt * 8 + j];
                af[i][2] = As[(rb + g)     * PSTR + kt * 8 + j + 4];
                af[i][3] = As[(rb + g + 8) * PSTR + kt * 8 + j + 4];
            }
#pragma unroll
            for (int n = 0; n < 4; n++) {
                int nb = wn * 32 + n * 8;
                uint32_t b0 = Ws[(nb + g) * PSTR + kt * 8 + j];
                uint32_t b1 = Ws[(nb + g) * PSTR + kt * 8 + j + 4];
#pragma unroll
                for (int i = 0; i < 2; i++)
                    mma_tf32(acc[i][n][0], acc[i][n][1], acc[i][n][2], acc[i][n][3],
                             af[i][0], af[i][1], af[i][2], af[i][3], b0, b1);
            }
        }
    }

#pragma unroll
    for (int i = 0; i < 2; i++) {
        int r_lo = m0 + wm * 32 + i * 16 + g;
        float p0a = 0.f, p1a = 0.f, p2a = 0.f, p0b = 0.f, p1b = 0.f, p2b = 0.f;
        if (pts) {
            p0a = pts[r_lo * 3 + 0]; p1a = pts[r_lo * 3 + 1]; p2a = pts[r_lo * 3 + 2];
            p0b = pts[(r_lo + 8) * 3 + 0]; p1b = pts[(r_lo + 8) * 3 + 1]; p2b = pts[(r_lo + 8) * 3 + 2];
        }
#pragma unroll
        for (int n = 0; n < 4; n++) {
            int col = n0 + wn * 32 + n * 8 + 2 * j;
            float b0 = bias[col], b1 = bias[col + 1];
            float v00 = acc[i][n][0] + b0, v01 = acc[i][n][1] + b1;
            float v10 = acc[i][n][2] + b0, v11 = acc[i][n][3] + b1;
            if (pts) {
                float s0 = sw[col * 3], s1 = sw[col * 3 + 1], s2 = sw[col * 3 + 2];
                float t0 = sw[(col+1) * 3], t1 = sw[(col+1) * 3 + 1], t2 = sw[(col+1) * 3 + 2];
                v00 += p0a * s0 + p1a * s1 + p2a * s2 + sb[col];
                v01 += p0a * t0 + p1a * t1 + p2a * t2 + sb[col + 1];
                v10 += p0b * s0 + p1b * s1 + p2b * s2 + sb[col];
                v11 += p0b * t0 + p1b * t1 + p2b * t2 + sb[col + 1];
            }
            if (out_bf16) {
                uint32_t* Cu = (uint32_t*)C;
                Cu[(size_t)r_lo * 128 + (col >> 1)]       = pk_bf16x2(v00, v01);
                Cu[(size_t)(r_lo + 8) * 128 + (col >> 1)] = pk_bf16x2(v10, v11);
            } else {
                *(float2*)&C[(size_t)r_lo * 256 + col]       = make_float2(v00, v01);
                *(float2*)&C[(size_t)(r_lo + 8) * 256 + col] = make_float2(v10, v11);
            }
        }
    }
}

// =====================================================================
// Kernel 4: flash attention, full bf16 MMA (m16n8k16) both GEMMs
// 128 q/CTA, 8 warps x 16 q-rows; kv chunk 128, double-buffered.
// K smem: [kv][dh-pair] u32, stride 20. V smem: kv-pair-packed
// [kvpair][dh] u32, stride 40 (PRMT repack at staging).
// No-max softmax (scores provably tiny), O accumulated across all kv.
// =====================================================================
#define KV32 20
#define VV32 40
#define SMEM_K_OFF(buf) ((buf) * (128 * KV32))
#define SMEM_V_OFF(buf) (2 * 128 * KV32 + (buf) * (64 * VV32))
#define FLASH_SMEM_U32 (2 * 128 * KV32 + 2 * 64 * VV32)

__global__ void __launch_bounds__(256, 2)
flash_mma_kernel(const uint32_t* __restrict__ Q, const uint32_t* __restrict__ K,
                 const uint32_t* __restrict__ V, float* __restrict__ O)
{
    extern __shared__ uint32_t smu[];

    const float SCALE = 0.17677669529663687f;   // 1/sqrt(32)
    int tid = threadIdx.x;
    int wid = tid >> 5, lane = tid & 31;
    int g = lane >> 2, j = lane & 3;
    int q0 = blockIdx.x * 128;
    int bh = blockIdx.y, b = bh >> 3, h = bh & 7;

    const uint32_t* qp = Q + ((size_t)b * NQ + q0 + wid * 16) * 128 + h * 16;
    const uint32_t* kp = K + (size_t)b * LK * 128 + h * 16;
    const uint32_t* vp = V + (size_t)b * LK * 128 + h * 16;

    // Q A-fragments (bf16 m16n8k16, 2 k-tiles over dh=32)
    uint32_t aq[2][4];
#pragma unroll
    for (int kt = 0; kt < 2; kt++) {
        aq[kt][0] = qp[(size_t)g * 128 + kt * 8 + j];
        aq[kt][1] = qp[(size_t)(g + 8) * 128 + kt * 8 + j];
        aq[kt][2] = qp[(size_t)g * 128 + kt * 8 + j + 4];
        aq[kt][3] = qp[(size_t)(g + 8) * 128 + kt * 8 + j + 4];
    }

    float o[4][4];
#pragma unroll
    for (int n = 0; n < 4; n++)
#pragma unroll
        for (int r = 0; r < 4; r++) o[n][r] = 0.0f;
    float l0 = 0.0f, l1 = 0.0f;

    // staging maps
    int krow[2], kq4[2];
#pragma unroll
    for (int u = 0; u < 2; u++) {
        int fid = tid + 256 * u;
        krow[u] = fid >> 2;        // 0..127
        kq4[u]  = (fid & 3) * 4;   // u32 quad 0/4/8/12
    }
    int vpi = tid >> 2, vqq = (tid & 3) * 4;   // pair 0..63, u32 quad (of 16)

    // prefetch chunk 0
    uint4 kpre[2], ve, vo;
#pragma unroll
    for (int u = 0; u < 2; u++)
        kpre[u] = *(const uint4*)&kp[(size_t)krow[u] * 128 + kq4[u]];
    ve = *(const uint4*)&vp[(size_t)(2 * vpi) * 128 + vqq];
    vo = *(const uint4*)&vp[(size_t)(2 * vpi + 1) * 128 + vqq];

    // stage chunk 0
#pragma unroll
    for (int u = 0; u < 2; u++)
        *(uint4*)&smu[SMEM_K_OFF(0) + krow[u] * KV32 + kq4[u]] = kpre[u];
    {
        uint4 w0, w1;
        w0.x = prmt(ve.x, vo.x, 0x5410); w0.y = prmt(ve.x, vo.x, 0x7632);
        w0.z = prmt(ve.y, vo.y, 0x5410); w0.w = prmt(ve.y, vo.y, 0x7632);
        w1.x = prmt(ve.z, vo.z, 0x5410); w1.y = prmt(ve.z, vo.z, 0x7632);
        w1.z = prmt(ve.w, vo.w, 0x5410); w1.w = prmt(ve.w, vo.w, 0x7632);
        *(uint4*)&smu[SMEM_V_OFF(0) + vpi * VV32 + vqq * 2]     = w0;
        *(uint4*)&smu[SMEM_V_OFF(0) + vpi * VV32 + vqq * 2 + 4] = w1;
    }

    for (int c = 0; c < 32; c++) {
        int buf = c & 1;
        if (c < 31) {
            int kb = (c + 1) * 128;
#pragma unroll
            for (int u = 0; u < 2; u++)
                kpre[u] = *(const uint4*)&kp[(size_t)(kb + krow[u]) * 128 + kq4[u]];
            ve = *(const uint4*)&vp[(size_t)(kb + 2 * vpi) * 128 + vqq];
            vo = *(const uint4*)&vp[(size_t)(kb + 2 * vpi + 1) * 128 + vqq];
        }
        __syncthreads();

        const uint32_t* Ks = &smu[SMEM_K_OFF(buf)];
        const uint32_t* Vs = &smu[SMEM_V_OFF(buf)];

#pragma unroll
        for (int nh = 0; nh < 2; nh++) {
            // ---- S = Q K^T (bf16 k16) for 8 n-tiles (64 kv) ----
            float s[8][4];
#pragma unroll
            for (int nt = 0; nt < 8; nt++)
#pragma unroll
                for (int r = 0; r < 4; r++) s[nt][r] = 0.0f;

#pragma unroll
            for (int kt = 0; kt < 2; kt++) {
#pragma unroll
                for (int nt = 0; nt < 8; nt++) {
                    int kvrow = nh * 64 + nt * 8 + g;
                    uint32_t b0 = Ks[kvrow * KV32 + kt * 8 + j];
                    uint32_t b1 = Ks[kvrow * KV32 + kt * 8 + j + 4];
                    mma_bf16(s[nt][0], s[nt][1], s[nt][2], s[nt][3],
                             aq[kt][0], aq[kt][1], aq[kt][2], aq[kt][3], b0, b1);
                }
            }

            // ---- exp + pack to bf16 A-frags + P*V (k16) ----
#pragma unroll
            for (int t = 0; t < 4; t++) {
                float pe0 = __expf(s[2*t][0] * SCALE);
                float pe1 = __expf(s[2*t][1] * SCALE);
                float pe2 = __expf(s[2*t][2] * SCALE);
                float pe3 = __expf(s[2*t][3] * SCALE);
                float po0 = __expf(s[2*t+1][0] * SCALE);
                float po1 = __expf(s[2*t+1][1] * SCALE);
                float po2 = __expf(s[2*t+1][2] * SCALE);
                float po3 = __expf(s[2*t+1][3] * SCALE);
                l0 += (pe0 + pe1) + (po0 + po1);
                l1 += (pe2 + pe3) + (po2 + po3);

                uint32_t a0 = pk_bf16x2(pe0, pe1);
                uint32_t a1 = pk_bf16x2(pe2, pe3);
                uint32_t a2 = pk_bf16x2(po0, po1);
                uint32_t a3 = pk_bf16x2(po2, po3);

                int pairbase = (nh * 4 + t) * 8;
#pragma unroll
                for (int no = 0; no < 4; no++) {
                    uint32_t b0 = Vs[(pairbase + j)     * VV32 + no * 8 + g];
                    uint32_t b1 = Vs[(pairbase + j + 4) * VV32 + no * 8 + g];
                    mma_bf16(o[no][0], o[no][1], o[no][2], o[no][3],
                             a0, a1, a2, a3, b0, b1);
                }
            }
        }

        if (c < 31) {
            int nb = 1 - buf;
#pragma unroll
            for (int u = 0; u < 2; u++)
                *(uint4*)&smu[SMEM_K_OFF(nb) + krow[u] * KV32 + kq4[u]] = kpre[u];
            uint4 w0, w1;
            w0.x = prmt(ve.x, vo.x, 0x5410); w0.y = prmt(ve.x, vo.x, 0x7632);
            w0.z = prmt(ve.y, vo.y, 0x5410); w0.w = prmt(ve.y, vo.y, 0x7632);
            w1.x = prmt(ve.z, vo.z, 0x5410); w1.y = prmt(ve.z, vo.z, 0x7632);
            w1.z = prmt(ve.w, vo.w, 0x5410); w1.w = prmt(ve.w, vo.w, 0x7632);
            *(uint4*)&smu[SMEM_V_OFF(nb) + vpi * VV32 + vqq * 2]     = w0;
            *(uint4*)&smu[SMEM_V_OFF(nb) + vpi * VV32 + vqq * 2 + 4] = w1;
        }
    }

    l0 += __shfl_xor_sync(0xffffffffu, l0, 1, 4);
    l0 += __shfl_xor_sync(0xffffffffu, l0, 2, 4);
    l1 += __shfl_xor_sync(0xffffffffu, l1, 1, 4);
    l1 += __shfl_xor_sync(0xffffffffu, l1, 2, 4);
    float inv0 = 1.0f / l0, inv1 = 1.0f / l1;

    float* op = O + ((size_t)b * NQ + q0 + wid * 16) * DD + h * DH;
#pragma unroll
    for (int no = 0; no < 4; no++) {
        int col = no * 8 + 2 * j;
        float2 lo = make_float2(o[no][0] * inv0, o[no][1] * inv0);
        float2 hi = make_float2(o[no][2] * inv1, o[no][3] * inv1);
        *(float2*)&op[(size_t)g * DD + col]       = lo;
        *(float2*)&op[(size_t)(g + 8) * DD + col] = hi;
    }
}

// =====================================================================
// Launch
// =====================================================================
extern "C" void kernel_launch(void* const* d_in, const int* in_sizes, int n_in,
                              void* d_out, int out_size)
{
    const float* cur_pts = (const float*)d_in[0];
    const float* cur_f   = (const float*)d_in[1];
    const float* nbr_pts = (const float*)d_in[2];
    const float* nbr_f   = (const float*)d_in[3];
    const float* in_w    = (const float*)d_in[4];
    const float* in_b    = (const float*)d_in[5];
    const float* out_w   = (const float*)d_in[6];
    const float* out_b   = (const float*)d_in[7];
    const float* sw      = (const float*)d_in[8];
    const float* sb      = (const float*)d_in[9];
    float* out = (float*)d_out;

    uint32_t *dq, *dk, *dv;
    float *dce, *dan, *dat;
    cudaGetSymbolAddress((void**)&dq,  g_q);
    cudaGetSymbolAddress((void**)&dk,  g_k);
    cudaGetSymbolAddress((void**)&dv,  g_v);
    cudaGetSymbolAddress((void**)&dce, g_cur_edge);
    cudaGetSymbolAddress((void**)&dan, g_all_nbr);
    cudaGetSymbolAddress((void**)&dat, g_attn);

    int flash_smem = FLASH_SMEM_U32 * (int)sizeof(uint32_t);
    int proj_smem  = PROJ_SMEM_FLOATS * (int)sizeof(float);
    static int attr_set = 0;
    if (!attr_set) {
        cudaFuncSetAttribute(flash_mma_kernel,
                             cudaFuncAttributeMaxDynamicSharedMemorySize, flash_smem);
        cudaFuncSetAttribute(gemm_proj_mma,
                             cudaFuncAttributeMaxDynamicSharedMemorySize, proj_smem);
        attr_set = 1;
    }

    knn_topk_kernel<<<dim3(NQ / 128, NSETS), 128>>>(cur_pts, nbr_pts);
    edge_feats_kernel<<<NSETS * NQ, DD>>>(cur_f, nbr_f);

    gemm_proj_mma<<<dim3((BB * NQ) / 128, 4), 256, proj_smem>>>(
        dce, in_w,           in_b,       (float*)dq, 1, nullptr, nullptr, nullptr);
    gemm_proj_mma<<<dim3((BB * LK) / 128, 4), 256, proj_smem>>>(
        dan, in_w + 256*256, in_b + 256, (float*)dk, 1, nullptr, nullptr, nullptr);
    gemm_proj_mma<<<dim3((BB * LK) / 128, 4), 256, proj_smem>>>(
        dan, in_w + 512*256, in_b + 512, (float*)dv, 1, nullptr, nullptr, nullptr);

    flash_mma_kernel<<<dim3(NQ / 128, BB * HH), 256, flash_smem>>>(dq, dk, dv, dat);

    // output projection + fused spatial epilogue (tf32 GEMM, fp32 epilogue)
    gemm_proj_mma<<<dim3((BB * NQ) / 128, 4), 256, proj_smem>>>(
        dat, out_w, out_b, out, 0, cur_pts, sw, sb);
}

// round 9
// speedup vs baseline: 3.8960x; 1.0918x over previous
#include <cuda_runtime.h>
#include <math.h>
#include <stdint.h>

// Problem constants
#define BB   2
#define NQ   2048
#define DD   256
#define HH   8
#define DH   32
#define LK   4096      // M*NN
#define NNK  2048
#define KNN  8
#define NSETS 6

static __device__ __forceinline__ uint32_t f2tf32(float x) {
    uint32_t u;
    asm("cvt.rna.tf32.f32 %0, %1;" : "=r"(u) : "f"(x));
    return u;
}
// pack {lo, hi} floats into f16x2 (lo -> bits[0:16])
static __device__ __forceinline__ uint32_t pk_f16x2(float lo, float hi) {
    uint32_t d;
    asm("cvt.rn.f16x2.f32 %0, %1, %2;" : "=r"(d) : "f"(hi), "f"(lo));
    return d;
}
// 2^x elementwise on f16x2
static __device__ __forceinline__ uint32_t ex2_f16x2(uint32_t x) {
    uint32_t d;
    asm("ex2.approx.f16x2 %0, %1;" : "=r"(d) : "r"(x));
    return d;
}
static __device__ __forceinline__ uint32_t prmt(uint32_t a, uint32_t b, uint32_t s) {
    uint32_t d;
    asm("prmt.b32 %0, %1, %2, %3;" : "=r"(d) : "r"(a), "r"(b), "r"(s));
    return d;
}

// m16n8k8 tf32 mma (projection kernels)
static __device__ __forceinline__ void mma_tf32(float& d0, float& d1, float& d2, float& d3,
                                                uint32_t a0, uint32_t a1, uint32_t a2, uint32_t a3,
                                                uint32_t b0, uint32_t b1)
{
    asm volatile(
        "mma.sync.aligned.m16n8k8.row.col.f32.tf32.tf32.f32 "
        "{%0,%1,%2,%3}, {%4,%5,%6,%7}, {%8,%9}, {%0,%1,%2,%3};"
        : "+f"(d0), "+f"(d1), "+f"(d2), "+f"(d3)
        : "r"(a0), "r"(a1), "r"(a2), "r"(a3), "r"(b0), "r"(b1));
}

// m16n8k16 f16 mma (f32 accum)
static __device__ __forceinline__ void mma_f16(float& d0, float& d1, float& d2, float& d3,
                                               uint32_t a0, uint32_t a1, uint32_t a2, uint32_t a3,
                                               uint32_t b0, uint32_t b1)
{
    asm volatile(
        "mma.sync.aligned.m16n8k16.row.col.f32.f16.f16.f32 "
        "{%0,%1,%2,%3}, {%4,%5,%6,%7}, {%8,%9}, {%0,%1,%2,%3};"
        : "+f"(d0), "+f"(d1), "+f"(d2), "+f"(d3)
        : "r"(a0), "r"(a1), "r"(a2), "r"(a3), "r"(b0), "r"(b1));
}

#define ONESH2 0x3C003C00u   // f16x2 {1.0, 1.0}

// ---------------- scratch ----------------
__device__ float    g_cur_edge[BB * NQ * DD];
__device__ float    g_all_nbr [BB * LK * DD];
__device__ uint32_t g_q   [BB * NQ * DD / 2];    // f16x2 packed (pre-scaled)
__device__ uint32_t g_k   [BB * LK * DD / 2];
__device__ uint32_t g_v   [BB * LK * DD / 2];
__device__ float    g_attn[BB * NQ * DD];
__device__ int      g_idx [NSETS * NQ * KNN];

// =====================================================================
// Kernel 1: KNN top-8 (4x unrolled scan: independent distance chains)
// =====================================================================
__global__ void knn_topk_kernel(const float* __restrict__ cur_pts,
                                const float* __restrict__ nbr_pts)
{
    int set = blockIdx.y;
    const float* pts = (set < 2) ? (cur_pts + (size_t)set * NQ * 3)
                                 : (nbr_pts + (size_t)(set - 2) * NNK * 3);
    __shared__ float px[2048], py[2048], pz[2048], sq[2048];
    for (int i = threadIdx.x; i < 2048; i += blockDim.x) {
        float x = pts[i * 3 + 0], y = pts[i * 3 + 1], z = pts[i * 3 + 2];
        px[i] = x; py[i] = y; pz[i] = z;
        sq[i] = x * x + y * y + z * z;
    }
    __syncthreads();

    int row = blockIdx.x * blockDim.x + threadIdx.x;
    float bx = px[row], by = py[row], bz = pz[row], bsq = sq[row];

    float bestd[KNN];
    int   besti[KNN];
#pragma unroll
    for (int t = 0; t < KNN; t++) { bestd[t] = INFINITY; besti[t] = -1; }

    for (int j0 = 0; j0 < 2048; j0 += 4) {
        float d2v[4];
#pragma unroll
        for (int u = 0; u < 4; u++) {
            int jj = j0 + u;
            float dot = bx * px[jj] + by * py[jj] + bz * pz[jj];
            d2v[u] = bsq + sq[jj] - 2.0f * dot;
        }
#pragma unroll
        for (int u = 0; u < 4; u++) {
            float d2 = d2v[u];
            if (d2 < bestd[KNN - 1]) {
                int t = KNN - 1;
#pragma unroll
                for (int w = KNN - 1; w > 0; w--) {
                    if (bestd[w - 1] > d2) { bestd[w] = bestd[w - 1]; besti[w] = besti[w - 1]; t = w - 1; }
                    else break;
                }
                bestd[t] = d2; besti[t] = j0 + u;
            }
        }
    }

    int* out = g_idx + ((size_t)set * NQ + row) * KNN;
#pragma unroll
    for (int t = 0; t < KNN; t++) out[t] = besti[t];
}

// =====================================================================
// Kernel 2: edge features
// =====================================================================
__global__ void edge_feats_kernel(const float* __restrict__ cur_f,
                                  const float* __restrict__ nbr_f)
{
    int gid = blockIdx.x;
    int set = gid >> 11;
    int row = gid & 2047;

    const float* f;
    float* outp;
    if (set < 2) {
        f    = cur_f + (size_t)set * NQ * DD;
        outp = g_cur_edge + ((size_t)set * NQ + row) * DD;
    } else {
        int mb = set - 2;
        int m = mb >> 1, b = mb & 1;
        f    = nbr_f + (size_t)mb * NNK * DD;
        outp = g_all_nbr + ((size_t)b * LK + (size_t)m * NNK + row) * DD;
    }

    const int* idx = g_idx + ((size_t)set * NQ + row) * KNN;
    int d = threadIdx.x;

    float acc = 0.0f;
#pragma unroll
    for (int t = 0; t < KNN; t++)
        acc += f[(size_t)idx[t] * DD + d];

    outp[d] = f[(size_t)row * DD + d] - acc * 0.125f;
}

// =====================================================================
// Kernel 3: projection GEMM on tensor pipe (m16n8k8 tf32)
// CTA tile 128x64, 8 warps, k-chunk 32, double-buffered.
// out_half: scale by oscale, pack output as f16x2 (Q/K/V for flash)
// pts != null: fused spatial-embedding epilogue (final output kernel)
// =====================================================================
#define PSTR 36
#define PROJ_SMEM_FLOATS (2 * 128 * PSTR + 2 * 64 * PSTR)
#define PSM_A(buf) ((buf) * (128 * PSTR))
#define PSM_W(buf) (2 * 128 * PSTR + (buf) * (64 * PSTR))

__global__ void __launch_bounds__(256, 2)
gemm_proj_mma(const float* __restrict__ A,
              const float* __restrict__ W,
              const float* __restrict__ bias,
              float* __restrict__ C,
              int out_half,
              float oscale,
              const float* __restrict__ pts,   // may be null
              const float* __restrict__ sw,
              const float* __restrict__ sb)
{
    extern __shared__ float psm[];

    int tid = threadIdx.x;
    int wid = tid >> 5, lane = tid & 31;
    int g = lane >> 2, j = lane & 3;
    int wm = wid >> 1, wn = wid & 1;
    int m0 = blockIdx.x * 128;
    int n0 = blockIdx.y * 64;

    int ar[4], ac[4];
#pragma unroll
    for (int u = 0; u < 4; u++) {
        int fid = tid + 256 * u;
        ar[u] = fid >> 3;  ac[u] = (fid & 7) * 4;
    }
    int wr[2], wc[2];
#pragma unroll
    for (int u = 0; u < 2; u++) {
        int fid = tid + 256 * u;
        wr[u] = fid >> 3;  wc[u] = (fid & 7) * 4;
    }

    const float* Ab = A + (size_t)m0 * 256;
    const float* Wb = W + (size_t)n0 * 256;

    float acc[2][4][4];
#pragma unroll
    for (int i = 0; i < 2; i++)
#pragma unroll
        for (int n = 0; n < 4; n++)
#pragma unroll
            for (int r = 0; r < 4; r++) acc[i][n][r] = 0.0f;

    float4 apre[4], wpre[2];
#pragma unroll
    for (int u = 0; u < 4; u++) apre[u] = *(const float4*)&Ab[(size_t)ar[u] * 256 + ac[u]];
#pragma unroll
    for (int u = 0; u < 2; u++) wpre[u] = *(const float4*)&Wb[(size_t)wr[u] * 256 + wc[u]];
#pragma unroll
    for (int u = 0; u < 4; u++) {
        uint4 t;
        t.x = f2tf32(apre[u].x); t.y = f2tf32(apre[u].y);
        t.z = f2tf32(apre[u].z); t.w = f2tf32(apre[u].w);
        *(uint4*)&psm[PSM_A(0) + ar[u] * PSTR + ac[u]] = t;
    }
#pragma unroll
    for (int u = 0; u < 2; u++) {
        uint4 t;
        t.x = f2tf32(wpre[u].x); t.y = f2tf32(wpre[u].y);
        t.z = f2tf32(wpre[u].z); t.w = f2tf32(wpre[u].w);
        *(uint4*)&psm[PSM_W(0) + wr[u] * PSTR + wc[u]] = t;
    }

    for (int it = 0; it < 8; it++) {
        int s = it & 1;
        if (it < 7) {
            int ko = (it + 1) * 32;
#pragma unroll
            for (int u = 0; u < 4; u++) apre[u] = *(const float4*)&Ab[(size_t)ar[u] * 256 + ko + ac[u]];
#pragma unroll
            for (int u = 0; u < 2; u++) wpre[u] = *(const float4*)&Wb[(size_t)wr[u] * 256 + ko + wc[u]];
        }
        __syncthreads();
        if (it < 7) {
#pragma unroll
            for (int u = 0; u < 4; u++) {
                uint4 t;
                t.x = f2tf32(apre[u].x); t.y = f2tf32(apre[u].y);
                t.z = f2tf32(apre[u].z); t.w = f2tf32(apre[u].w);
                *(uint4*)&psm[PSM_A(1 - s) + ar[u] * PSTR + ac[u]] = t;
            }
#pragma unroll
            for (int u = 0; u < 2; u++) {
                uint4 t;
                t.x = f2tf32(wpre[u].x); t.y = f2tf32(wpre[u].y);
                t.z = f2tf32(wpre[u].z); t.w = f2tf32(wpre[u].w);
                *(uint4*)&psm[PSM_W(1 - s) + wr[u] * PSTR + wc[u]] = t;
            }
        }

        const uint32_t* As = (const uint32_t*)&psm[PSM_A(s)];
        const uint32_t* Ws = (const uint32_t*)&psm[PSM_W(s)];

#pragma unroll
        for (int kt = 0; kt < 4; kt++) {
            uint32_t af[2][4];
#pragma unroll
            for (int i = 0; i < 2; i++) {
                int rb = wm * 32 + i * 16;
                af[i][0] = As[(rb + g)     * PSTR + kt * 8 + j];
                af[i][1] = As[(rb + g + 8) * PSTR + kt * 8 + j];
                af[i][2] = As[(rb + g)     * PSTR + kt * 8 + j + 4];
                af[i][3] = As[(rb + g + 8) * PSTR + kt * 8 + j + 4];
            }
#pragma unroll
            for (int n = 0; n < 4; n++) {
                int nb = wn * 32 + n * 8;
                uint32_t b0 = Ws[(nb + g) * PSTR + kt * 8 + j];
                uint32_t b1 = Ws[(nb + g) * PSTR + kt * 8 + j + 4];
#pragma unroll
                for (int i = 0; i < 2; i++)
                    mma_tf32(acc[i][n][0], acc[i][n][1], acc[i][n][2], acc[i][n][3],
                             af[i][0], af[i][1], af[i][2], af[i][3], b0, b1);
            }
        }
    }

#pragma unroll
    for (int i = 0; i < 2; i++) {
        int r_lo = m0 + wm * 32 + i * 16 + g;
        float p0a = 0.f, p1a = 0.f, p2a = 0.f, p0b = 0.f, p1b = 0.f, p2b = 0.f;
        if (pts) {
            p0a = pts[r_lo * 3 + 0]; p1a = pts[r_lo * 3 + 1]; p2a = pts[r_lo * 3 + 2];
            p0b = pts[(r_lo + 8) * 3 + 0]; p1b = pts[(r_lo + 8) * 3 + 1]; p2b = pts[(r_lo + 8) * 3 + 2];
        }
#pragma unroll
        for (int n = 0; n < 4; n++) {
            int col = n0 + wn * 32 + n * 8 + 2 * j;
            float b0 = bias[col], b1 = bias[col + 1];
            float v00 = acc[i][n][0] + b0, v01 = acc[i][n][1] + b1;
            float v10 = acc[i][n][2] + b0, v11 = acc[i][n][3] + b1;
            if (pts) {
                float s0 = sw[col * 3], s1 = sw[col * 3 + 1], s2 = sw[col * 3 + 2];
                float t0 = sw[(col+1) * 3], t1 = sw[(col+1) * 3 + 1], t2 = sw[(col+1) * 3 + 2];
                v00 += p0a * s0 + p1a * s1 + p2a * s2 + sb[col];
                v01 += p0a * t0 + p1a * t1 + p2a * t2 + sb[col + 1];
                v10 += p0b * s0 + p1b * s1 + p2b * s2 + sb[col];
                v11 += p0b * t0 + p1b * t1 + p2b * t2 + sb[col + 1];
            }
            if (out_half) {
                uint32_t* Cu = (uint32_t*)C;
                Cu[(size_t)r_lo * 128 + (col >> 1)]       = pk_f16x2(v00 * oscale, v01 * oscale);
                Cu[(size_t)(r_lo + 8) * 128 + (col >> 1)] = pk_f16x2(v10 * oscale, v11 * oscale);
            } else {
                *(float2*)&C[(size_t)r_lo * 256 + col]       = make_float2(v00, v01);
                *(float2*)&C[(size_t)(r_lo + 8) * 256 + col] = make_float2(v10, v11);
            }
        }
    }
}

// =====================================================================
// Kernel 4: flash attention, fp16 MMA both GEMMs; P = 2^S via
// ex2.approx.f16x2 (scale folded into Q); row sums via ones-MMA.
// 128 q/CTA, 8 warps x 16 q-rows; kv chunk 128, double-buffered.
// =====================================================================
#define KV32 20
#define VV32 40
#define SMEM_K_OFF(buf) ((buf) * (128 * KV32))
#define SMEM_V_OFF(buf) (2 * 128 * KV32 + (buf) * (64 * VV32))
#define FLASH_SMEM_U32 (2 * 128 * KV32 + 2 * 64 * VV32)

__global__ void __launch_bounds__(256, 2)
flash_mma_kernel(const uint32_t* __restrict__ Q, const uint32_t* __restrict__ K,
                 const uint32_t* __restrict__ V, float* __restrict__ O)
{
    extern __shared__ uint32_t smu[];

    int tid = threadIdx.x;
    int wid = tid >> 5, lane = tid & 31;
    int g = lane >> 2, j = lane & 3;
    int q0 = blockIdx.x * 128;
    int bh = blockIdx.y, b = bh >> 3, h = bh & 7;

    const uint32_t* qp = Q + ((size_t)b * NQ + q0 + wid * 16) * 128 + h * 16;
    const uint32_t* kp = K + (size_t)b * LK * 128 + h * 16;
    const uint32_t* vp = V + (size_t)b * LK * 128 + h * 16;

    // Q A-fragments (f16 m16n8k16, 2 k-tiles over dh=32)
    uint32_t aq[2][4];
#pragma unroll
    for (int kt = 0; kt < 2; kt++) {
        aq[kt][0] = qp[(size_t)g * 128 + kt * 8 + j];
        aq[kt][1] = qp[(size_t)(g + 8) * 128 + kt * 8 + j];
        aq[kt][2] = qp[(size_t)g * 128 + kt * 8 + j + 4];
        aq[kt][3] = qp[(size_t)(g + 8) * 128 + kt * 8 + j + 4];
    }

    float o[4][4];
#pragma unroll
    for (int n = 0; n < 4; n++)
#pragma unroll
        for (int r = 0; r < 4; r++) o[n][r] = 0.0f;
    float lacc[4] = {0.0f, 0.0f, 0.0f, 0.0f};   // ones-MMA row sums

    // staging maps
    int krow[2], kq4[2];
#pragma unroll
    for (int u = 0; u < 2; u++) {
        int fid = tid + 256 * u;
        krow[u] = fid >> 2;
        kq4[u]  = (fid & 3) * 4;
    }
    int vpi = tid >> 2, vqq = (tid & 3) * 4;

    // prefetch chunk 0
    uint4 kpre[2], ve, vo;
#pragma unroll
    for (int u = 0; u < 2; u++)
        kpre[u] = *(const uint4*)&kp[(size_t)krow[u] * 128 + kq4[u]];
    ve = *(const uint4*)&vp[(size_t)(2 * vpi) * 128 + vqq];
    vo = *(const uint4*)&vp[(size_t)(2 * vpi + 1) * 128 + vqq];

    // stage chunk 0
#pragma unroll
    for (int u = 0; u < 2; u++)
        *(uint4*)&smu[SMEM_K_OFF(0) + krow[u] * KV32 + kq4[u]] = kpre[u];
    {
        uint4 w0, w1;
        w0.x = prmt(ve.x, vo.x, 0x5410); w0.y = prmt(ve.x, vo.x, 0x7632);
        w0.z = prmt(ve.y, vo.y, 0x5410); w0.w = prmt(ve.y, vo.y, 0x7632);
        w1.x = prmt(ve.z, vo.z, 0x5410); w1.y = prmt(ve.z, vo.z, 0x7632);
        w1.z = prmt(ve.w, vo.w, 0x5410); w1.w = prmt(ve.w, vo.w, 0x7632);
        *(uint4*)&smu[SMEM_V_OFF(0) + vpi * VV32 + vqq * 2]     = w0;
        *(uint4*)&smu[SMEM_V_OFF(0) + vpi * VV32 + vqq * 2 + 4] = w1;
    }

    for (int c = 0; c < 32; c++) {
        int buf = c & 1;
        if (c < 31) {
            int kb = (c + 1) * 128;
#pragma unroll
            for (int u = 0; u < 2; u++)
                kpre[u] = *(const uint4*)&kp[(size_t)(kb + krow[u]) * 128 + kq4[u]];
            ve = *(const uint4*)&vp[(size_t)(kb + 2 * vpi) * 128 + vqq];
            vo = *(const uint4*)&vp[(size_t)(kb + 2 * vpi + 1) * 128 + vqq];
        }
        __syncthreads();

        const uint32_t* Ks = &smu[SMEM_K_OFF(buf)];
        const uint32_t* Vs = &smu[SMEM_V_OFF(buf)];

#pragma unroll
        for (int nh = 0; nh < 2; nh++) {
            // ---- S = Q K^T (f16 k16) for 8 n-tiles (64 kv) ----
            float s[8][4];
#pragma unroll
            for (int nt = 0; nt < 8; nt++)
#pragma unroll
                for (int r = 0; r < 4; r++) s[nt][r] = 0.0f;

#pragma unroll
            for (int kt = 0; kt < 2; kt++) {
#pragma unroll
                for (int nt = 0; nt < 8; nt++) {
                    int kvrow = nh * 64 + nt * 8 + g;
                    uint32_t b0 = Ks[kvrow * KV32 + kt * 8 + j];
                    uint32_t b1 = Ks[kvrow * KV32 + kt * 8 + j + 4];
                    mma_f16(s[nt][0], s[nt][1], s[nt][2], s[nt][3],
                            aq[kt][0], aq[kt][1], aq[kt][2], aq[kt][3], b0, b1);
                }
            }

            // ---- P = 2^S via f16x2 ex2 (frags direct) + l ones-MMA + P*V ----
#pragma unroll
            for (int t = 0; t < 4; t++) {
                uint32_t a0 = ex2_f16x2(pk_f16x2(s[2*t][0],   s[2*t][1]));
                uint32_t a1 = ex2_f16x2(pk_f16x2(s[2*t][2],   s[2*t][3]));
                uint32_t a2 = ex2_f16x2(pk_f16x2(s[2*t+1][0], s[2*t+1][1]));
                uint32_t a3 = ex2_f16x2(pk_f16x2(s[2*t+1][2], s[2*t+1][3]));

                // row sums of P (f32 accum, cross-lane reduced by MMA)
                mma_f16(lacc[0], lacc[1], lacc[2], lacc[3],
                        a0, a1, a2, a3, ONESH2, ONESH2);

                int pairbase = (nh * 4 + t) * 8;
#pragma unroll
                for (int no = 0; no < 4; no++) {
                    uint32_t b0 = Vs[(pairbase + j)     * VV32 + no * 8 + g];
                    uint32_t b1 = Vs[(pairbase + j + 4) * VV32 + no * 8 + g];
                    mma_f16(o[no][0], o[no][1], o[no][2], o[no][3],
                            a0, a1, a2, a3, b0, b1);
                }
            }
        }

        if (c < 31) {
            int nb = 1 - buf;
#pragma unroll
            for (int u = 0; u < 2; u++)
                *(uint4*)&smu[SMEM_K_OFF(nb) + krow[u] * KV32 + kq4[u]] = kpre[u];
            uint4 w0, w1;
            w0.x = prmt(ve.x, vo.x, 0x5410); w0.y = prmt(ve.x, vo.x, 0x7632);
            w0.z = prmt(ve.y, vo.y, 0x5410); w0.w = prmt(ve.y, vo.y, 0x7632);
            w1.x = prmt(ve.z, vo.z, 0x5410); w1.y = prmt(ve.z, vo.z, 0x7632);
            w1.z = prmt(ve.w, vo.w, 0x5410); w1.w = prmt(ve.w, vo.w, 0x7632);
            *(uint4*)&smu[SMEM_V_OFF(nb) + vpi * VV32 + vqq * 2]     = w0;
            *(uint4*)&smu[SMEM_V_OFF(nb) + vpi * VV32 + vqq * 2 + 4] = w1;
        }
    }

    float inv0 = 1.0f / lacc[0];   // row g sum (cols duplicated)
    float inv1 = 1.0f / lacc[2];   // row g+8 sum

    float* op = O + ((size_t)b * NQ + q0 + wid * 16) * DD + h * DH;
#pragma unroll
    for (int no = 0; no < 4; no++) {
        int col = no * 8 + 2 * j;
        float2 lo = make_float2(o[no][0] * inv0, o[no][1] * inv0);
        float2 hi = make_float2(o[no][2] * inv1, o[no][3] * inv1);
        *(float2*)&op[(size_t)g * DD + col]       = lo;
        *(float2*)&op[(size_t)(g + 8) * DD + col] = hi;
    }
}

// =====================================================================
// Launch
// =====================================================================
extern "C" void kernel_launch(void* const* d_in, const int* in_sizes, int n_in,
                              void* d_out, int out_size)
{
    const float* cur_pts = (const float*)d_in[0];
    const float* cur_f   = (const float*)d_in[1];
    const float* nbr_pts = (const float*)d_in[2];
    const float* nbr_f   = (const float*)d_in[3];
    const float* in_w    = (const float*)d_in[4];
    const float* in_b    = (const float*)d_in[5];
    const float* out_w   = (const float*)d_in[6];
    const float* out_b   = (const float*)d_in[7];
    const float* sw      = (const float*)d_in[8];
    const float* sb      = (const float*)d_in[9];
    float* out = (float*)d_out;

    uint32_t *dq, *dk, *dv;
    float *dce, *dan, *dat;
    cudaGetSymbolAddress((void**)&dq,  g_q);
    cudaGetSymbolAddress((void**)&dk,  g_k);
    cudaGetSymbolAddress((void**)&dv,  g_v);
    cudaGetSymbolAddress((void**)&dce, g_cur_edge);
    cudaGetSymbolAddress((void**)&dan, g_all_nbr);
    cudaGetSymbolAddress((void**)&dat, g_attn);

    int flash_smem = FLASH_SMEM_U32 * (int)sizeof(uint32_t);
    int proj_smem  = PROJ_SMEM_FLOATS * (int)sizeof(float);
    static int attr_set = 0;
    if (!attr_set) {
        cudaFuncSetAttribute(flash_mma_kernel,
                             cudaFuncAttributeMaxDynamicSharedMemorySize, flash_smem);
        cudaFuncSetAttribute(gemm_proj_mma,
                             cudaFuncAttributeMaxDynamicSharedMemorySize, proj_smem);
        attr_set = 1;
    }

    // scale folded into Q so P = 2^S in flash: (1/sqrt(32)) * log2(e)
    const float QSCALE = 0.25503488f;

    knn_topk_kernel<<<dim3(NQ / 128, NSETS), 128>>>(cur_pts, nbr_pts);
    edge_feats_kernel<<<NSETS * NQ, DD>>>(cur_f, nbr_f);

    gemm_proj_mma<<<dim3((BB * NQ) / 128, 4), 256, proj_smem>>>(
        dce, in_w,           in_b,       (float*)dq, 1, QSCALE, nullptr, nullptr, nullptr);
    gemm_proj_mma<<<dim3((BB * LK) / 128, 4), 256, proj_smem>>>(
        dan, in_w + 256*256, in_b + 256, (float*)dk, 1, 1.0f, nullptr, nullptr, nullptr);
    gemm_proj_mma<<<dim3((BB * LK) / 128, 4), 256, proj_smem>>>(
        dan, in_w + 512*256, in_b + 512, (float*)dv, 1, 1.0f, nullptr, nullptr, nullptr);

    flash_mma_kernel<<<dim3(NQ / 128, BB * HH), 256, flash_smem>>>(dq, dk, dv, dat);

    // output projection + fused spatial epilogue (tf32 GEMM, fp32 epilogue)
    gemm_proj_mma<<<dim3((BB * NQ) / 128, 4), 256, proj_smem>>>(
        dat, out_w, out_b, out, 0, 1.0f, cur_pts, sw, sb);
}

// round 10
// speedup vs baseline: 3.9331x; 1.0095x over previous
#include <cuda_runtime.h>
#include <math.h>
#include <stdint.h>

// Problem constants
#define BB   2
#define NQ   2048
#define DD   256
#define HH   8
#define DH   32
#define LK   4096      // M*NN
#define NNK  2048
#define KNN  8
#define NSETS 6

static __device__ __forceinline__ uint32_t f2tf32(float x) {
    uint32_t u;
    asm("cvt.rna.tf32.f32 %0, %1;" : "=r"(u) : "f"(x));
    return u;
}
// pack {lo, hi} floats into f16x2 (lo -> bits[0:16])
static __device__ __forceinline__ uint32_t pk_f16x2(float lo, float hi) {
    uint32_t d;
    asm("cvt.rn.f16x2.f32 %0, %1, %2;" : "=r"(d) : "f"(hi), "f"(lo));
    return d;
}
// 2^x elementwise on f16x2
static __device__ __forceinline__ uint32_t ex2_f16x2(uint32_t x) {
    uint32_t d;
    asm("ex2.approx.f16x2 %0, %1;" : "=r"(d) : "r"(x));
    return d;
}
static __device__ __forceinline__ uint32_t prmt(uint32_t a, uint32_t b, uint32_t s) {
    uint32_t d;
    asm("prmt.b32 %0, %1, %2, %3;" : "=r"(d) : "r"(a), "r"(b), "r"(s));
    return d;
}

// m16n8k8 tf32 mma (projection kernels)
static __device__ __forceinline__ void mma_tf32(float& d0, float& d1, float& d2, float& d3,
                                                uint32_t a0, uint32_t a1, uint32_t a2, uint32_t a3,
                                                uint32_t b0, uint32_t b1)
{
    asm volatile(
        "mma.sync.aligned.m16n8k8.row.col.f32.tf32.tf32.f32 "
        "{%0,%1,%2,%3}, {%4,%5,%6,%7}, {%8,%9}, {%0,%1,%2,%3};"
        : "+f"(d0), "+f"(d1), "+f"(d2), "+f"(d3)
        : "r"(a0), "r"(a1), "r"(a2), "r"(a3), "r"(b0), "r"(b1));
}

// m16n8k16 f16 mma (f32 accum)
static __device__ __forceinline__ void mma_f16(float& d0, float& d1, float& d2, float& d3,
                                               uint32_t a0, uint32_t a1, uint32_t a2, uint32_t a3,
                                               uint32_t b0, uint32_t b1)
{
    asm volatile(
        "mma.sync.aligned.m16n8k16.row.col.f32.f16.f16.f32 "
        "{%0,%1,%2,%3}, {%4,%5,%6,%7}, {%8,%9}, {%0,%1,%2,%3};"
        : "+f"(d0), "+f"(d1), "+f"(d2), "+f"(d3)
        : "r"(a0), "r"(a1), "r"(a2), "r"(a3), "r"(b0), "r"(b1));
}

#define ONESH2 0x3C003C00u   // f16x2 {1.0, 1.0}

// ---------------- scratch ----------------
__device__ float    g_cur_edge[BB * NQ * DD];
__device__ float    g_all_nbr [BB * LK * DD];
__device__ uint32_t g_q   [BB * NQ * DD / 2];    // f16x2 packed (pre-scaled)
__device__ uint32_t g_k   [BB * LK * DD / 2];
__device__ uint32_t g_v   [BB * LK * DD / 2];
__device__ float    g_attn[BB * NQ * DD];
__device__ int      g_idx [NSETS * NQ * KNN];

// =====================================================================
// Kernel 1: KNN top-8 (4x unrolled scan)
// =====================================================================
__global__ void knn_topk_kernel(const float* __restrict__ cur_pts,
                                const float* __restrict__ nbr_pts)
{
    int set = blockIdx.y;
    const float* pts = (set < 2) ? (cur_pts + (size_t)set * NQ * 3)
                                 : (nbr_pts + (size_t)(set - 2) * NNK * 3);
    __shared__ float px[2048], py[2048], pz[2048], sq[2048];
    for (int i = threadIdx.x; i < 2048; i += blockDim.x) {
        float x = pts[i * 3 + 0], y = pts[i * 3 + 1], z = pts[i * 3 + 2];
        px[i] = x; py[i] = y; pz[i] = z;
        sq[i] = x * x + y * y + z * z;
    }
    __syncthreads();

    int row = blockIdx.x * blockDim.x + threadIdx.x;
    float bx = px[row], by = py[row], bz = pz[row], bsq = sq[row];

    float bestd[KNN];
    int   besti[KNN];
#pragma unroll
    for (int t = 0; t < KNN; t++) { bestd[t] = INFINITY; besti[t] = -1; }

    for (int j0 = 0; j0 < 2048; j0 += 4) {
        float d2v[4];
#pragma unroll
        for (int u = 0; u < 4; u++) {
            int jj = j0 + u;
            float dot = bx * px[jj] + by * py[jj] + bz * pz[jj];
            d2v[u] = bsq + sq[jj] - 2.0f * dot;
        }
#pragma unroll
        for (int u = 0; u < 4; u++) {
            float d2 = d2v[u];
            if (d2 < bestd[KNN - 1]) {
                int t = KNN - 1;
#pragma unroll
                for (int w = KNN - 1; w > 0; w--) {
                    if (bestd[w - 1] > d2) { bestd[w] = bestd[w - 1]; besti[w] = besti[w - 1]; t = w - 1; }
                    else break;
                }
                bestd[t] = d2; besti[t] = j0 + u;
            }
        }
    }

    int* out = g_idx + ((size_t)set * NQ + row) * KNN;
#pragma unroll
    for (int t = 0; t < KNN; t++) out[t] = besti[t];
}

// =====================================================================
// Kernel 2: edge features
// =====================================================================
__global__ void edge_feats_kernel(const float* __restrict__ cur_f,
                                  const float* __restrict__ nbr_f)
{
    int gid = blockIdx.x;
    int set = gid >> 11;
    int row = gid & 2047;

    const float* f;
    float* outp;
    if (set < 2) {
        f    = cur_f + (size_t)set * NQ * DD;
        outp = g_cur_edge + ((size_t)set * NQ + row) * DD;
    } else {
        int mb = set - 2;
        int m = mb >> 1, b = mb & 1;
        f    = nbr_f + (size_t)mb * NNK * DD;
        outp = g_all_nbr + ((size_t)b * LK + (size_t)m * NNK + row) * DD;
    }

    const int* idx = g_idx + ((size_t)set * NQ + row) * KNN;
    int d = threadIdx.x;

    float acc = 0.0f;
#pragma unroll
    for (int t = 0; t < KNN; t++)
        acc += f[(size_t)idx[t] * DD + d];

    outp[d] = f[(size_t)row * DD + d] - acc * 0.125f;
}

// =====================================================================
// Kernel 3: projection GEMM on tensor pipe (m16n8k8 tf32)
// (unchanged from round 9 — validated)
// =====================================================================
#define PSTR 36
#define PROJ_SMEM_FLOATS (2 * 128 * PSTR + 2 * 64 * PSTR)
#define PSM_A(buf) ((buf) * (128 * PSTR))
#define PSM_W(buf) (2 * 128 * PSTR + (buf) * (64 * PSTR))

__global__ void __launch_bounds__(256, 2)
gemm_proj_mma(const float* __restrict__ A,
              const float* __restrict__ W,
              const float* __restrict__ bias,
              float* __restrict__ C,
              int out_half,
              float oscale,
              const float* __restrict__ pts,   // may be null
              const float* __restrict__ sw,
              const float* __restrict__ sb)
{
    extern __shared__ float psm[];

    int tid = threadIdx.x;
    int wid = tid >> 5, lane = tid & 31;
    int g = lane >> 2, j = lane & 3;
    int wm = wid >> 1, wn = wid & 1;
    int m0 = blockIdx.x * 128;
    int n0 = blockIdx.y * 64;

    int ar[4], ac[4];
#pragma unroll
    for (int u = 0; u < 4; u++) {
        int fid = tid + 256 * u;
        ar[u] = fid >> 3;  ac[u] = (fid & 7) * 4;
    }
    int wr[2], wc[2];
#pragma unroll
    for (int u = 0; u < 2; u++) {
        int fid = tid + 256 * u;
        wr[u] = fid >> 3;  wc[u] = (fid & 7) * 4;
    }

    const float* Ab = A + (size_t)m0 * 256;
    const float* Wb = W + (size_t)n0 * 256;

    float acc[2][4][4];
#pragma unroll
    for (int i = 0; i < 2; i++)
#pragma unroll
        for (int n = 0; n < 4; n++)
#pragma unroll
            for (int r = 0; r < 4; r++) acc[i][n][r] = 0.0f;

    float4 apre[4], wpre[2];
#pragma unroll
    for (int u = 0; u < 4; u++) apre[u] = *(const float4*)&Ab[(size_t)ar[u] * 256 + ac[u]];
#pragma unroll
    for (int u = 0; u < 2; u++) wpre[u] = *(const float4*)&Wb[(size_t)wr[u] * 256 + wc[u]];
#pragma unroll
    for (int u = 0; u < 4; u++) {
        uint4 t;
        t.x = f2tf32(apre[u].x); t.y = f2tf32(apre[u].y);
        t.z = f2tf32(apre[u].z); t.w = f2tf32(apre[u].w);
        *(uint4*)&psm[PSM_A(0) + ar[u] * PSTR + ac[u]] = t;
    }
#pragma unroll
    for (int u = 0; u < 2; u++) {
        uint4 t;
        t.x = f2tf32(wpre[u].x); t.y = f2tf32(wpre[u].y);
        t.z = f2tf32(wpre[u].z); t.w = f2tf32(wpre[u].w);
        *(uint4*)&psm[PSM_W(0) + wr[u] * PSTR + wc[u]] = t;
    }

    for (int it = 0; it < 8; it++) {
        int s = it & 1;
        if (it < 7) {
            int ko = (it + 1) * 32;
#pragma unroll
            for (int u = 0; u < 4; u++) apre[u] = *(const float4*)&Ab[(size_t)ar[u] * 256 + ko + ac[u]];
#pragma unroll
            for (int u = 0; u < 2; u++) wpre[u] = *(const float4*)&Wb[(size_t)wr[u] * 256 + ko + wc[u]];
        }
        __syncthreads();
        if (it < 7) {
#pragma unroll
            for (int u = 0; u < 4; u++) {
                uint4 t;
                t.x = f2tf32(apre[u].x); t.y = f2tf32(apre[u].y);
                t.z = f2tf32(apre[u].z); t.w = f2tf32(apre[u].w);
                *(uint4*)&psm[PSM_A(1 - s) + ar[u] * PSTR + ac[u]] = t;
            }
#pragma unroll
            for (int u = 0; u < 2; u++) {
                uint4 t;
                t.x = f2tf32(wpre[u].x); t.y = f2tf32(wpre[u].y);
                t.z = f2tf32(wpre[u].z); t.w = f2tf32(wpre[u].w);
                *(uint4*)&psm[PSM_W(1 - s) + wr[u] * PSTR + wc[u]] = t;
            }
        }

        const uint32_t* As = (const uint32_t*)&psm[PSM_A(s)];
        const uint32_t* Ws = (const uint32_t*)&psm[PSM_W(s)];

#pragma unroll
        for (int kt = 0; kt < 4; kt++) {
            uint32_t af[2][4];
#pragma unroll
            for (int i = 0; i < 2; i++) {
                int rb = wm * 32 + i * 16;
                af[i][0] = As[(rb + g)     * PSTR + kt * 8 + j];
                af[i][1] = As[(rb + g + 8) * PSTR + kt * 8 + j];
                af[i][2] = As[(rb + g)     * PSTR + kt * 8 + j + 4];
                af[i][3] = As[(rb + g + 8) * PSTR + kt * 8 + j + 4];
            }
#pragma unroll
            for (int n = 0; n < 4; n++) {
                int nb = wn * 32 + n * 8;
                uint32_t b0 = Ws[(nb + g) * PSTR + kt * 8 + j];
                uint32_t b1 = Ws[(nb + g) * PSTR + kt * 8 + j + 4];
#pragma unroll
                for (int i = 0; i < 2; i++)
                    mma_tf32(acc[i][n][0], acc[i][n][1], acc[i][n][2], acc[i][n][3],
                             af[i][0], af[i][1], af[i][2], af[i][3], b0, b1);
            }
        }
    }

#pragma unroll
    for (int i = 0; i < 2; i++) {
        int r_lo = m0 + wm * 32 + i * 16 + g;
        float p0a = 0.f, p1a = 0.f, p2a = 0.f, p0b = 0.f, p1b = 0.f, p2b = 0.f;
        if (pts) {
            p0a = pts[r_lo * 3 + 0]; p1a = pts[r_lo * 3 + 1]; p2a = pts[r_lo * 3 + 2];
            p0b = pts[(r_lo + 8) * 3 + 0]; p1b = pts[(r_lo + 8) * 3 + 1]; p2b = pts[(r_lo + 8) * 3 + 2];
        }
#pragma unroll
        for (int n = 0; n < 4; n++) {
            int col = n0 + wn * 32 + n * 8 + 2 * j;
            float b0 = bias[col], b1 = bias[col + 1];
            float v00 = acc[i][n][0] + b0, v01 = acc[i][n][1] + b1;
            float v10 = acc[i][n][2] + b0, v11 = acc[i][n][3] + b1;
            if (pts) {
                float s0 = sw[col * 3], s1 = sw[col * 3 + 1], s2 = sw[col * 3 + 2];
                float t0 = sw[(col+1) * 3], t1 = sw[(col+1) * 3 + 1], t2 = sw[(col+1) * 3 + 2];
                v00 += p0a * s0 + p1a * s1 + p2a * s2 + sb[col];
                v01 += p0a * t0 + p1a * t1 + p2a * t2 + sb[col + 1];
                v10 += p0b * s0 + p1b * s1 + p2b * s2 + sb[col];
                v11 += p0b * t0 + p1b * t1 + p2b * t2 + sb[col + 1];
            }
            if (out_half) {
                uint32_t* Cu = (uint32_t*)C;
                Cu[(size_t)r_lo * 128 + (col >> 1)]       = pk_f16x2(v00 * oscale, v01 * oscale);
                Cu[(size_t)(r_lo + 8) * 128 + (col >> 1)] = pk_f16x2(v10 * oscale, v11 * oscale);
            } else {
                *(float2*)&C[(size_t)r_lo * 256 + col]       = make_float2(v00, v01);
                *(float2*)&C[(size_t)(r_lo + 8) * 256 + col] = make_float2(v10, v11);
            }
        }
    }
}

// =====================================================================
// Kernel 4: flash attention, fp16 MMA; 4 warps x 32 q-rows (two m16
// A-tiles per warp -> every K/V B-fragment feeds 2 MMAs, LDS/MMA = 1).
// P = 2^S via ex2.f16x2 (scale folded into Q); row sums via ones-MMA.
// kv chunk 128 double-buffered; kv processed in 32-wide quarters to
// bound live S registers.
// =====================================================================
#define KV32 20
#define VV32 40
#define SMEM_K_OFF(buf) ((buf) * (128 * KV32))
#define SMEM_V_OFF(buf) (2 * 128 * KV32 + (buf) * (64 * VV32))
#define FLASH_SMEM_U32 (2 * 128 * KV32 + 2 * 64 * VV32)

__global__ void __launch_bounds__(128, 3)
flash_mma_kernel(const uint32_t* __restrict__ Q, const uint32_t* __restrict__ K,
                 const uint32_t* __restrict__ V, float* __restrict__ O)
{
    extern __shared__ uint32_t smu[];

    int tid = threadIdx.x;
    int wid = tid >> 5, lane = tid & 31;
    int g = lane >> 2, j = lane & 3;
    int q0 = blockIdx.x * 128;
    int bh = blockIdx.y, b = bh >> 3, h = bh & 7;

    const uint32_t* qp = Q + ((size_t)b * NQ + q0 + wid * 32) * 128 + h * 16;
    const uint32_t* kp = K + (size_t)b * LK * 128 + h * 16;
    const uint32_t* vp = V + (size_t)b * LK * 128 + h * 16;

    // Q A-fragments: two m16 tiles (i), 2 k-tiles over dh=32
    uint32_t aq[2][2][4];
#pragma unroll
    for (int i = 0; i < 2; i++)
#pragma unroll
        for (int kt = 0; kt < 2; kt++) {
            int rb = i * 16;
            aq[i][kt][0] = qp[(size_t)(rb + g) * 128 + kt * 8 + j];
            aq[i][kt][1] = qp[(size_t)(rb + g + 8) * 128 + kt * 8 + j];
            aq[i][kt][2] = qp[(size_t)(rb + g) * 128 + kt * 8 + j + 4];
            aq[i][kt][3] = qp[(size_t)(rb + g + 8) * 128 + kt * 8 + j + 4];
        }

    float o[2][4][4];
#pragma unroll
    for (int i = 0; i < 2; i++)
#pragma unroll
        for (int n = 0; n < 4; n++)
#pragma unroll
            for (int r = 0; r < 4; r++) o[i][n][r] = 0.0f;
    float lacc[2][4] = {{0,0,0,0},{0,0,0,0}};

    // staging maps (128 threads)
    int krow[4], kq4[4];
#pragma unroll
    for (int u = 0; u < 4; u++) {
        int fid = tid + 128 * u;         // 0..511
        krow[u] = fid >> 2;
        kq4[u]  = (fid & 3) * 4;
    }
    int vpi[2], vqq[2];
#pragma unroll
    for (int u = 0; u < 2; u++) {
        int fid = tid + 128 * u;         // 0..255
        vpi[u] = fid >> 2;               // pair 0..63
        vqq[u] = (fid & 3) * 4;
    }

    // prefetch + stage chunk 0
    uint4 kpre[4], ve[2], vo[2];
#pragma unroll
    for (int u = 0; u < 4; u++)
        kpre[u] = *(const uint4*)&kp[(size_t)krow[u] * 128 + kq4[u]];
#pragma unroll
    for (int u = 0; u < 2; u++) {
        ve[u] = *(const uint4*)&vp[(size_t)(2 * vpi[u]) * 128 + vqq[u]];
        vo[u] = *(const uint4*)&vp[(size_t)(2 * vpi[u] + 1) * 128 + vqq[u]];
    }
#pragma unroll
    for (int u = 0; u < 4; u++)
        *(uint4*)&smu[SMEM_K_OFF(0) + krow[u] * KV32 + kq4[u]] = kpre[u];
#pragma unroll
    for (int u = 0; u < 2; u++) {
        uint4 w0, w1;
        w0.x = prmt(ve[u].x, vo[u].x, 0x5410); w0.y = prmt(ve[u].x, vo[u].x, 0x7632);
        w0.z = prmt(ve[u].y, vo[u].y, 0x5410); w0.w = prmt(ve[u].y, vo[u].y, 0x7632);
        w1.x = prmt(ve[u].z, vo[u].z, 0x5410); w1.y = prmt(ve[u].z, vo[u].z, 0x7632);
        w1.z = prmt(ve[u].w, vo[u].w, 0x5410); w1.w = prmt(ve[u].w, vo[u].w, 0x7632);
        *(uint4*)&smu[SMEM_V_OFF(0) + vpi[u] * VV32 + vqq[u] * 2]     = w0;
        *(uint4*)&smu[SMEM_V_OFF(0) + vpi[u] * VV32 + vqq[u] * 2 + 4] = w1;
    }

    for (int c = 0; c < 32; c++) {
        int buf = c & 1;
        if (c < 31) {
            int kb = (c + 1) * 128;
#pragma unroll
            for (int u = 0; u < 4; u++)
                kpre[u] = *(const uint4*)&kp[(size_t)(kb + krow[u]) * 128 + kq4[u]];
#pragma unroll
            for (int u = 0; u < 2; u++) {
                ve[u] = *(const uint4*)&vp[(size_t)(kb + 2 * vpi[u]) * 128 + vqq[u]];
                vo[u] = *(const uint4*)&vp[(size_t)(kb + 2 * vpi[u] + 1) * 128 + vqq[u]];
            }
        }
        __syncthreads();

        const uint32_t* Ks = &smu[SMEM_K_OFF(buf)];
        const uint32_t* Vs = &smu[SMEM_V_OFF(buf)];

        // kv in quarters of 32 (bounds live S registers to 32 f32)
#pragma unroll
        for (int qq = 0; qq < 4; qq++) {
            float s[2][4][4];
#pragma unroll
            for (int i = 0; i < 2; i++)
#pragma unroll
                for (int nt = 0; nt < 4; nt++)
#pragma unroll
                    for (int r = 0; r < 4; r++) s[i][nt][r] = 0.0f;

            // ---- S = Q K^T : B-frags shared across the two A-tiles ----
#pragma unroll
            for (int kt = 0; kt < 2; kt++) {
#pragma unroll
                for (int nt = 0; nt < 4; nt++) {
                    int kvrow = qq * 32 + nt * 8 + g;
                    uint32_t b0 = Ks[kvrow * KV32 + kt * 8 + j];
                    uint32_t b1 = Ks[kvrow * KV32 + kt * 8 + j + 4];
#pragma unroll
                    for (int i = 0; i < 2; i++)
                        mma_f16(s[i][nt][0], s[i][nt][1], s[i][nt][2], s[i][nt][3],
                                aq[i][kt][0], aq[i][kt][1], aq[i][kt][2], aq[i][kt][3],
                                b0, b1);
                }
            }

            // ---- P = 2^S -> fp16 A-frags ; ones-MMA row sums ; P*V ----
#pragma unroll
            for (int t = 0; t < 2; t++) {          // k16 tiles within quarter
                uint32_t pa[2][4];
#pragma unroll
                for (int i = 0; i < 2; i++) {
                    pa[i][0] = ex2_f16x2(pk_f16x2(s[i][2*t][0],   s[i][2*t][1]));
                    pa[i][1] = ex2_f16x2(pk_f16x2(s[i][2*t][2],   s[i][2*t][3]));
                    pa[i][2] = ex2_f16x2(pk_f16x2(s[i][2*t+1][0], s[i][2*t+1][1]));
                    pa[i][3] = ex2_f16x2(pk_f16x2(s[i][2*t+1][2], s[i][2*t+1][3]));
                    mma_f16(lacc[i][0], lacc[i][1], lacc[i][2], lacc[i][3],
                            pa[i][0], pa[i][1], pa[i][2], pa[i][3], ONESH2, ONESH2);
                }

                int pairbase = (qq * 2 + t) * 8;
#pragma unroll
                for (int no = 0; no < 4; no++) {
                    uint32_t b0 = Vs[(pairbase + j)     * VV32 + no * 8 + g];
                    uint32_t b1 = Vs[(pairbase + j + 4) * VV32 + no * 8 + g];
#pragma unroll
                    for (int i = 0; i < 2; i++)
                        mma_f16(o[i][no][0], o[i][no][1], o[i][no][2], o[i][no][3],
                                pa[i][0], pa[i][1], pa[i][2], pa[i][3], b0, b1);
                }
            }
        }

        if (c < 31) {
            int nb = 1 - buf;
#pragma unroll
            for (int u = 0; u < 4; u++)
                *(uint4*)&smu[SMEM_K_OFF(nb) + krow[u] * KV32 + kq4[u]] = kpre[u];
#pragma unroll
            for (int u = 0; u < 2; u++) {
                uint4 w0, w1;
                w0.x = prmt(ve[u].x, vo[u].x, 0x5410); w0.y = prmt(ve[u].x, vo[u].x, 0x7632);
                w0.z = prmt(ve[u].y, vo[u].y, 0x5410); w0.w = prmt(ve[u].y, vo[u].y, 0x7632);
                w1.x = prmt(ve[u].z, vo[u].z, 0x5410); w1.y = prmt(ve[u].z, vo[u].z, 0x7632);
                w1.z = prmt(ve[u].w, vo[u].w, 0x5410); w1.w = prmt(ve[u].w, vo[u].w, 0x7632);
                *(uint4*)&smu[SMEM_V_OFF(nb) + vpi[u] * VV32 + vqq[u] * 2]     = w0;
                *(uint4*)&smu[SMEM_V_OFF(nb) + vpi[u] * VV32 + vqq[u] * 2 + 4] = w1;
            }
        }
    }

#pragma unroll
    for (int i = 0; i < 2; i++) {
        float inv0 = 1.0f / lacc[i][0];   // row g sum
        float inv1 = 1.0f / lacc[i][2];   // row g+8 sum
        float* op = O + ((size_t)b * NQ + q0 + wid * 32 + i * 16) * DD + h * DH;
#pragma unroll
        for (int no = 0; no < 4; no++) {
            int col = no * 8 + 2 * j;
            float2 lo = make_float2(o[i][no][0] * inv0, o[i][no][1] * inv0);
            float2 hi = make_float2(o[i][no][2] * inv1, o[i][no][3] * inv1);
            *(float2*)&op[(size_t)g * DD + col]       = lo;
            *(float2*)&op[(size_t)(g + 8) * DD + col] = hi;
        }
    }
}

// =====================================================================
// Launch
// =====================================================================
extern "C" void kernel_launch(void* const* d_in, const int* in_sizes, int n_in,
                              void* d_out, int out_size)
{
    const float* cur_pts = (const float*)d_in[0];
    const float* cur_f   = (const float*)d_in[1];
    const float* nbr_pts = (const float*)d_in[2];
    const float* nbr_f   = (const float*)d_in[3];
    const float* in_w    = (const float*)d_in[4];
    const float* in_b    = (const float*)d_in[5];
    const float* out_w   = (const float*)d_in[6];
    const float* out_b   = (const float*)d_in[7];
    const float* sw      = (const float*)d_in[8];
    const float* sb      = (const float*)d_in[9];
    float* out = (float*)d_out;

    uint32_t *dq, *dk, *dv;
    float *dce, *dan, *dat;
    cudaGetSymbolAddress((void**)&dq,  g_q);
    cudaGetSymbolAddress((void**)&dk,  g_k);
    cudaGetSymbolAddress((void**)&dv,  g_v);
    cudaGetSymbolAddress((void**)&dce, g_cur_edge);
    cudaGetSymbolAddress((void**)&dan, g_all_nbr);
    cudaGetSymbolAddress((void**)&dat, g_attn);

    int flash_smem = FLASH_SMEM_U32 * (int)sizeof(uint32_t);
    int proj_smem  = PROJ_SMEM_FLOATS * (int)sizeof(float);
    static int attr_set = 0;
    if (!attr_set) {
        cudaFuncSetAttribute(flash_mma_kernel,
                             cudaFuncAttributeMaxDynamicSharedMemorySize, flash_smem);
        cudaFuncSetAttribute(gemm_proj_mma,
                             cudaFuncAttributeMaxDynamicSharedMemorySize, proj_smem);
        attr_set = 1;
    }

    // scale folded into Q so P = 2^S in flash: (1/sqrt(32)) * log2(e)
    const float QSCALE = 0.25503488f;

    knn_topk_kernel<<<dim3(NQ / 128, NSETS), 128>>>(cur_pts, nbr_pts);
    edge_feats_kernel<<<NSETS * NQ, DD>>>(cur_f, nbr_f);

    gemm_proj_mma<<<dim3((BB * NQ) / 128, 4), 256, proj_smem>>>(
        dce, in_w,           in_b,       (float*)dq, 1, QSCALE, nullptr, nullptr, nullptr);
    gemm_proj_mma<<<dim3((BB * LK) / 128, 4), 256, proj_smem>>>(
        dan, in_w + 256*256, in_b + 256, (float*)dk, 1, 1.0f, nullptr, nullptr, nullptr);
    gemm_proj_mma<<<dim3((BB * LK) / 128, 4), 256, proj_smem>>>(
        dan, in_w + 512*256, in_b + 512, (float*)dv, 1, 1.0f, nullptr, nullptr, nullptr);

    flash_mma_kernel<<<dim3(NQ / 128, BB * HH), 128, flash_smem>>>(dq, dk, dv, dat);

    // output projection + fused spatial epilogue (tf32 GEMM, fp32 epilogue)
    gemm_proj_mma<<<dim3((BB * NQ) / 128, 4), 256, proj_smem>>>(
        dat, out_w, out_b, out, 0, 1.0f, cur_pts, sw, sb);
}